// round 8
// baseline (speedup 1.0000x reference)
#include <cuda_runtime.h>
#include <math.h>

// ---------------- problem constants ----------------
#define TOK   4096          // B*S = 4*1024
#define SEQ   1024
#define BATCH 4
#define EMB   512
#define NH    8
#define HD    64
#define NEXP  32
#define TOPK  4
#define RRANK 64
#define SHID  4096
#define EHID  512

// ---------------- device scratch (static, allocation-free) ----------------
__device__ float g_h1[TOK * EMB];
__device__ float g_q[TOK * EMB];
__device__ float g_k[TOK * EMB];
__device__ float g_v[TOK * EMB];
__device__ float g_attn[TOK * EMB];
__device__ float g_x1[TOK * EMB];
__device__ float g_h2[TOK * EMB];
__device__ float g_rlat[TOK * RRANK];
__device__ float g_logits[TOK * NEXP];
__device__ int   g_topi[TOK * TOPK];
__device__ float g_topw[TOK * TOPK];
__device__ float g_imp[NEXP];
__device__ int   g_cnt[NEXP];
__device__ int   g_off[NEXP];
__device__ int   g_cur[NEXP];
__device__ int   g_atok[TOK * TOPK];
__device__ float g_aw[TOK * TOPK];
__device__ float g_H[TOK * TOPK * EHID];   // routed hidden
__device__ float g_hs[TOK * SHID];         // shared-expert hidden

// ---------------- helpers ----------------
__device__ __forceinline__ float gelu_tanh(float x) {
    float x3 = x * x * x;
    return 0.5f * x * (1.0f + tanhf(0.7978845608028654f * (x + 0.044715f * x3)));
}

__device__ __forceinline__ unsigned f2tf32(float f) {
    unsigned r;
    asm("cvt.rna.tf32.f32 %0, %1;" : "=r"(r) : "f"(f));
    return r;
}

__device__ __forceinline__ void tf32_split(float f, unsigned& hi, unsigned& lo) {
    hi = f2tf32(f);
    lo = f2tf32(f - __uint_as_float(hi));
}

__device__ __forceinline__ void mma_tf32(float& c0, float& c1, float& c2, float& c3,
                                         unsigned a0, unsigned a1, unsigned a2, unsigned a3,
                                         unsigned b0, unsigned b1) {
    asm volatile(
        "mma.sync.aligned.m16n8k8.row.col.f32.tf32.tf32.f32 "
        "{%0,%1,%2,%3}, {%4,%5,%6,%7}, {%8,%9}, {%0,%1,%2,%3};"
        : "+f"(c0), "+f"(c1), "+f"(c2), "+f"(c3)
        : "r"(a0), "r"(a1), "r"(a2), "r"(a3), "r"(b0), "r"(b1));
}

// ================= 3xTF32 tensor-core GEMM, hi/lo pre-split in smem ============
// BM=128, BN=128, BK=32, 256 threads = 8 warps (2 M x 4 N), warp tile 64x32.
// hi/lo tf32 split happens ONCE per tile element at staging; mainloop = LDS + MMA.
#define APAD 36
#define BPAD 136
#define ASZ (128 * APAD)
#define BSZ (32 * BPAD)
#define TG_SMEM ((2 * ASZ + 2 * BSZ) * 4)   // 71680 bytes

__device__ __forceinline__ void stage_split4(unsigned* __restrict__ Hi,
                                             unsigned* __restrict__ Lo,
                                             int off, float4 v) {
    unsigned h, l;
    tf32_split(v.x, h, l); Hi[off + 0] = h; Lo[off + 0] = l;
    tf32_split(v.y, h, l); Hi[off + 1] = h; Lo[off + 1] = l;
    tf32_split(v.z, h, l); Hi[off + 2] = h; Lo[off + 2] = l;
    tf32_split(v.w, h, l); Hi[off + 3] = h; Lo[off + 3] = l;
}

// generic body.
// EPI 0: plain store (bias/act/res), A rows = row0+arow (identity)
// EPI 1: gelu -> C[off+m] scatter store; A rows GATHERED via atok[off+m] (token ids)
// EPI 2: atomic scatter to C[tok]; A rows = row0+arow LOCAL (A already expert-based),
//        validity m < cnt; atok/aw used in epilogue only.
template <int ACT, int EPI>
__device__ __forceinline__ void tgemm_body(
    const float* __restrict__ A, const float* __restrict__ B,
    const float* __restrict__ bias, const float* __restrict__ res,
    float* __restrict__ C, int M, int N, int K,
    int row0, int col0,
    const int* __restrict__ atok, const float* __restrict__ aw,
    int cnt, int off) {

    extern __shared__ unsigned dsm[];
    unsigned* Ah = dsm;
    unsigned* Al = Ah + ASZ;
    unsigned* Bh = Al + ASZ;
    unsigned* Bl = Bh + BSZ;

    int tid = threadIdx.x;
    int warp = tid >> 5, lane = tid & 31;
    int wm = warp >> 2, wn = warp & 3;
    int g = lane >> 2, t = lane & 3;

    int arow = tid >> 1, acb = (tid & 1) * 16;
    int brow = tid >> 3, bcb = (tid & 7) * 16;

    // A source row:
    int asrc;
    bool avalid;
    if (EPI == 1) {                 // gather rows by token id
        int m = row0 + arow;
        avalid = (m < cnt);
        asrc = avalid ? atok[off + m] : 0;
    } else if (EPI == 2) {          // local contiguous rows, bounded by cnt
        int m = row0 + arow;
        avalid = (m < cnt);
        asrc = avalid ? m : 0;
    } else {                        // identity
        avalid = true;
        asrc = row0 + arow;
    }

    float c[4][4][4];
#pragma unroll
    for (int i = 0; i < 4; i++)
#pragma unroll
        for (int j = 0; j < 4; j++) { c[i][j][0] = c[i][j][1] = c[i][j][2] = c[i][j][3] = 0.f; }

    for (int k0 = 0; k0 < K; k0 += 32) {
#pragma unroll
        for (int i = 0; i < 4; i++) {
            float4 v = make_float4(0.f, 0.f, 0.f, 0.f);
            if (avalid)
                v = *reinterpret_cast<const float4*>(A + (size_t)asrc * K + k0 + acb + i * 4);
            stage_split4(Ah, Al, arow * APAD + acb + i * 4, v);
        }
        const float* Bp = B + (size_t)(k0 + brow) * N + col0 + bcb;
#pragma unroll
        for (int i = 0; i < 4; i++)
            stage_split4(Bh, Bl, brow * BPAD + bcb + i * 4,
                         *reinterpret_cast<const float4*>(Bp + i * 4));
        __syncthreads();
#pragma unroll
        for (int kk = 0; kk < 4; kk++) {
            int kb = kk * 8;
            unsigned ah[4][4], al[4][4], bh[4][2], bl[4][2];
#pragma unroll
            for (int mt = 0; mt < 4; mt++) {
                int mb = wm * 64 + mt * 16;
                int i0 = (mb + g) * APAD + kb + t;
                int i1 = (mb + g + 8) * APAD + kb + t;
                ah[mt][0] = Ah[i0];     al[mt][0] = Al[i0];
                ah[mt][1] = Ah[i1];     al[mt][1] = Al[i1];
                ah[mt][2] = Ah[i0 + 4]; al[mt][2] = Al[i0 + 4];
                ah[mt][3] = Ah[i1 + 4]; al[mt][3] = Al[i1 + 4];
            }
#pragma unroll
            for (int nt = 0; nt < 4; nt++) {
                int nb = wn * 32 + nt * 8;
                int j0 = (kb + t) * BPAD + nb + g;
                int j1 = (kb + t + 4) * BPAD + nb + g;
                bh[nt][0] = Bh[j0]; bl[nt][0] = Bl[j0];
                bh[nt][1] = Bh[j1]; bl[nt][1] = Bl[j1];
            }
#pragma unroll
            for (int mt = 0; mt < 4; mt++)
#pragma unroll
                for (int nt = 0; nt < 4; nt++) {
                    mma_tf32(c[mt][nt][0], c[mt][nt][1], c[mt][nt][2], c[mt][nt][3],
                             al[mt][0], al[mt][1], al[mt][2], al[mt][3],
                             bh[nt][0], bh[nt][1]);
                    mma_tf32(c[mt][nt][0], c[mt][nt][1], c[mt][nt][2], c[mt][nt][3],
                             ah[mt][0], ah[mt][1], ah[mt][2], ah[mt][3],
                             bl[nt][0], bl[nt][1]);
                    mma_tf32(c[mt][nt][0], c[mt][nt][1], c[mt][nt][2], c[mt][nt][3],
                             ah[mt][0], ah[mt][1], ah[mt][2], ah[mt][3],
                             bh[nt][0], bh[nt][1]);
                }
        }
        __syncthreads();
    }

    // epilogue: c0:(m=mb+g, n=nb+2t) c1:(+1) c2:(m+8) c3:(m+8,+1)
#pragma unroll
    for (int mt = 0; mt < 4; mt++) {
        int mb = row0 + wm * 64 + mt * 16;
#pragma unroll
        for (int nt = 0; nt < 4; nt++) {
            int nb = col0 + wn * 32 + nt * 8 + 2 * t;
#pragma unroll
            for (int half = 0; half < 2; half++) {
                int r = mb + g + half * 8;
                float v0 = c[mt][nt][half * 2 + 0];
                float v1 = c[mt][nt][half * 2 + 1];
                if (EPI == 0) {
                    if (bias) { v0 += bias[nb]; v1 += bias[nb + 1]; }
                    if (ACT == 1) { v0 = gelu_tanh(v0); v1 = gelu_tanh(v1); }
                    if (res) {
                        v0 += res[(size_t)r * N + nb];
                        v1 += res[(size_t)r * N + nb + 1];
                    }
                    C[(size_t)r * N + nb] = v0;
                    C[(size_t)r * N + nb + 1] = v1;
                } else if (EPI == 1) {
                    if (r < cnt) {
                        C[(size_t)(off + r) * N + nb] = gelu_tanh(v0 + bias[nb]);
                        C[(size_t)(off + r) * N + nb + 1] = gelu_tanh(v1 + bias[nb + 1]);
                    }
                } else {  // EPI == 2
                    if (r < cnt) {
                        int tok = atok[off + r];
                        float wgt = aw[off + r];
                        atomicAdd(&C[(size_t)tok * N + nb], (v0 + bias[nb]) * wgt);
                        atomicAdd(&C[(size_t)tok * N + nb + 1], (v1 + bias[nb + 1]) * wgt);
                    }
                }
            }
        }
    }
}

template <int ACT>
__global__ __launch_bounds__(256) void tgemm(const float* __restrict__ A,
                                             const float* __restrict__ B,
                                             const float* __restrict__ bias,
                                             const float* __restrict__ res,
                                             float* __restrict__ C,
                                             int M, int N, int K) {
    tgemm_body<ACT, 0>(A, B, bias, res, C, M, N, K,
                       blockIdx.y * 128, blockIdx.x * 128, nullptr, nullptr, 0, 0);
}

// fused QKV: blockIdx.z selects weight/bias/output
__global__ __launch_bounds__(256) void qkv_tgemm(const float* __restrict__ A,
                                                 const float* __restrict__ wq,
                                                 const float* __restrict__ wk,
                                                 const float* __restrict__ wv,
                                                 const float* __restrict__ bq,
                                                 const float* __restrict__ bk,
                                                 const float* __restrict__ bv) {
    int z = blockIdx.z;
    const float* W = (z == 0) ? wq : (z == 1) ? wk : wv;
    const float* bias = (z == 0) ? bq : (z == 1) ? bk : bv;
    float* C = (z == 0) ? g_q : (z == 1) ? g_k : g_v;
    tgemm_body<0, 0>(A, W, bias, nullptr, C, TOK, EMB, EMB,
                     blockIdx.y * 128, blockIdx.x * 128, nullptr, nullptr, 0, 0);
}

// routed expert GEMM1: H[off+m] = gelu(h2[atok[off+m]] @ W1[e] + b1[e])
__global__ __launch_bounds__(256) void routed_tgemm1(const float* __restrict__ W1all,
                                                     const float* __restrict__ b1all) {
    int e = blockIdx.z;
    int cnt = g_cnt[e];
    int m0 = blockIdx.y * 128;
    if (m0 >= cnt) return;
    tgemm_body<0, 1>(g_h2, W1all + (size_t)e * EMB * EHID, b1all + (size_t)e * EHID,
                     nullptr, g_H, TOK, EHID, EMB,
                     m0, blockIdx.x * 128, g_atok, nullptr, cnt, g_off[e]);
}

// routed expert GEMM2: out[atok[off+m]] += gate * (H[off+m] @ W2[e] + b2[e])
// A rows are LOCAL contiguous (EPI==2 path); atok used for scatter only.
__global__ __launch_bounds__(256) void routed_tgemm2(const float* __restrict__ W2all,
                                                     const float* __restrict__ b2all,
                                                     float* __restrict__ out) {
    int e = blockIdx.z;
    int cnt = g_cnt[e];
    int m0 = blockIdx.y * 128;
    if (m0 >= cnt) return;
    int off = g_off[e];
    tgemm_body<0, 2>(g_H + (size_t)off * EHID, W2all + (size_t)e * EHID * EMB,
                     b2all + (size_t)e * EMB, nullptr, out, TOK, EMB, EHID,
                     m0, blockIdx.x * 128, g_atok, g_aw, cnt, off);
}

// ---------------- LayerNorm ----------------
__global__ __launch_bounds__(128) void ln_kernel(const float* __restrict__ X,
                                                 const float* __restrict__ g,
                                                 const float* __restrict__ b,
                                                 float* __restrict__ Y) {
    int t = blockIdx.x;
    int tid = threadIdx.x;
    const float4 v = *reinterpret_cast<const float4*>(X + (size_t)t * EMB + tid * 4);
    float s  = v.x + v.y + v.z + v.w;
    float sq = v.x * v.x + v.y * v.y + v.z * v.z + v.w * v.w;
    for (int o = 16; o > 0; o >>= 1) {
        s  += __shfl_xor_sync(0xffffffff, s, o);
        sq += __shfl_xor_sync(0xffffffff, sq, o);
    }
    __shared__ float ssum[4], ssq[4], stats[2];
    int w = tid >> 5;
    if ((tid & 31) == 0) { ssum[w] = s; ssq[w] = sq; }
    __syncthreads();
    if (tid == 0) {
        float S = ssum[0] + ssum[1] + ssum[2] + ssum[3];
        float Q = ssq[0] + ssq[1] + ssq[2] + ssq[3];
        float mu = S * (1.0f / EMB);
        float var = Q * (1.0f / EMB) - mu * mu;
        stats[0] = mu;
        stats[1] = rsqrtf(var + 1e-5f);
    }
    __syncthreads();
    float mu = stats[0], rs = stats[1];
    int cc = tid * 4;
    float4 gg = *reinterpret_cast<const float4*>(g + cc);
    float4 bb = *reinterpret_cast<const float4*>(b + cc);
    float4 o;
    o.x = (v.x - mu) * rs * gg.x + bb.x;
    o.y = (v.y - mu) * rs * gg.y + bb.y;
    o.z = (v.z - mu) * rs * gg.z + bb.z;
    o.w = (v.w - mu) * rs * gg.w + bb.w;
    *reinterpret_cast<float4*>(Y + (size_t)t * EMB + cc) = o;
}

// ---------------- fp32 SGEMM (router only, small N) ----------------
template <int ACT>
__global__ __launch_bounds__(256) void sgemm(const float* __restrict__ A,
                                             const float* __restrict__ B,
                                             const float* __restrict__ bias,
                                             const float* __restrict__ res,
                                             float* __restrict__ C,
                                             int M, int N, int K) {
    __shared__ float As[8][128];
    __shared__ float Bs[8][128];
    int tid = threadIdx.x;
    int row0 = blockIdx.y * 128, col0 = blockIdx.x * 128;
    int aRow = tid >> 1, aCol = (tid & 1) * 4;
    int bRow = tid >> 5, bCol = (tid & 31) * 4;
    int tr = (tid >> 4) * 8, tc = (tid & 15) * 8;

    float acc[8][8];
#pragma unroll
    for (int i = 0; i < 8; i++)
#pragma unroll
        for (int j = 0; j < 8; j++) acc[i][j] = 0.f;

    const float* Ap = A + (size_t)(row0 + aRow) * K + aCol;
    for (int k0 = 0; k0 < K; k0 += 8) {
        float4 av = *reinterpret_cast<const float4*>(Ap + k0);
        As[aCol + 0][aRow] = av.x;
        As[aCol + 1][aRow] = av.y;
        As[aCol + 2][aRow] = av.z;
        As[aCol + 3][aRow] = av.w;
        int gc = col0 + bCol;
        const float* Bp = B + (size_t)(k0 + bRow) * N + gc;
        float4 bv;
        if (gc + 3 < N) {
            bv = *reinterpret_cast<const float4*>(Bp);
        } else {
            bv.x = (gc + 0 < N) ? Bp[0] : 0.f;
            bv.y = (gc + 1 < N) ? Bp[1] : 0.f;
            bv.z = (gc + 2 < N) ? Bp[2] : 0.f;
            bv.w = (gc + 3 < N) ? Bp[3] : 0.f;
        }
        Bs[bRow][bCol + 0] = bv.x;
        Bs[bRow][bCol + 1] = bv.y;
        Bs[bRow][bCol + 2] = bv.z;
        Bs[bRow][bCol + 3] = bv.w;
        __syncthreads();
#pragma unroll
        for (int k = 0; k < 8; k++) {
            float4 ra0 = *reinterpret_cast<const float4*>(&As[k][tr]);
            float4 ra1 = *reinterpret_cast<const float4*>(&As[k][tr + 4]);
            float4 rb0 = *reinterpret_cast<const float4*>(&Bs[k][tc]);
            float4 rb1 = *reinterpret_cast<const float4*>(&Bs[k][tc + 4]);
            float ra[8] = {ra0.x, ra0.y, ra0.z, ra0.w, ra1.x, ra1.y, ra1.z, ra1.w};
            float rb[8] = {rb0.x, rb0.y, rb0.z, rb0.w, rb1.x, rb1.y, rb1.z, rb1.w};
#pragma unroll
            for (int i = 0; i < 8; i++)
#pragma unroll
                for (int j = 0; j < 8; j++) acc[i][j] += ra[i] * rb[j];
        }
        __syncthreads();
    }
#pragma unroll
    for (int i = 0; i < 8; i++) {
        int gr = row0 + tr + i;
#pragma unroll
        for (int j = 0; j < 8; j++) {
            int gc = col0 + tc + j;
            if (gc < N) {
                float v = acc[i][j];
                if (bias) v += bias[gc];
                if (ACT == 1) v = gelu_tanh(v);
                if (res) v += res[(size_t)gr * N + gc];
                C[(size_t)gr * N + gc] = v;
            }
        }
    }
}

// ---------------- flash attention (fp32, static smem) ----------------
#define KT 32
__global__ __launch_bounds__(128) void attn_kernel() {
    const float* __restrict__ Q = g_q;
    const float* __restrict__ K = g_k;
    const float* __restrict__ V = g_v;
    float* __restrict__ O = g_attn;

    __shared__ float Qs[64 * 64];
    __shared__ float Kts[64 * (KT + 1)];
    __shared__ float Vs[KT * 64];
    __shared__ float Ss[64 * (KT + 1)];
    __shared__ float rowm[64], rowl[64], rowf[64];

    int bh = blockIdx.x;
    int qt = blockIdx.y;
    int b = bh >> 3, h = bh & 7;
    const size_t base = (size_t)b * SEQ * EMB + h * HD;
    int tid = threadIdx.x;
    int tr = (tid >> 4) * 8;
    int tc = (tid & 15) * 4;
    int sc = (tid & 15) * 2;

    for (int idx = tid; idx < 64 * 16; idx += 128) {
        int r = idx >> 4, c4 = (idx & 15) * 4;
        float4 qv = *reinterpret_cast<const float4*>(Q + base + (size_t)(qt * 64 + r) * EMB + c4);
        Qs[r * 64 + c4 + 0] = qv.x;
        Qs[r * 64 + c4 + 1] = qv.y;
        Qs[r * 64 + c4 + 2] = qv.z;
        Qs[r * 64 + c4 + 3] = qv.w;
    }
    if (tid < 64) { rowm[tid] = -1e30f; rowl[tid] = 0.f; }

    float o[8][4];
#pragma unroll
    for (int i = 0; i < 8; i++)
#pragma unroll
        for (int j = 0; j < 4; j++) o[i][j] = 0.f;
    __syncthreads();

    for (int kt = 0; kt < SEQ / KT; kt++) {
        for (int idx = tid; idx < KT * 16; idx += 128) {
            int r = idx >> 4, c4 = (idx & 15) * 4;
            float4 kv = *reinterpret_cast<const float4*>(K + base + (size_t)(kt * KT + r) * EMB + c4);
            Kts[(c4 + 0) * (KT + 1) + r] = kv.x;
            Kts[(c4 + 1) * (KT + 1) + r] = kv.y;
            Kts[(c4 + 2) * (KT + 1) + r] = kv.z;
            Kts[(c4 + 3) * (KT + 1) + r] = kv.w;
            float4 vv = *reinterpret_cast<const float4*>(V + base + (size_t)(kt * KT + r) * EMB + c4);
            *reinterpret_cast<float4*>(Vs + r * 64 + c4) = vv;
        }
        __syncthreads();
        float s[8][2];
#pragma unroll
        for (int i = 0; i < 8; i++) { s[i][0] = 0.f; s[i][1] = 0.f; }
        for (int d = 0; d < 64; d++) {
            float rb0 = Kts[d * (KT + 1) + sc];
            float rb1 = Kts[d * (KT + 1) + sc + 1];
#pragma unroll
            for (int i = 0; i < 8; i++) {
                float ra = Qs[(tr + i) * 64 + d];
                s[i][0] += ra * rb0;
                s[i][1] += ra * rb1;
            }
        }
#pragma unroll
        for (int i = 0; i < 8; i++) {
            Ss[(tr + i) * (KT + 1) + sc]     = s[i][0] * 0.125f;
            Ss[(tr + i) * (KT + 1) + sc + 1] = s[i][1] * 0.125f;
        }
        __syncthreads();
        if (tid < 64) {
            int r = tid;
            float mo = rowm[r];
            float mx = mo;
#pragma unroll
            for (int j = 0; j < KT; j++) mx = fmaxf(mx, Ss[r * (KT + 1) + j]);
            float f = __expf(mo - mx);
            float l = rowl[r] * f;
#pragma unroll
            for (int j = 0; j < KT; j++) {
                float p = __expf(Ss[r * (KT + 1) + j] - mx);
                Ss[r * (KT + 1) + j] = p;
                l += p;
            }
            rowm[r] = mx;
            rowl[r] = l;
            rowf[r] = f;
        }
        __syncthreads();
#pragma unroll
        for (int i = 0; i < 8; i++) {
            float f = rowf[tr + i];
#pragma unroll
            for (int j = 0; j < 4; j++) o[i][j] *= f;
        }
        for (int t = 0; t < KT; t++) {
            float4 rv = *reinterpret_cast<const float4*>(Vs + t * 64 + tc);
#pragma unroll
            for (int i = 0; i < 8; i++) {
                float rp = Ss[(tr + i) * (KT + 1) + t];
                o[i][0] += rp * rv.x;
                o[i][1] += rp * rv.y;
                o[i][2] += rp * rv.z;
                o[i][3] += rp * rv.w;
            }
        }
        __syncthreads();
    }
#pragma unroll
    for (int i = 0; i < 8; i++) {
        float inv = 1.0f / rowl[tr + i];
#pragma unroll
        for (int j = 0; j < 4; j++)
            O[base + (size_t)(qt * 64 + tr + i) * EMB + tc + j] = o[i][j] * inv;
    }
}

// ---------------- router: softmax + top-4 + stats ----------------
__global__ __launch_bounds__(128) void router_topk_kernel() {
    const float* __restrict__ logits = g_logits;
    __shared__ float s_imp[NEXP];
    __shared__ int s_cnt[NEXP];
    int tid = threadIdx.x;
    if (tid < NEXP) { s_imp[tid] = 0.f; s_cnt[tid] = 0; }
    __syncthreads();
    int t = blockIdx.x * 128 + tid;
    float p[NEXP];
    float mx = -1e30f;
#pragma unroll
    for (int e = 0; e < NEXP; e++) {
        p[e] = logits[(size_t)t * NEXP + e];
        mx = fmaxf(mx, p[e]);
    }
    float sum = 0.f;
#pragma unroll
    for (int e = 0; e < NEXP; e++) { p[e] = __expf(p[e] - mx); sum += p[e]; }
    float inv = 1.f / sum;
#pragma unroll
    for (int e = 0; e < NEXP; e++) {
        p[e] *= inv;
        atomicAdd(&s_imp[e], p[e]);
    }
    int idx[TOPK];
    float w[TOPK];
    float tot = 0.f;
#pragma unroll
    for (int k = 0; k < TOPK; k++) {
        float best = -1.f;
        int bi = 0;
#pragma unroll
        for (int e = 0; e < NEXP; e++)
            if (p[e] > best) { best = p[e]; bi = e; }
        idx[k] = bi;
        w[k] = best;
        tot += best;
        p[bi] = -1.f;
        atomicAdd(&s_cnt[bi], 1);
    }
    float it = 1.f / tot;
#pragma unroll
    for (int k = 0; k < TOPK; k++) {
        g_topi[t * TOPK + k] = idx[k];
        g_topw[t * TOPK + k] = w[k] * it;
    }
    __syncthreads();
    if (tid < NEXP) {
        atomicAdd(&g_imp[tid], s_imp[tid]);
        atomicAdd(&g_cnt[tid], s_cnt[tid]);
    }
}

// ---------------- prefix scan + aux loss ----------------
__global__ void scan_aux_kernel(float* __restrict__ out, int out_size) {
    if (threadIdx.x == 0) {
        int acc = 0;
        float aux = 0.f;
        for (int e = 0; e < NEXP; e++) {
            g_off[e] = acc;
            acc += g_cnt[e];
            aux += g_imp[e] * (float)g_cnt[e];
        }
        aux *= (float)NEXP / ((float)TOK * (float)TOK);
        if (out_size > TOK * EMB) out[TOK * EMB] = aux;
    }
}

// ---------------- fill per-expert assignment lists ----------------
__global__ __launch_bounds__(128) void fill_assign_kernel() {
    int t = blockIdx.x * 128 + threadIdx.x;
#pragma unroll
    for (int k = 0; k < TOPK; k++) {
        int e = g_topi[t * TOPK + k];
        int pos = atomicAdd(&g_cur[e], 1);
        int gidx = g_off[e] + pos;
        g_atok[gidx] = t;
        g_aw[gidx] = g_topw[t * TOPK + k];
    }
}

__global__ void zero_small_kernel() {
    int i = threadIdx.x;
    if (i < NEXP) { g_imp[i] = 0.f; g_cnt[i] = 0; g_cur[i] = 0; }
}

// ---------------- launch ----------------
extern "C" void kernel_launch(void* const* d_in, const int* in_sizes, int n_in,
                              void* d_out, int out_size) {
    const float* x        = (const float*)d_in[0];
    const float* ln1_g    = (const float*)d_in[1];
    const float* ln1_b    = (const float*)d_in[2];
    const float* wq       = (const float*)d_in[3];
    const float* bq       = (const float*)d_in[4];
    const float* wk       = (const float*)d_in[5];
    const float* bk       = (const float*)d_in[6];
    const float* wv       = (const float*)d_in[7];
    const float* bv       = (const float*)d_in[8];
    const float* wo       = (const float*)d_in[9];
    const float* bo       = (const float*)d_in[10];
    const float* ln2_g    = (const float*)d_in[11];
    const float* ln2_b    = (const float*)d_in[12];
    const float* router_a = (const float*)d_in[13];
    const float* router_b = (const float*)d_in[14];
    const float* re_w1    = (const float*)d_in[15];
    const float* re_b1    = (const float*)d_in[16];
    const float* re_w2    = (const float*)d_in[17];
    const float* re_b2    = (const float*)d_in[18];
    const float* se_w1    = (const float*)d_in[19];
    const float* se_b1    = (const float*)d_in[20];
    const float* se_w2    = (const float*)d_in[21];
    const float* se_b2    = (const float*)d_in[22];
    float* out = (float*)d_out;

    float *p_h1, *p_attn, *p_x1, *p_h2, *p_rlat, *p_logits, *p_hs;
    cudaGetSymbolAddress((void**)&p_h1, g_h1);
    cudaGetSymbolAddress((void**)&p_attn, g_attn);
    cudaGetSymbolAddress((void**)&p_x1, g_x1);
    cudaGetSymbolAddress((void**)&p_h2, g_h2);
    cudaGetSymbolAddress((void**)&p_rlat, g_rlat);
    cudaGetSymbolAddress((void**)&p_logits, g_logits);
    cudaGetSymbolAddress((void**)&p_hs, g_hs);

    // allow 70KB dynamic smem on the tf32 kernels (host attribute, idempotent)
    cudaFuncSetAttribute(tgemm<0>, cudaFuncAttributeMaxDynamicSharedMemorySize, TG_SMEM);
    cudaFuncSetAttribute(tgemm<1>, cudaFuncAttributeMaxDynamicSharedMemorySize, TG_SMEM);
    cudaFuncSetAttribute(qkv_tgemm, cudaFuncAttributeMaxDynamicSharedMemorySize, TG_SMEM);
    cudaFuncSetAttribute(routed_tgemm1, cudaFuncAttributeMaxDynamicSharedMemorySize, TG_SMEM);
    cudaFuncSetAttribute(routed_tgemm2, cudaFuncAttributeMaxDynamicSharedMemorySize, TG_SMEM);

    zero_small_kernel<<<1, 32>>>();
    ln_kernel<<<TOK, 128>>>(x, ln1_g, ln1_b, p_h1);

    // fused QKV: 384 blocks
    qkv_tgemm<<<dim3(4, 32, 3), 256, TG_SMEM>>>(p_h1, wq, wk, wv, bq, bk, bv);

    attn_kernel<<<dim3(32, 16), 128>>>();

    dim3 g512(4, 32);
    tgemm<0><<<g512, 256, TG_SMEM>>>(p_attn, wo, bo, x, p_x1, TOK, EMB, EMB);
    ln_kernel<<<TOK, 128>>>(p_x1, ln2_g, ln2_b, p_h2);

    // router (low-rank) — small N, fp32 path
    sgemm<0><<<dim3(1, 32), 256>>>(p_h2, router_a, nullptr, nullptr, p_rlat, TOK, RRANK, EMB);
    sgemm<0><<<dim3(1, 32), 256>>>(p_rlat, router_b, nullptr, nullptr, p_logits, TOK, NEXP, RRANK);
    router_topk_kernel<<<TOK / 128, 128>>>();
    scan_aux_kernel<<<1, 32>>>(out, out_size);
    fill_assign_kernel<<<TOK / 128, 128>>>();

    // routed experts (sparse, grouped)
    routed_tgemm1<<<dim3(4, 128, 32), 256, TG_SMEM>>>(re_w1, re_b1);

    // shared expert
    tgemm<1><<<dim3(32, 32), 256, TG_SMEM>>>(p_h2, se_w1, se_b1, nullptr, p_hs, TOK, SHID, EMB);
    tgemm<0><<<dim3(4, 32), 256, TG_SMEM>>>(p_hs, se_w2, se_b2, p_x1, out, TOK, EMB, SHID);

    // routed contribution accumulates on top
    routed_tgemm2<<<dim3(4, 128, 32), 256, TG_SMEM>>>(re_w2, re_b2, out);
}

// round 9
// speedup vs baseline: 1.0475x; 1.0475x over previous
#include <cuda_runtime.h>
#include <math.h>

// ---------------- problem constants ----------------
#define TOK   4096          // B*S = 4*1024
#define SEQ   1024
#define BATCH 4
#define EMB   512
#define NH    8
#define HD    64
#define NEXP  32
#define TOPK  4
#define RRANK 64
#define SHID  4096
#define EHID  512

// ---------------- device scratch (static, allocation-free) ----------------
__device__ float g_h1[TOK * EMB];
__device__ float g_q[TOK * EMB];
__device__ float g_k[TOK * EMB];
__device__ float g_v[TOK * EMB];
__device__ float g_attn[TOK * EMB];
__device__ float g_x1[TOK * EMB];
__device__ float g_h2[TOK * EMB];
__device__ float g_rlat[TOK * RRANK];
__device__ float g_logits[TOK * NEXP];
__device__ int   g_topi[TOK * TOPK];
__device__ float g_topw[TOK * TOPK];
__device__ float g_imp[NEXP];
__device__ int   g_cnt[NEXP];
__device__ int   g_off[NEXP];
__device__ int   g_cur[NEXP];
__device__ int   g_atok[TOK * TOPK];
__device__ float g_aw[TOK * TOPK];
__device__ float g_H[TOK * TOPK * EHID];   // routed hidden
__device__ float g_hs[TOK * SHID];         // shared-expert hidden

// ---------------- helpers ----------------
__device__ __forceinline__ float gelu_tanh(float x) {
    float x3 = x * x * x;
    return 0.5f * x * (1.0f + tanhf(0.7978845608028654f * (x + 0.044715f * x3)));
}

__device__ __forceinline__ unsigned f2tf32(float f) {
    unsigned r;
    asm("cvt.rna.tf32.f32 %0, %1;" : "=r"(r) : "f"(f));
    return r;
}

__device__ __forceinline__ void tf32_split(float f, unsigned& hi, unsigned& lo) {
    hi = f2tf32(f);
    lo = f2tf32(f - __uint_as_float(hi));
}

__device__ __forceinline__ void mma_tf32(float& c0, float& c1, float& c2, float& c3,
                                         unsigned a0, unsigned a1, unsigned a2, unsigned a3,
                                         unsigned b0, unsigned b1) {
    asm volatile(
        "mma.sync.aligned.m16n8k8.row.col.f32.tf32.tf32.f32 "
        "{%0,%1,%2,%3}, {%4,%5,%6,%7}, {%8,%9}, {%0,%1,%2,%3};"
        : "+f"(c0), "+f"(c1), "+f"(c2), "+f"(c3)
        : "r"(a0), "r"(a1), "r"(a2), "r"(a3), "r"(b0), "r"(b1));
}

__device__ __forceinline__ void cp16(float* s, const float* g) {
    unsigned sa = (unsigned)__cvta_generic_to_shared(s);
    asm volatile("cp.async.cg.shared.global [%0], [%1], 16;" :: "r"(sa), "l"(g));
}
__device__ __forceinline__ void cp_commit() {
    asm volatile("cp.async.commit_group;");
}

// ================= 3xTF32 tensor-core GEMM, cp.async double-buffered ============
// BM=128, BN=128, BK=32, 256 threads = 8 warps (2 M x 4 N), warp tile 64x32.
// fp32 tiles staged via cp.async (2 buffers); hi/lo split at fragment load.
#define APAD 36
#define BPAD 136
#define ASZ (128 * APAD)
#define BSZ (32 * BPAD)
#define TG_SMEM ((2 * ASZ + 2 * BSZ) * 4)   // 71680 bytes

// EPI 0: plain store (bias/act/res), A rows identity.
// EPI 1: gelu -> C[off+m] store; A rows GATHERED via atok[off+m].
// EPI 2: atomic scatter to C[tok]; A rows LOCAL contiguous (bounded by cnt).
template <int ACT, int EPI>
__device__ __forceinline__ void tgemm_body(
    const float* __restrict__ A, const float* __restrict__ B,
    const float* __restrict__ bias, const float* __restrict__ res,
    float* __restrict__ C, int M, int N, int K,
    int row0, int col0,
    const int* __restrict__ atok, const float* __restrict__ aw,
    int cnt, int off) {

    extern __shared__ float dsm[];
    float* As = dsm;                 // [2][ASZ]
    float* Bs = dsm + 2 * ASZ;       // [2][BSZ]

    int tid = threadIdx.x;
    int warp = tid >> 5, lane = tid & 31;
    int wm = warp >> 2, wn = warp & 3;
    int g = lane >> 2, t = lane & 3;

    int arow = tid >> 1, acb = (tid & 1) * 16;
    int brow = tid >> 3, bcb = (tid & 7) * 16;

    // A source row. For EPI 1/2, invalid rows load row 0 (garbage is masked in
    // the epilogue since it only affects output rows >= cnt).
    int asrc;
    if (EPI == 1) {
        int m = row0 + arow;
        asrc = (m < cnt) ? atok[off + m] : 0;
    } else if (EPI == 2) {
        int m = row0 + arow;
        asrc = (m < cnt) ? m : 0;
    } else {
        asrc = row0 + arow;
    }

    const float* Asrc = A + (size_t)asrc * K + acb;
    const float* Bsrc = B + (size_t)brow * N + col0 + bcb;

    float c[4][4][4];
#pragma unroll
    for (int i = 0; i < 4; i++)
#pragma unroll
        for (int j = 0; j < 4; j++) { c[i][j][0] = c[i][j][1] = c[i][j][2] = c[i][j][3] = 0.f; }

    int NS = K / 32;
    // prologue: stage slab 0 into buffer 0
    {
        float* da = As + arow * APAD + acb;
        float* db = Bs + brow * BPAD + bcb;
#pragma unroll
        for (int i = 0; i < 4; i++) cp16(da + i * 4, Asrc + i * 4);
#pragma unroll
        for (int i = 0; i < 4; i++) cp16(db + i * 4, Bsrc + i * 4);
        cp_commit();
    }

    for (int s = 0; s < NS; s++) {
        if (s + 1 < NS) {
            int buf = (s + 1) & 1;
            int k0 = (s + 1) * 32;
            float* da = As + buf * ASZ + arow * APAD + acb;
            float* db = Bs + buf * BSZ + brow * BPAD + bcb;
#pragma unroll
            for (int i = 0; i < 4; i++) cp16(da + i * 4, Asrc + k0 + i * 4);
#pragma unroll
            for (int i = 0; i < 4; i++) cp16(db + i * 4, Bsrc + (size_t)k0 * N + i * 4);
            cp_commit();
            asm volatile("cp.async.wait_group 1;");
        } else {
            asm volatile("cp.async.wait_group 0;");
        }
        __syncthreads();

        const float* Ab = As + (s & 1) * ASZ;
        const float* Bb = Bs + (s & 1) * BSZ;
#pragma unroll
        for (int kk = 0; kk < 4; kk++) {
            int kb = kk * 8;
            unsigned ah[4][4], al[4][4], bh[4][2], bl[4][2];
#pragma unroll
            for (int mt = 0; mt < 4; mt++) {
                int mb = wm * 64 + mt * 16;
                int i0 = (mb + g) * APAD + kb + t;
                int i1 = (mb + g + 8) * APAD + kb + t;
                tf32_split(Ab[i0],     ah[mt][0], al[mt][0]);
                tf32_split(Ab[i1],     ah[mt][1], al[mt][1]);
                tf32_split(Ab[i0 + 4], ah[mt][2], al[mt][2]);
                tf32_split(Ab[i1 + 4], ah[mt][3], al[mt][3]);
            }
#pragma unroll
            for (int nt = 0; nt < 4; nt++) {
                int nb = wn * 32 + nt * 8;
                tf32_split(Bb[(kb + t) * BPAD + nb + g],     bh[nt][0], bl[nt][0]);
                tf32_split(Bb[(kb + t + 4) * BPAD + nb + g], bh[nt][1], bl[nt][1]);
            }
#pragma unroll
            for (int mt = 0; mt < 4; mt++)
#pragma unroll
                for (int nt = 0; nt < 4; nt++) {
                    mma_tf32(c[mt][nt][0], c[mt][nt][1], c[mt][nt][2], c[mt][nt][3],
                             al[mt][0], al[mt][1], al[mt][2], al[mt][3],
                             bh[nt][0], bh[nt][1]);
                    mma_tf32(c[mt][nt][0], c[mt][nt][1], c[mt][nt][2], c[mt][nt][3],
                             ah[mt][0], ah[mt][1], ah[mt][2], ah[mt][3],
                             bl[nt][0], bl[nt][1]);
                    mma_tf32(c[mt][nt][0], c[mt][nt][1], c[mt][nt][2], c[mt][nt][3],
                             ah[mt][0], ah[mt][1], ah[mt][2], ah[mt][3],
                             bh[nt][0], bh[nt][1]);
                }
        }
        __syncthreads();
    }

    // epilogue: c0:(m=mb+g, n=nb+2t) c1:(+1) c2:(m+8) c3:(m+8,+1)
#pragma unroll
    for (int mt = 0; mt < 4; mt++) {
        int mb = row0 + wm * 64 + mt * 16;
#pragma unroll
        for (int nt = 0; nt < 4; nt++) {
            int nb = col0 + wn * 32 + nt * 8 + 2 * t;
#pragma unroll
            for (int half = 0; half < 2; half++) {
                int r = mb + g + half * 8;
                float v0 = c[mt][nt][half * 2 + 0];
                float v1 = c[mt][nt][half * 2 + 1];
                if (EPI == 0) {
                    if (bias) { v0 += bias[nb]; v1 += bias[nb + 1]; }
                    if (ACT == 1) { v0 = gelu_tanh(v0); v1 = gelu_tanh(v1); }
                    if (res) {
                        v0 += res[(size_t)r * N + nb];
                        v1 += res[(size_t)r * N + nb + 1];
                    }
                    C[(size_t)r * N + nb] = v0;
                    C[(size_t)r * N + nb + 1] = v1;
                } else if (EPI == 1) {
                    if (r < cnt) {
                        C[(size_t)(off + r) * N + nb] = gelu_tanh(v0 + bias[nb]);
                        C[(size_t)(off + r) * N + nb + 1] = gelu_tanh(v1 + bias[nb + 1]);
                    }
                } else {
                    if (r < cnt) {
                        int tok = atok[off + r];
                        float wgt = aw[off + r];
                        atomicAdd(&C[(size_t)tok * N + nb], (v0 + bias[nb]) * wgt);
                        atomicAdd(&C[(size_t)tok * N + nb + 1], (v1 + bias[nb + 1]) * wgt);
                    }
                }
            }
        }
    }
}

template <int ACT>
__global__ __launch_bounds__(256) void tgemm(const float* __restrict__ A,
                                             const float* __restrict__ B,
                                             const float* __restrict__ bias,
                                             const float* __restrict__ res,
                                             float* __restrict__ C,
                                             int M, int N, int K) {
    tgemm_body<ACT, 0>(A, B, bias, res, C, M, N, K,
                       blockIdx.y * 128, blockIdx.x * 128, nullptr, nullptr, 0, 0);
}

__global__ __launch_bounds__(256) void qkv_tgemm(const float* __restrict__ A,
                                                 const float* __restrict__ wq,
                                                 const float* __restrict__ wk,
                                                 const float* __restrict__ wv,
                                                 const float* __restrict__ bq,
                                                 const float* __restrict__ bk,
                                                 const float* __restrict__ bv) {
    int z = blockIdx.z;
    const float* W = (z == 0) ? wq : (z == 1) ? wk : wv;
    const float* bias = (z == 0) ? bq : (z == 1) ? bk : bv;
    float* C = (z == 0) ? g_q : (z == 1) ? g_k : g_v;
    tgemm_body<0, 0>(A, W, bias, nullptr, C, TOK, EMB, EMB,
                     blockIdx.y * 128, blockIdx.x * 128, nullptr, nullptr, 0, 0);
}

__global__ __launch_bounds__(256) void routed_tgemm1(const float* __restrict__ W1all,
                                                     const float* __restrict__ b1all) {
    int e = blockIdx.z;
    int cnt = g_cnt[e];
    int m0 = blockIdx.y * 128;
    if (m0 >= cnt) return;
    tgemm_body<0, 1>(g_h2, W1all + (size_t)e * EMB * EHID, b1all + (size_t)e * EHID,
                     nullptr, g_H, TOK, EHID, EMB,
                     m0, blockIdx.x * 128, g_atok, nullptr, cnt, g_off[e]);
}

__global__ __launch_bounds__(256) void routed_tgemm2(const float* __restrict__ W2all,
                                                     const float* __restrict__ b2all,
                                                     float* __restrict__ out) {
    int e = blockIdx.z;
    int cnt = g_cnt[e];
    int m0 = blockIdx.y * 128;
    if (m0 >= cnt) return;
    int off = g_off[e];
    tgemm_body<0, 2>(g_H + (size_t)off * EHID, W2all + (size_t)e * EHID * EMB,
                     b2all + (size_t)e * EMB, nullptr, out, TOK, EMB, EHID,
                     m0, blockIdx.x * 128, g_atok, g_aw, cnt, off);
}

// ---------------- LayerNorm ----------------
__global__ __launch_bounds__(128) void ln_kernel(const float* __restrict__ X,
                                                 const float* __restrict__ g,
                                                 const float* __restrict__ b,
                                                 float* __restrict__ Y) {
    int t = blockIdx.x;
    int tid = threadIdx.x;
    const float4 v = *reinterpret_cast<const float4*>(X + (size_t)t * EMB + tid * 4);
    float s  = v.x + v.y + v.z + v.w;
    float sq = v.x * v.x + v.y * v.y + v.z * v.z + v.w * v.w;
    for (int o = 16; o > 0; o >>= 1) {
        s  += __shfl_xor_sync(0xffffffff, s, o);
        sq += __shfl_xor_sync(0xffffffff, sq, o);
    }
    __shared__ float ssum[4], ssq[4], stats[2];
    int w = tid >> 5;
    if ((tid & 31) == 0) { ssum[w] = s; ssq[w] = sq; }
    __syncthreads();
    if (tid == 0) {
        float S = ssum[0] + ssum[1] + ssum[2] + ssum[3];
        float Q = ssq[0] + ssq[1] + ssq[2] + ssq[3];
        float mu = S * (1.0f / EMB);
        float var = Q * (1.0f / EMB) - mu * mu;
        stats[0] = mu;
        stats[1] = rsqrtf(var + 1e-5f);
    }
    __syncthreads();
    float mu = stats[0], rs = stats[1];
    int cc = tid * 4;
    float4 gg = *reinterpret_cast<const float4*>(g + cc);
    float4 bb = *reinterpret_cast<const float4*>(b + cc);
    float4 o;
    o.x = (v.x - mu) * rs * gg.x + bb.x;
    o.y = (v.y - mu) * rs * gg.y + bb.y;
    o.z = (v.z - mu) * rs * gg.z + bb.z;
    o.w = (v.w - mu) * rs * gg.w + bb.w;
    *reinterpret_cast<float4*>(Y + (size_t)t * EMB + cc) = o;
}

// ---------------- fp32 SGEMM (router only, small N) ----------------
template <int ACT>
__global__ __launch_bounds__(256) void sgemm(const float* __restrict__ A,
                                             const float* __restrict__ B,
                                             const float* __restrict__ bias,
                                             const float* __restrict__ res,
                                             float* __restrict__ C,
                                             int M, int N, int K) {
    __shared__ float As[8][128];
    __shared__ float Bs[8][128];
    int tid = threadIdx.x;
    int row0 = blockIdx.y * 128, col0 = blockIdx.x * 128;
    int aRow = tid >> 1, aCol = (tid & 1) * 4;
    int bRow = tid >> 5, bCol = (tid & 31) * 4;
    int tr = (tid >> 4) * 8, tc = (tid & 15) * 8;

    float acc[8][8];
#pragma unroll
    for (int i = 0; i < 8; i++)
#pragma unroll
        for (int j = 0; j < 8; j++) acc[i][j] = 0.f;

    const float* Ap = A + (size_t)(row0 + aRow) * K + aCol;
    for (int k0 = 0; k0 < K; k0 += 8) {
        float4 av = *reinterpret_cast<const float4*>(Ap + k0);
        As[aCol + 0][aRow] = av.x;
        As[aCol + 1][aRow] = av.y;
        As[aCol + 2][aRow] = av.z;
        As[aCol + 3][aRow] = av.w;
        int gc = col0 + bCol;
        const float* Bp = B + (size_t)(k0 + bRow) * N + gc;
        float4 bv;
        if (gc + 3 < N) {
            bv = *reinterpret_cast<const float4*>(Bp);
        } else {
            bv.x = (gc + 0 < N) ? Bp[0] : 0.f;
            bv.y = (gc + 1 < N) ? Bp[1] : 0.f;
            bv.z = (gc + 2 < N) ? Bp[2] : 0.f;
            bv.w = (gc + 3 < N) ? Bp[3] : 0.f;
        }
        Bs[bRow][bCol + 0] = bv.x;
        Bs[bRow][bCol + 1] = bv.y;
        Bs[bRow][bCol + 2] = bv.z;
        Bs[bRow][bCol + 3] = bv.w;
        __syncthreads();
#pragma unroll
        for (int k = 0; k < 8; k++) {
            float4 ra0 = *reinterpret_cast<const float4*>(&As[k][tr]);
            float4 ra1 = *reinterpret_cast<const float4*>(&As[k][tr + 4]);
            float4 rb0 = *reinterpret_cast<const float4*>(&Bs[k][tc]);
            float4 rb1 = *reinterpret_cast<const float4*>(&Bs[k][tc + 4]);
            float ra[8] = {ra0.x, ra0.y, ra0.z, ra0.w, ra1.x, ra1.y, ra1.z, ra1.w};
            float rb[8] = {rb0.x, rb0.y, rb0.z, rb0.w, rb1.x, rb1.y, rb1.z, rb1.w};
#pragma unroll
            for (int i = 0; i < 8; i++)
#pragma unroll
                for (int j = 0; j < 8; j++) acc[i][j] += ra[i] * rb[j];
        }
        __syncthreads();
    }
#pragma unroll
    for (int i = 0; i < 8; i++) {
        int gr = row0 + tr + i;
#pragma unroll
        for (int j = 0; j < 8; j++) {
            int gc = col0 + tc + j;
            if (gc < N) {
                float v = acc[i][j];
                if (bias) v += bias[gc];
                if (ACT == 1) v = gelu_tanh(v);
                if (res) v += res[(size_t)gr * N + gc];
                C[(size_t)gr * N + gc] = v;
            }
        }
    }
}

// ---------------- flash attention v2: 256 thr, 4x4 reg tiles, parallel softmax ----
// Per block: (b,h) x 64-row q tile; K-tile = 64. All operands staged transposed
// for outer-product float4 LDS. Dynamic smem: 5 arrays of 64x68 floats = 87 KB.
#define ATP 68
#define AT_SMEM (5 * 64 * ATP * 4)

__global__ __launch_bounds__(256) void attn_kernel() {
    const float* __restrict__ Q = g_q;
    const float* __restrict__ K = g_k;
    const float* __restrict__ V = g_v;
    float* __restrict__ O = g_attn;

    extern __shared__ float dsm[];
    float* Qt = dsm;                 // [d][qrow]
    float* Kt = Qt + 64 * ATP;       // [d][krow]
    float* Vs = Kt + 64 * ATP;       // [krow][d]
    float* Ss = Vs + 64 * ATP;       // [qrow][krow]
    float* Pt = Ss + 64 * ATP;       // [krow][qrow]
    __shared__ float rowm[64], rowl[64], rowf[64];

    int bh = blockIdx.x;
    int qt = blockIdx.y;
    int b = bh >> 3, h = bh & 7;
    const size_t base = (size_t)b * SEQ * EMB + h * HD;
    int tid = threadIdx.x;
    int warp = tid >> 5, lane = tid & 31;
    int ti = (tid >> 4) * 4;         // q-row group (4)
    int tj = (tid & 15) * 4;         // col group (4): k-col for S, d-col for O

    // load Q transposed (64 rows x 64 d)
    for (int idx = tid; idx < 64 * 16; idx += 256) {
        int r = idx >> 4, c4 = (idx & 15) * 4;
        float4 qv = *reinterpret_cast<const float4*>(Q + base + (size_t)(qt * 64 + r) * EMB + c4);
        Qt[(c4 + 0) * ATP + r] = qv.x;
        Qt[(c4 + 1) * ATP + r] = qv.y;
        Qt[(c4 + 2) * ATP + r] = qv.z;
        Qt[(c4 + 3) * ATP + r] = qv.w;
    }
    if (tid < 64) { rowm[tid] = -1e30f; rowl[tid] = 0.f; }

    float o[4][4];
#pragma unroll
    for (int i = 0; i < 4; i++)
#pragma unroll
        for (int j = 0; j < 4; j++) o[i][j] = 0.f;
    __syncthreads();

    for (int kt = 0; kt < SEQ / 64; kt++) {
        // load K transposed + V row-major
        for (int idx = tid; idx < 64 * 16; idx += 256) {
            int r = idx >> 4, c4 = (idx & 15) * 4;
            float4 kv = *reinterpret_cast<const float4*>(K + base + (size_t)(kt * 64 + r) * EMB + c4);
            Kt[(c4 + 0) * ATP + r] = kv.x;
            Kt[(c4 + 1) * ATP + r] = kv.y;
            Kt[(c4 + 2) * ATP + r] = kv.z;
            Kt[(c4 + 3) * ATP + r] = kv.w;
            float4 vv = *reinterpret_cast<const float4*>(V + base + (size_t)(kt * 64 + r) * EMB + c4);
            *reinterpret_cast<float4*>(&Vs[r * ATP + c4]) = vv;
        }
        __syncthreads();

        // S = Q @ K^T (outer product over d), 4x4 per thread
        float s[4][4];
#pragma unroll
        for (int i = 0; i < 4; i++)
#pragma unroll
            for (int j = 0; j < 4; j++) s[i][j] = 0.f;
        for (int d = 0; d < 64; d++) {
            float4 qa = *reinterpret_cast<const float4*>(&Qt[d * ATP + ti]);
            float4 kb = *reinterpret_cast<const float4*>(&Kt[d * ATP + tj]);
            float a[4] = {qa.x, qa.y, qa.z, qa.w};
            float bb[4] = {kb.x, kb.y, kb.z, kb.w};
#pragma unroll
            for (int i = 0; i < 4; i++)
#pragma unroll
                for (int j = 0; j < 4; j++) s[i][j] += a[i] * bb[j];
        }
#pragma unroll
        for (int i = 0; i < 4; i++)
#pragma unroll
            for (int j = 0; j < 4; j++)
                Ss[(ti + i) * ATP + tj + j] = s[i][j] * 0.125f;
        __syncthreads();

        // parallel online softmax: warp w owns rows [8w, 8w+8); writes P transposed
        {
            int r0 = warp * 8;
            for (int k = 0; k < 8; k++) {
                int r = r0 + k;
                float x0 = Ss[r * ATP + lane];
                float x1 = Ss[r * ATP + lane + 32];
                float m = fmaxf(x0, x1);
                for (int o2 = 16; o2 > 0; o2 >>= 1)
                    m = fmaxf(m, __shfl_xor_sync(0xffffffff, m, o2));
                float mo = rowm[r];
                float mx = fmaxf(m, mo);
                float p0 = __expf(x0 - mx);
                float p1 = __expf(x1 - mx);
                float sm = p0 + p1;
                for (int o2 = 16; o2 > 0; o2 >>= 1)
                    sm += __shfl_xor_sync(0xffffffff, sm, o2);
                Pt[lane * ATP + r] = p0;
                Pt[(lane + 32) * ATP + r] = p1;
                if (lane == 0) {
                    float f = __expf(mo - mx);
                    rowf[r] = f;
                    rowl[r] = rowl[r] * f + sm;
                    rowm[r] = mx;
                }
            }
        }
        __syncthreads();

        // rescale O accumulators, then O += P @ V (outer product over t)
#pragma unroll
        for (int i = 0; i < 4; i++) {
            float f = rowf[ti + i];
#pragma unroll
            for (int j = 0; j < 4; j++) o[i][j] *= f;
        }
        for (int t = 0; t < 64; t++) {
            float4 pa = *reinterpret_cast<const float4*>(&Pt[t * ATP + ti]);
            float4 vb = *reinterpret_cast<const float4*>(&Vs[t * ATP + tj]);
            float a[4] = {pa.x, pa.y, pa.z, pa.w};
            float bb[4] = {vb.x, vb.y, vb.z, vb.w};
#pragma unroll
            for (int i = 0; i < 4; i++)
#pragma unroll
                for (int j = 0; j < 4; j++) o[i][j] += a[i] * bb[j];
        }
        __syncthreads();
    }
#pragma unroll
    for (int i = 0; i < 4; i++) {
        float inv = 1.0f / rowl[ti + i];
#pragma unroll
        for (int j = 0; j < 4; j++)
            O[base + (size_t)(qt * 64 + ti + i) * EMB + tj + j] = o[i][j] * inv;
    }
}

// ---------------- router: softmax + top-4 + stats ----------------
__global__ __launch_bounds__(128) void router_topk_kernel() {
    const float* __restrict__ logits = g_logits;
    __shared__ float s_imp[NEXP];
    __shared__ int s_cnt[NEXP];
    int tid = threadIdx.x;
    if (tid < NEXP) { s_imp[tid] = 0.f; s_cnt[tid] = 0; }
    __syncthreads();
    int t = blockIdx.x * 128 + tid;
    float p[NEXP];
    float mx = -1e30f;
#pragma unroll
    for (int e = 0; e < NEXP; e++) {
        p[e] = logits[(size_t)t * NEXP + e];
        mx = fmaxf(mx, p[e]);
    }
    float sum = 0.f;
#pragma unroll
    for (int e = 0; e < NEXP; e++) { p[e] = __expf(p[e] - mx); sum += p[e]; }
    float inv = 1.f / sum;
#pragma unroll
    for (int e = 0; e < NEXP; e++) {
        p[e] *= inv;
        atomicAdd(&s_imp[e], p[e]);
    }
    int idx[TOPK];
    float w[TOPK];
    float tot = 0.f;
#pragma unroll
    for (int k = 0; k < TOPK; k++) {
        float best = -1.f;
        int bi = 0;
#pragma unroll
        for (int e = 0; e < NEXP; e++)
            if (p[e] > best) { best = p[e]; bi = e; }
        idx[k] = bi;
        w[k] = best;
        tot += best;
        p[bi] = -1.f;
        atomicAdd(&s_cnt[bi], 1);
    }
    float it = 1.f / tot;
#pragma unroll
    for (int k = 0; k < TOPK; k++) {
        g_topi[t * TOPK + k] = idx[k];
        g_topw[t * TOPK + k] = w[k] * it;
    }
    __syncthreads();
    if (tid < NEXP) {
        atomicAdd(&g_imp[tid], s_imp[tid]);
        atomicAdd(&g_cnt[tid], s_cnt[tid]);
    }
}

// ---------------- prefix scan + aux loss ----------------
__global__ void scan_aux_kernel(float* __restrict__ out, int out_size) {
    if (threadIdx.x == 0) {
        int acc = 0;
        float aux = 0.f;
        for (int e = 0; e < NEXP; e++) {
            g_off[e] = acc;
            acc += g_cnt[e];
            aux += g_imp[e] * (float)g_cnt[e];
        }
        aux *= (float)NEXP / ((float)TOK * (float)TOK);
        if (out_size > TOK * EMB) out[TOK * EMB] = aux;
    }
}

// ---------------- fill per-expert assignment lists ----------------
__global__ __launch_bounds__(128) void fill_assign_kernel() {
    int t = blockIdx.x * 128 + threadIdx.x;
#pragma unroll
    for (int k = 0; k < TOPK; k++) {
        int e = g_topi[t * TOPK + k];
        int pos = atomicAdd(&g_cur[e], 1);
        int gidx = g_off[e] + pos;
        g_atok[gidx] = t;
        g_aw[gidx] = g_topw[t * TOPK + k];
    }
}

__global__ void zero_small_kernel() {
    int i = threadIdx.x;
    if (i < NEXP) { g_imp[i] = 0.f; g_cnt[i] = 0; g_cur[i] = 0; }
}

// ---------------- launch ----------------
extern "C" void kernel_launch(void* const* d_in, const int* in_sizes, int n_in,
                              void* d_out, int out_size) {
    const float* x        = (const float*)d_in[0];
    const float* ln1_g    = (const float*)d_in[1];
    const float* ln1_b    = (const float*)d_in[2];
    const float* wq       = (const float*)d_in[3];
    const float* bq       = (const float*)d_in[4];
    const float* wk       = (const float*)d_in[5];
    const float* bk       = (const float*)d_in[6];
    const float* wv       = (const float*)d_in[7];
    const float* bv       = (const float*)d_in[8];
    const float* wo       = (const float*)d_in[9];
    const float* bo       = (const float*)d_in[10];
    const float* ln2_g    = (const float*)d_in[11];
    const float* ln2_b    = (const float*)d_in[12];
    const float* router_a = (const float*)d_in[13];
    const float* router_b = (const float*)d_in[14];
    const float* re_w1    = (const float*)d_in[15];
    const float* re_b1    = (const float*)d_in[16];
    const float* re_w2    = (const float*)d_in[17];
    const float* re_b2    = (const float*)d_in[18];
    const float* se_w1    = (const float*)d_in[19];
    const float* se_b1    = (const float*)d_in[20];
    const float* se_w2    = (const float*)d_in[21];
    const float* se_b2    = (const float*)d_in[22];
    float* out = (float*)d_out;

    float *p_h1, *p_attn, *p_x1, *p_h2, *p_rlat, *p_logits, *p_hs;
    cudaGetSymbolAddress((void**)&p_h1, g_h1);
    cudaGetSymbolAddress((void**)&p_attn, g_attn);
    cudaGetSymbolAddress((void**)&p_x1, g_x1);
    cudaGetSymbolAddress((void**)&p_h2, g_h2);
    cudaGetSymbolAddress((void**)&p_rlat, g_rlat);
    cudaGetSymbolAddress((void**)&p_logits, g_logits);
    cudaGetSymbolAddress((void**)&p_hs, g_hs);

    cudaFuncSetAttribute(tgemm<0>, cudaFuncAttributeMaxDynamicSharedMemorySize, TG_SMEM);
    cudaFuncSetAttribute(tgemm<1>, cudaFuncAttributeMaxDynamicSharedMemorySize, TG_SMEM);
    cudaFuncSetAttribute(qkv_tgemm, cudaFuncAttributeMaxDynamicSharedMemorySize, TG_SMEM);
    cudaFuncSetAttribute(routed_tgemm1, cudaFuncAttributeMaxDynamicSharedMemorySize, TG_SMEM);
    cudaFuncSetAttribute(routed_tgemm2, cudaFuncAttributeMaxDynamicSharedMemorySize, TG_SMEM);
    cudaFuncSetAttribute(attn_kernel, cudaFuncAttributeMaxDynamicSharedMemorySize, AT_SMEM);

    zero_small_kernel<<<1, 32>>>();
    ln_kernel<<<TOK, 128>>>(x, ln1_g, ln1_b, p_h1);

    qkv_tgemm<<<dim3(4, 32, 3), 256, TG_SMEM>>>(p_h1, wq, wk, wv, bq, bk, bv);

    attn_kernel<<<dim3(32, 16), 256, AT_SMEM>>>();

    dim3 g512(4, 32);
    tgemm<0><<<g512, 256, TG_SMEM>>>(p_attn, wo, bo, x, p_x1, TOK, EMB, EMB);
    ln_kernel<<<TOK, 128>>>(p_x1, ln2_g, ln2_b, p_h2);

    sgemm<0><<<dim3(1, 32), 256>>>(p_h2, router_a, nullptr, nullptr, p_rlat, TOK, RRANK, EMB);
    sgemm<0><<<dim3(1, 32), 256>>>(p_rlat, router_b, nullptr, nullptr, p_logits, TOK, NEXP, RRANK);
    router_topk_kernel<<<TOK / 128, 128>>>();
    scan_aux_kernel<<<1, 32>>>(out, out_size);
    fill_assign_kernel<<<TOK / 128, 128>>>();

    routed_tgemm1<<<dim3(4, 128, 32), 256, TG_SMEM>>>(re_w1, re_b1);

    tgemm<1><<<dim3(32, 32), 256, TG_SMEM>>>(p_h2, se_w1, se_b1, nullptr, p_hs, TOK, SHID, EMB);
    tgemm<0><<<dim3(4, 32), 256, TG_SMEM>>>(p_hs, se_w2, se_b2, p_x1, out, TOK, EMB, SHID);

    routed_tgemm2<<<dim3(4, 128, 32), 256, TG_SMEM>>>(re_w2, re_b2, out);
}

// round 10
// speedup vs baseline: 1.0922x; 1.0427x over previous
#include <cuda_runtime.h>
#include <math.h>

// ---------------- problem constants ----------------
#define TOK   4096          // B*S = 4*1024
#define SEQ   1024
#define BATCH 4
#define EMB   512
#define NH    8
#define HD    64
#define NEXP  32
#define TOPK  4
#define RRANK 64
#define SHID  4096
#define EHID  512

// ---------------- device scratch (static, allocation-free) ----------------
__device__ float g_h1[TOK * EMB];
__device__ float g_q[TOK * EMB];
__device__ float g_k[TOK * EMB];
__device__ float g_v[TOK * EMB];
__device__ float g_attn[TOK * EMB];
__device__ float g_x1[TOK * EMB];
__device__ float g_h2[TOK * EMB];
__device__ float g_rlat[TOK * RRANK];
__device__ float g_logits[TOK * NEXP];
__device__ int   g_topi[TOK * TOPK];
__device__ float g_topw[TOK * TOPK];
__device__ float g_imp[NEXP];
__device__ int   g_cnt[NEXP];
__device__ int   g_off[NEXP];
__device__ int   g_cur[NEXP];
__device__ int   g_atok[TOK * TOPK];
__device__ float g_aw[TOK * TOPK];
__device__ float g_H[TOK * TOPK * EHID];   // routed hidden
__device__ float g_hs[TOK * SHID];         // shared-expert hidden

// ---------------- helpers ----------------
__device__ __forceinline__ float gelu_tanh(float x) {
    float x3 = x * x * x;
    return 0.5f * x * (1.0f + tanhf(0.7978845608028654f * (x + 0.044715f * x3)));
}

__device__ __forceinline__ unsigned f2tf32(float f) {
    unsigned r;
    asm("cvt.rna.tf32.f32 %0, %1;" : "=r"(r) : "f"(f));
    return r;
}

__device__ __forceinline__ void tf32_split(float f, unsigned& hi, unsigned& lo) {
    hi = f2tf32(f);
    lo = f2tf32(f - __uint_as_float(hi));
}

__device__ __forceinline__ void mma_tf32(float& c0, float& c1, float& c2, float& c3,
                                         unsigned a0, unsigned a1, unsigned a2, unsigned a3,
                                         unsigned b0, unsigned b1) {
    asm volatile(
        "mma.sync.aligned.m16n8k8.row.col.f32.tf32.tf32.f32 "
        "{%0,%1,%2,%3}, {%4,%5,%6,%7}, {%8,%9}, {%0,%1,%2,%3};"
        : "+f"(c0), "+f"(c1), "+f"(c2), "+f"(c3)
        : "r"(a0), "r"(a1), "r"(a2), "r"(a3), "r"(b0), "r"(b1));
}

__device__ __forceinline__ void cp16(float* s, const float* g) {
    unsigned sa = (unsigned)__cvta_generic_to_shared(s);
    asm volatile("cp.async.cg.shared.global [%0], [%1], 16;" :: "r"(sa), "l"(g));
}
__device__ __forceinline__ void cp_commit() {
    asm volatile("cp.async.commit_group;");
}

// ================= 3xTF32 tensor-core GEMM, cp.async double-buffered ============
// BM=128, BN=128, BK=32, 256 threads = 8 warps (2 M x 4 N), warp tile 64x32.
#define APAD 36
#define BPAD 136
#define ASZ (128 * APAD)
#define BSZ (32 * BPAD)
#define TG_SMEM ((2 * ASZ + 2 * BSZ) * 4)   // 71680 bytes

// EPI 0: plain store (bias/act/res), A rows identity.
// EPI 1: gelu -> C[off+m] store; A rows GATHERED via atok[off+m].
// EPI 2: atomic scatter to C[tok] with bias+gate; A rows LOCAL (bounded by cnt).
// EPI 3: plain atomicAdd (split-K accumulate), no bias/res; A rows identity.
template <int ACT, int EPI>
__device__ __forceinline__ void tgemm_body(
    const float* __restrict__ A, const float* __restrict__ B,
    const float* __restrict__ bias, const float* __restrict__ res,
    float* __restrict__ C, int M, int N, int K, int Kstride,
    int row0, int col0,
    const int* __restrict__ atok, const float* __restrict__ aw,
    int cnt, int off) {

    extern __shared__ float dsm[];
    float* As = dsm;                 // [2][ASZ]
    float* Bs = dsm + 2 * ASZ;       // [2][BSZ]

    int tid = threadIdx.x;
    int warp = tid >> 5, lane = tid & 31;
    int wm = warp >> 2, wn = warp & 3;
    int g = lane >> 2, t = lane & 3;

    int arow = tid >> 1, acb = (tid & 1) * 16;
    int brow = tid >> 3, bcb = (tid & 7) * 16;

    int asrc;
    if (EPI == 1) {
        int m = row0 + arow;
        asrc = (m < cnt) ? atok[off + m] : 0;
    } else if (EPI == 2) {
        int m = row0 + arow;
        asrc = (m < cnt) ? m : 0;
    } else {
        asrc = row0 + arow;
    }

    const float* Asrc = A + (size_t)asrc * Kstride + acb;
    const float* Bsrc = B + (size_t)brow * N + col0 + bcb;

    float c[4][4][4];
#pragma unroll
    for (int i = 0; i < 4; i++)
#pragma unroll
        for (int j = 0; j < 4; j++) { c[i][j][0] = c[i][j][1] = c[i][j][2] = c[i][j][3] = 0.f; }

    int NS = K / 32;
    {
        float* da = As + arow * APAD + acb;
        float* db = Bs + brow * BPAD + bcb;
#pragma unroll
        for (int i = 0; i < 4; i++) cp16(da + i * 4, Asrc + i * 4);
#pragma unroll
        for (int i = 0; i < 4; i++) cp16(db + i * 4, Bsrc + i * 4);
        cp_commit();
    }

    for (int s = 0; s < NS; s++) {
        if (s + 1 < NS) {
            int buf = (s + 1) & 1;
            int k0 = (s + 1) * 32;
            float* da = As + buf * ASZ + arow * APAD + acb;
            float* db = Bs + buf * BSZ + brow * BPAD + bcb;
#pragma unroll
            for (int i = 0; i < 4; i++) cp16(da + i * 4, Asrc + k0 + i * 4);
#pragma unroll
            for (int i = 0; i < 4; i++) cp16(db + i * 4, Bsrc + (size_t)k0 * N + i * 4);
            cp_commit();
            asm volatile("cp.async.wait_group 1;");
        } else {
            asm volatile("cp.async.wait_group 0;");
        }
        __syncthreads();

        const float* Ab = As + (s & 1) * ASZ;
        const float* Bb = Bs + (s & 1) * BSZ;
#pragma unroll
        for (int kk = 0; kk < 4; kk++) {
            int kb = kk * 8;
            unsigned ah[4][4], al[4][4], bh[4][2], bl[4][2];
#pragma unroll
            for (int mt = 0; mt < 4; mt++) {
                int mb = wm * 64 + mt * 16;
                int i0 = (mb + g) * APAD + kb + t;
                int i1 = (mb + g + 8) * APAD + kb + t;
                tf32_split(Ab[i0],     ah[mt][0], al[mt][0]);
                tf32_split(Ab[i1],     ah[mt][1], al[mt][1]);
                tf32_split(Ab[i0 + 4], ah[mt][2], al[mt][2]);
                tf32_split(Ab[i1 + 4], ah[mt][3], al[mt][3]);
            }
#pragma unroll
            for (int nt = 0; nt < 4; nt++) {
                int nb = wn * 32 + nt * 8;
                tf32_split(Bb[(kb + t) * BPAD + nb + g],     bh[nt][0], bl[nt][0]);
                tf32_split(Bb[(kb + t + 4) * BPAD + nb + g], bh[nt][1], bl[nt][1]);
            }
#pragma unroll
            for (int mt = 0; mt < 4; mt++)
#pragma unroll
                for (int nt = 0; nt < 4; nt++) {
                    mma_tf32(c[mt][nt][0], c[mt][nt][1], c[mt][nt][2], c[mt][nt][3],
                             al[mt][0], al[mt][1], al[mt][2], al[mt][3],
                             bh[nt][0], bh[nt][1]);
                    mma_tf32(c[mt][nt][0], c[mt][nt][1], c[mt][nt][2], c[mt][nt][3],
                             ah[mt][0], ah[mt][1], ah[mt][2], ah[mt][3],
                             bl[nt][0], bl[nt][1]);
                    mma_tf32(c[mt][nt][0], c[mt][nt][1], c[mt][nt][2], c[mt][nt][3],
                             ah[mt][0], ah[mt][1], ah[mt][2], ah[mt][3],
                             bh[nt][0], bh[nt][1]);
                }
        }
        __syncthreads();
    }

#pragma unroll
    for (int mt = 0; mt < 4; mt++) {
        int mb = row0 + wm * 64 + mt * 16;
#pragma unroll
        for (int nt = 0; nt < 4; nt++) {
            int nb = col0 + wn * 32 + nt * 8 + 2 * t;
#pragma unroll
            for (int half = 0; half < 2; half++) {
                int r = mb + g + half * 8;
                float v0 = c[mt][nt][half * 2 + 0];
                float v1 = c[mt][nt][half * 2 + 1];
                if (EPI == 0) {
                    if (bias) { v0 += bias[nb]; v1 += bias[nb + 1]; }
                    if (ACT == 1) { v0 = gelu_tanh(v0); v1 = gelu_tanh(v1); }
                    if (res) {
                        v0 += res[(size_t)r * N + nb];
                        v1 += res[(size_t)r * N + nb + 1];
                    }
                    C[(size_t)r * N + nb] = v0;
                    C[(size_t)r * N + nb + 1] = v1;
                } else if (EPI == 1) {
                    if (r < cnt) {
                        C[(size_t)(off + r) * N + nb] = gelu_tanh(v0 + bias[nb]);
                        C[(size_t)(off + r) * N + nb + 1] = gelu_tanh(v1 + bias[nb + 1]);
                    }
                } else if (EPI == 2) {
                    if (r < cnt) {
                        int tok = atok[off + r];
                        float wgt = aw[off + r];
                        atomicAdd(&C[(size_t)tok * N + nb], (v0 + bias[nb]) * wgt);
                        atomicAdd(&C[(size_t)tok * N + nb + 1], (v1 + bias[nb + 1]) * wgt);
                    }
                } else {  // EPI == 3: split-K accumulate
                    atomicAdd(&C[(size_t)r * N + nb], v0);
                    atomicAdd(&C[(size_t)r * N + nb + 1], v1);
                }
            }
        }
    }
}

template <int ACT>
__global__ __launch_bounds__(256) void tgemm(const float* __restrict__ A,
                                             const float* __restrict__ B,
                                             const float* __restrict__ bias,
                                             const float* __restrict__ res,
                                             float* __restrict__ C,
                                             int M, int N, int K) {
    tgemm_body<ACT, 0>(A, B, bias, res, C, M, N, K, K,
                       blockIdx.y * 128, blockIdx.x * 128, nullptr, nullptr, 0, 0);
}

__global__ __launch_bounds__(256) void qkv_tgemm(const float* __restrict__ A,
                                                 const float* __restrict__ wq,
                                                 const float* __restrict__ wk,
                                                 const float* __restrict__ wv,
                                                 const float* __restrict__ bq,
                                                 const float* __restrict__ bk,
                                                 const float* __restrict__ bv) {
    int z = blockIdx.z;
    const float* W = (z == 0) ? wq : (z == 1) ? wk : wv;
    const float* bias = (z == 0) ? bq : (z == 1) ? bk : bv;
    float* C = (z == 0) ? g_q : (z == 1) ? g_k : g_v;
    tgemm_body<0, 0>(A, W, bias, nullptr, C, TOK, EMB, EMB, EMB,
                     blockIdx.y * 128, blockIdx.x * 128, nullptr, nullptr, 0, 0);
}

__global__ __launch_bounds__(256) void routed_tgemm1(const float* __restrict__ W1all,
                                                     const float* __restrict__ b1all) {
    int e = blockIdx.z;
    int cnt = g_cnt[e];
    int m0 = blockIdx.y * 128;
    if (m0 >= cnt) return;
    tgemm_body<0, 1>(g_h2, W1all + (size_t)e * EMB * EHID, b1all + (size_t)e * EHID,
                     nullptr, g_H, TOK, EHID, EMB, EMB,
                     m0, blockIdx.x * 128, g_atok, nullptr, cnt, g_off[e]);
}

__global__ __launch_bounds__(256) void routed_tgemm2(const float* __restrict__ W2all,
                                                     const float* __restrict__ b2all,
                                                     float* __restrict__ out) {
    int e = blockIdx.z;
    int cnt = g_cnt[e];
    int m0 = blockIdx.y * 128;
    if (m0 >= cnt) return;
    int off = g_off[e];
    tgemm_body<0, 2>(g_H + (size_t)off * EHID, W2all + (size_t)e * EHID * EMB,
                     b2all + (size_t)e * EMB, nullptr, out, TOK, EMB, EHID, EHID,
                     m0, blockIdx.x * 128, g_atok, g_aw, cnt, off);
}

// shared-expert GEMM2 split-K: out += hs[:, kc*1024:(kc+1)*1024] @ w2[kc*1024:...]
#define KSPLIT 4
#define KCH (SHID / KSPLIT)
__global__ __launch_bounds__(256) void shared2_splitk(const float* __restrict__ hs,
                                                      const float* __restrict__ w2,
                                                      float* __restrict__ out) {
    int kc = blockIdx.z;
    tgemm_body<0, 3>(hs + (size_t)kc * KCH, w2 + (size_t)kc * KCH * EMB,
                     nullptr, nullptr, out, TOK, EMB, KCH, SHID,
                     blockIdx.y * 128, blockIdx.x * 128, nullptr, nullptr, 0, 0);
}

// init out = x1 + se_b2 (so shared2/routed2 can accumulate atomically)
__global__ __launch_bounds__(256) void init_out_kernel(const float* __restrict__ x1,
                                                       const float* __restrict__ b2,
                                                       float* __restrict__ out) {
    int i = blockIdx.x * 256 + threadIdx.x;   // float4 index
    float4 v = reinterpret_cast<const float4*>(x1)[i];
    int col = (i * 4) & (EMB - 1);
    float4 b = *reinterpret_cast<const float4*>(b2 + col);
    v.x += b.x; v.y += b.y; v.z += b.z; v.w += b.w;
    reinterpret_cast<float4*>(out)[i] = v;
}

// ---------------- LayerNorm ----------------
__global__ __launch_bounds__(128) void ln_kernel(const float* __restrict__ X,
                                                 const float* __restrict__ g,
                                                 const float* __restrict__ b,
                                                 float* __restrict__ Y) {
    int t = blockIdx.x;
    int tid = threadIdx.x;
    const float4 v = *reinterpret_cast<const float4*>(X + (size_t)t * EMB + tid * 4);
    float s  = v.x + v.y + v.z + v.w;
    float sq = v.x * v.x + v.y * v.y + v.z * v.z + v.w * v.w;
    for (int o = 16; o > 0; o >>= 1) {
        s  += __shfl_xor_sync(0xffffffff, s, o);
        sq += __shfl_xor_sync(0xffffffff, sq, o);
    }
    __shared__ float ssum[4], ssq[4], stats[2];
    int w = tid >> 5;
    if ((tid & 31) == 0) { ssum[w] = s; ssq[w] = sq; }
    __syncthreads();
    if (tid == 0) {
        float S = ssum[0] + ssum[1] + ssum[2] + ssum[3];
        float Q = ssq[0] + ssq[1] + ssq[2] + ssq[3];
        float mu = S * (1.0f / EMB);
        float var = Q * (1.0f / EMB) - mu * mu;
        stats[0] = mu;
        stats[1] = rsqrtf(var + 1e-5f);
    }
    __syncthreads();
    float mu = stats[0], rs = stats[1];
    int cc = tid * 4;
    float4 gg = *reinterpret_cast<const float4*>(g + cc);
    float4 bb = *reinterpret_cast<const float4*>(b + cc);
    float4 o;
    o.x = (v.x - mu) * rs * gg.x + bb.x;
    o.y = (v.y - mu) * rs * gg.y + bb.y;
    o.z = (v.z - mu) * rs * gg.z + bb.z;
    o.w = (v.w - mu) * rs * gg.w + bb.w;
    *reinterpret_cast<float4*>(Y + (size_t)t * EMB + cc) = o;
}

// ---------------- fp32 SGEMM (router only, small N) ----------------
template <int ACT>
__global__ __launch_bounds__(256) void sgemm(const float* __restrict__ A,
                                             const float* __restrict__ B,
                                             const float* __restrict__ bias,
                                             const float* __restrict__ res,
                                             float* __restrict__ C,
                                             int M, int N, int K) {
    __shared__ float As[8][128];
    __shared__ float Bs[8][128];
    int tid = threadIdx.x;
    int row0 = blockIdx.y * 128, col0 = blockIdx.x * 128;
    int aRow = tid >> 1, aCol = (tid & 1) * 4;
    int bRow = tid >> 5, bCol = (tid & 31) * 4;
    int tr = (tid >> 4) * 8, tc = (tid & 15) * 8;

    float acc[8][8];
#pragma unroll
    for (int i = 0; i < 8; i++)
#pragma unroll
        for (int j = 0; j < 8; j++) acc[i][j] = 0.f;

    const float* Ap = A + (size_t)(row0 + aRow) * K + aCol;
    for (int k0 = 0; k0 < K; k0 += 8) {
        float4 av = *reinterpret_cast<const float4*>(Ap + k0);
        As[aCol + 0][aRow] = av.x;
        As[aCol + 1][aRow] = av.y;
        As[aCol + 2][aRow] = av.z;
        As[aCol + 3][aRow] = av.w;
        int gc = col0 + bCol;
        const float* Bp = B + (size_t)(k0 + bRow) * N + gc;
        float4 bv;
        if (gc + 3 < N) {
            bv = *reinterpret_cast<const float4*>(Bp);
        } else {
            bv.x = (gc + 0 < N) ? Bp[0] : 0.f;
            bv.y = (gc + 1 < N) ? Bp[1] : 0.f;
            bv.z = (gc + 2 < N) ? Bp[2] : 0.f;
            bv.w = (gc + 3 < N) ? Bp[3] : 0.f;
        }
        Bs[bRow][bCol + 0] = bv.x;
        Bs[bRow][bCol + 1] = bv.y;
        Bs[bRow][bCol + 2] = bv.z;
        Bs[bRow][bCol + 3] = bv.w;
        __syncthreads();
#pragma unroll
        for (int k = 0; k < 8; k++) {
            float4 ra0 = *reinterpret_cast<const float4*>(&As[k][tr]);
            float4 ra1 = *reinterpret_cast<const float4*>(&As[k][tr + 4]);
            float4 rb0 = *reinterpret_cast<const float4*>(&Bs[k][tc]);
            float4 rb1 = *reinterpret_cast<const float4*>(&Bs[k][tc + 4]);
            float ra[8] = {ra0.x, ra0.y, ra0.z, ra0.w, ra1.x, ra1.y, ra1.z, ra1.w};
            float rb[8] = {rb0.x, rb0.y, rb0.z, rb0.w, rb1.x, rb1.y, rb1.z, rb1.w};
#pragma unroll
            for (int i = 0; i < 8; i++)
#pragma unroll
                for (int j = 0; j < 8; j++) acc[i][j] += ra[i] * rb[j];
        }
        __syncthreads();
    }
#pragma unroll
    for (int i = 0; i < 8; i++) {
        int gr = row0 + tr + i;
#pragma unroll
        for (int j = 0; j < 8; j++) {
            int gc = col0 + tc + j;
            if (gc < N) {
                float v = acc[i][j];
                if (bias) v += bias[gc];
                if (ACT == 1) v = gelu_tanh(v);
                if (res) v += res[(size_t)gr * N + gc];
                C[(size_t)gr * N + gc] = v;
            }
        }
    }
}

// ---------------- flash attention v3: register softmax, no score smem ----------
// 256 thr, per-thread 4x4; row-group = 16 threads sharing 4 q-rows (shuffle
// reductions). P stored row-major [q][k] (odd pitch 65): STS 2-way, PV reads
// broadcast scalars. smem: Qt/Kt/Vs 64x68 + Ps 64x65 = 68.9 KB.
#define ATP 68
#define PSP 65
#define AT_SMEM ((3 * 64 * ATP + 64 * PSP) * 4)

__global__ __launch_bounds__(256) void attn_kernel() {
    const float* __restrict__ Q = g_q;
    const float* __restrict__ K = g_k;
    const float* __restrict__ V = g_v;
    float* __restrict__ O = g_attn;

    extern __shared__ float dsm[];
    float* Qt = dsm;                 // [d][qrow]
    float* Kt = Qt + 64 * ATP;       // [d][krow]
    float* Vs = Kt + 64 * ATP;       // [krow][d]
    float* Ps = Vs + 64 * ATP;       // [qrow][krow] pitch 65
    __shared__ float rowm[64], rowl[64];

    int bh = blockIdx.x;
    int qt = blockIdx.y;
    int b = bh >> 3, h = bh & 7;
    const size_t base = (size_t)b * SEQ * EMB + h * HD;
    int tid = threadIdx.x;
    int ti = (tid >> 4) * 4;         // q-row group of 4
    int tj = (tid & 15) * 4;         // k-col / d-col group of 4
    bool glead = ((tid & 15) == 0);  // one leader per row group

    for (int idx = tid; idx < 64 * 16; idx += 256) {
        int r = idx >> 4, c4 = (idx & 15) * 4;
        float4 qv = *reinterpret_cast<const float4*>(Q + base + (size_t)(qt * 64 + r) * EMB + c4);
        Qt[(c4 + 0) * ATP + r] = qv.x;
        Qt[(c4 + 1) * ATP + r] = qv.y;
        Qt[(c4 + 2) * ATP + r] = qv.z;
        Qt[(c4 + 3) * ATP + r] = qv.w;
    }
    if (tid < 64) { rowm[tid] = -1e30f; rowl[tid] = 0.f; }

    float o[4][4];
#pragma unroll
    for (int i = 0; i < 4; i++)
#pragma unroll
        for (int j = 0; j < 4; j++) o[i][j] = 0.f;
    __syncthreads();

    for (int kt = 0; kt < SEQ / 64; kt++) {
        for (int idx = tid; idx < 64 * 16; idx += 256) {
            int r = idx >> 4, c4 = (idx & 15) * 4;
            float4 kv = *reinterpret_cast<const float4*>(K + base + (size_t)(kt * 64 + r) * EMB + c4);
            Kt[(c4 + 0) * ATP + r] = kv.x;
            Kt[(c4 + 1) * ATP + r] = kv.y;
            Kt[(c4 + 2) * ATP + r] = kv.z;
            Kt[(c4 + 3) * ATP + r] = kv.w;
            float4 vv = *reinterpret_cast<const float4*>(V + base + (size_t)(kt * 64 + r) * EMB + c4);
            *reinterpret_cast<float4*>(&Vs[r * ATP + c4]) = vv;
        }
        __syncthreads();

        // S = Q @ K^T * 0.125 in registers
        float s[4][4];
#pragma unroll
        for (int i = 0; i < 4; i++)
#pragma unroll
            for (int j = 0; j < 4; j++) s[i][j] = 0.f;
        for (int d = 0; d < 64; d++) {
            float4 qa = *reinterpret_cast<const float4*>(&Qt[d * ATP + ti]);
            float4 kb = *reinterpret_cast<const float4*>(&Kt[d * ATP + tj]);
            float a[4] = {qa.x, qa.y, qa.z, qa.w};
            float bb[4] = {kb.x, kb.y, kb.z, kb.w};
#pragma unroll
            for (int i = 0; i < 4; i++)
#pragma unroll
                for (int j = 0; j < 4; j++) s[i][j] += a[i] * bb[j];
        }

        // register softmax per row (16-lane shuffle groups), write P to smem
        float fi[4];
#pragma unroll
        for (int i = 0; i < 4; i++) {
            int r = ti + i;
            float mloc = fmaxf(fmaxf(s[i][0], s[i][1]), fmaxf(s[i][2], s[i][3])) * 0.125f;
#pragma unroll
            for (int off = 8; off > 0; off >>= 1)
                mloc = fmaxf(mloc, __shfl_xor_sync(0xffffffff, mloc, off));
            float mo = rowm[r];
            float mx = fmaxf(mloc, mo);
            float p0 = __expf(s[i][0] * 0.125f - mx);
            float p1 = __expf(s[i][1] * 0.125f - mx);
            float p2 = __expf(s[i][2] * 0.125f - mx);
            float p3 = __expf(s[i][3] * 0.125f - mx);
            float sm = p0 + p1 + p2 + p3;
#pragma unroll
            for (int off = 8; off > 0; off >>= 1)
                sm += __shfl_xor_sync(0xffffffff, sm, off);
            Ps[r * PSP + tj + 0] = p0;
            Ps[r * PSP + tj + 1] = p1;
            Ps[r * PSP + tj + 2] = p2;
            Ps[r * PSP + tj + 3] = p3;
            float f = __expf(mo - mx);
            fi[i] = f;
            if (glead) {
                rowl[r] = rowl[r] * f + sm;
                rowm[r] = mx;
            }
        }
        __syncthreads();

        // O rescale + O += P @ V
#pragma unroll
        for (int i = 0; i < 4; i++)
#pragma unroll
            for (int j = 0; j < 4; j++) o[i][j] *= fi[i];
        for (int t = 0; t < 64; t++) {
            float p0 = Ps[(ti + 0) * PSP + t];
            float p1 = Ps[(ti + 1) * PSP + t];
            float p2 = Ps[(ti + 2) * PSP + t];
            float p3 = Ps[(ti + 3) * PSP + t];
            float4 vb = *reinterpret_cast<const float4*>(&Vs[t * ATP + tj]);
            o[0][0] += p0 * vb.x; o[0][1] += p0 * vb.y; o[0][2] += p0 * vb.z; o[0][3] += p0 * vb.w;
            o[1][0] += p1 * vb.x; o[1][1] += p1 * vb.y; o[1][2] += p1 * vb.z; o[1][3] += p1 * vb.w;
            o[2][0] += p2 * vb.x; o[2][1] += p2 * vb.y; o[2][2] += p2 * vb.z; o[2][3] += p2 * vb.w;
            o[3][0] += p3 * vb.x; o[3][1] += p3 * vb.y; o[3][2] += p3 * vb.z; o[3][3] += p3 * vb.w;
        }
        __syncthreads();
    }
#pragma unroll
    for (int i = 0; i < 4; i++) {
        float inv = 1.0f / rowl[ti + i];
#pragma unroll
        for (int j = 0; j < 4; j++)
            O[base + (size_t)(qt * 64 + ti + i) * EMB + tj + j] = o[i][j] * inv;
    }
}

// ---------------- router: softmax + top-4 + stats ----------------
__global__ __launch_bounds__(128) void router_topk_kernel() {
    const float* __restrict__ logits = g_logits;
    __shared__ float s_imp[NEXP];
    __shared__ int s_cnt[NEXP];
    int tid = threadIdx.x;
    if (tid < NEXP) { s_imp[tid] = 0.f; s_cnt[tid] = 0; }
    __syncthreads();
    int t = blockIdx.x * 128 + tid;
    float p[NEXP];
    float mx = -1e30f;
#pragma unroll
    for (int e = 0; e < NEXP; e++) {
        p[e] = logits[(size_t)t * NEXP + e];
        mx = fmaxf(mx, p[e]);
    }
    float sum = 0.f;
#pragma unroll
    for (int e = 0; e < NEXP; e++) { p[e] = __expf(p[e] - mx); sum += p[e]; }
    float inv = 1.f / sum;
#pragma unroll
    for (int e = 0; e < NEXP; e++) {
        p[e] *= inv;
        atomicAdd(&s_imp[e], p[e]);
    }
    int idx[TOPK];
    float w[TOPK];
    float tot = 0.f;
#pragma unroll
    for (int k = 0; k < TOPK; k++) {
        float best = -1.f;
        int bi = 0;
#pragma unroll
        for (int e = 0; e < NEXP; e++)
            if (p[e] > best) { best = p[e]; bi = e; }
        idx[k] = bi;
        w[k] = best;
        tot += best;
        p[bi] = -1.f;
        atomicAdd(&s_cnt[bi], 1);
    }
    float it = 1.f / tot;
#pragma unroll
    for (int k = 0; k < TOPK; k++) {
        g_topi[t * TOPK + k] = idx[k];
        g_topw[t * TOPK + k] = w[k] * it;
    }
    __syncthreads();
    if (tid < NEXP) {
        atomicAdd(&g_imp[tid], s_imp[tid]);
        atomicAdd(&g_cnt[tid], s_cnt[tid]);
    }
}

// ---------------- prefix scan + aux loss ----------------
__global__ void scan_aux_kernel(float* __restrict__ out, int out_size) {
    if (threadIdx.x == 0) {
        int acc = 0;
        float aux = 0.f;
        for (int e = 0; e < NEXP; e++) {
            g_off[e] = acc;
            acc += g_cnt[e];
            aux += g_imp[e] * (float)g_cnt[e];
        }
        aux *= (float)NEXP / ((float)TOK * (float)TOK);
        if (out_size > TOK * EMB) out[TOK * EMB] = aux;
    }
}

// ---------------- fill per-expert assignment lists ----------------
__global__ __launch_bounds__(128) void fill_assign_kernel() {
    int t = blockIdx.x * 128 + threadIdx.x;
#pragma unroll
    for (int k = 0; k < TOPK; k++) {
        int e = g_topi[t * TOPK + k];
        int pos = atomicAdd(&g_cur[e], 1);
        int gidx = g_off[e] + pos;
        g_atok[gidx] = t;
        g_aw[gidx] = g_topw[t * TOPK + k];
    }
}

__global__ void zero_small_kernel() {
    int i = threadIdx.x;
    if (i < NEXP) { g_imp[i] = 0.f; g_cnt[i] = 0; g_cur[i] = 0; }
}

// ---------------- launch ----------------
extern "C" void kernel_launch(void* const* d_in, const int* in_sizes, int n_in,
                              void* d_out, int out_size) {
    const float* x        = (const float*)d_in[0];
    const float* ln1_g    = (const float*)d_in[1];
    const float* ln1_b    = (const float*)d_in[2];
    const float* wq       = (const float*)d_in[3];
    const float* bq       = (const float*)d_in[4];
    const float* wk       = (const float*)d_in[5];
    const float* bk       = (const float*)d_in[6];
    const float* wv       = (const float*)d_in[7];
    const float* bv       = (const float*)d_in[8];
    const float* wo       = (const float*)d_in[9];
    const float* bo       = (const float*)d_in[10];
    const float* ln2_g    = (const float*)d_in[11];
    const float* ln2_b    = (const float*)d_in[12];
    const float* router_a = (const float*)d_in[13];
    const float* router_b = (const float*)d_in[14];
    const float* re_w1    = (const float*)d_in[15];
    const float* re_b1    = (const float*)d_in[16];
    const float* re_w2    = (const float*)d_in[17];
    const float* re_b2    = (const float*)d_in[18];
    const float* se_w1    = (const float*)d_in[19];
    const float* se_b1    = (const float*)d_in[20];
    const float* se_w2    = (const float*)d_in[21];
    const float* se_b2    = (const float*)d_in[22];
    float* out = (float*)d_out;

    float *p_h1, *p_attn, *p_x1, *p_h2, *p_rlat, *p_logits, *p_hs;
    cudaGetSymbolAddress((void**)&p_h1, g_h1);
    cudaGetSymbolAddress((void**)&p_attn, g_attn);
    cudaGetSymbolAddress((void**)&p_x1, g_x1);
    cudaGetSymbolAddress((void**)&p_h2, g_h2);
    cudaGetSymbolAddress((void**)&p_rlat, g_rlat);
    cudaGetSymbolAddress((void**)&p_logits, g_logits);
    cudaGetSymbolAddress((void**)&p_hs, g_hs);

    cudaFuncSetAttribute(tgemm<0>, cudaFuncAttributeMaxDynamicSharedMemorySize, TG_SMEM);
    cudaFuncSetAttribute(tgemm<1>, cudaFuncAttributeMaxDynamicSharedMemorySize, TG_SMEM);
    cudaFuncSetAttribute(qkv_tgemm, cudaFuncAttributeMaxDynamicSharedMemorySize, TG_SMEM);
    cudaFuncSetAttribute(routed_tgemm1, cudaFuncAttributeMaxDynamicSharedMemorySize, TG_SMEM);
    cudaFuncSetAttribute(routed_tgemm2, cudaFuncAttributeMaxDynamicSharedMemorySize, TG_SMEM);
    cudaFuncSetAttribute(shared2_splitk, cudaFuncAttributeMaxDynamicSharedMemorySize, TG_SMEM);
    cudaFuncSetAttribute(attn_kernel, cudaFuncAttributeMaxDynamicSharedMemorySize, AT_SMEM);

    zero_small_kernel<<<1, 32>>>();
    ln_kernel<<<TOK, 128>>>(x, ln1_g, ln1_b, p_h1);

    qkv_tgemm<<<dim3(4, 32, 3), 256, TG_SMEM>>>(p_h1, wq, wk, wv, bq, bk, bv);

    attn_kernel<<<dim3(32, 16), 256, AT_SMEM>>>();

    dim3 g512(4, 32);
    tgemm<0><<<g512, 256, TG_SMEM>>>(p_attn, wo, bo, x, p_x1, TOK, EMB, EMB);
    ln_kernel<<<TOK, 128>>>(p_x1, ln2_g, ln2_b, p_h2);

    sgemm<0><<<dim3(1, 32), 256>>>(p_h2, router_a, nullptr, nullptr, p_rlat, TOK, RRANK, EMB);
    sgemm<0><<<dim3(1, 32), 256>>>(p_rlat, router_b, nullptr, nullptr, p_logits, TOK, NEXP, RRANK);
    router_topk_kernel<<<TOK / 128, 128>>>();
    scan_aux_kernel<<<1, 32>>>(out, out_size);
    fill_assign_kernel<<<TOK / 128, 128>>>();

    // routed experts: per-expert max rows = TOK -> 32 m-tiles
    routed_tgemm1<<<dim3(4, 32, 32), 256, TG_SMEM>>>(re_w1, re_b1);

    // shared expert
    tgemm<1><<<dim3(32, 32), 256, TG_SMEM>>>(p_h2, se_w1, se_b1, nullptr, p_hs, TOK, SHID, EMB);

    // out = x1 + b2, then atomic accumulation from shared2 (split-K) and routed2
    init_out_kernel<<<(TOK * EMB / 4) / 256, 256>>>(p_x1, se_b2, out);
    shared2_splitk<<<dim3(4, 32, KSPLIT), 256, TG_SMEM>>>(p_hs, se_w2, out);
    routed_tgemm2<<<dim3(4, 32, 32), 256, TG_SMEM>>>(re_w2, re_b2, out);
}

// round 11
// speedup vs baseline: 1.1039x; 1.0107x over previous
#include <cuda_runtime.h>
#include <math.h>

// ---------------- problem constants ----------------
#define TOK   4096          // B*S = 4*1024
#define SEQ   1024
#define BATCH 4
#define EMB   512
#define NH    8
#define HD    64
#define NEXP  32
#define TOPK  4
#define RRANK 64
#define SHID  4096
#define EHID  512

// ---------------- device scratch (static, allocation-free) ----------------
__device__ float g_h1[TOK * EMB];
__device__ float g_q[TOK * EMB];
__device__ float g_k[TOK * EMB];
__device__ float g_v[TOK * EMB];
__device__ float g_attn[TOK * EMB];
__device__ float g_x1[TOK * EMB];
__device__ float g_h2[TOK * EMB];
__device__ float g_rlat[TOK * RRANK];
__device__ float g_logits[TOK * NEXP];
__device__ int   g_topi[TOK * TOPK];
__device__ float g_topw[TOK * TOPK];
__device__ float g_imp[NEXP];
__device__ int   g_cnt[NEXP];
__device__ int   g_off[NEXP];
__device__ int   g_cur[NEXP];
__device__ int   g_atok[TOK * TOPK];
__device__ float g_aw[TOK * TOPK];
__device__ float g_H[TOK * TOPK * EHID];   // routed hidden
__device__ float g_hs[TOK * SHID];         // shared-expert hidden

// ---------------- helpers ----------------
__device__ __forceinline__ float gelu_tanh(float x) {
    float x3 = x * x * x;
    return 0.5f * x * (1.0f + tanhf(0.7978845608028654f * (x + 0.044715f * x3)));
}

__device__ __forceinline__ unsigned f2tf32(float f) {
    unsigned r;
    asm("cvt.rna.tf32.f32 %0, %1;" : "=r"(r) : "f"(f));
    return r;
}

__device__ __forceinline__ void tf32_split(float f, unsigned& hi, unsigned& lo) {
    hi = f2tf32(f);
    lo = f2tf32(f - __uint_as_float(hi));
}

__device__ __forceinline__ void mma_tf32(float& c0, float& c1, float& c2, float& c3,
                                         unsigned a0, unsigned a1, unsigned a2, unsigned a3,
                                         unsigned b0, unsigned b1) {
    asm volatile(
        "mma.sync.aligned.m16n8k8.row.col.f32.tf32.tf32.f32 "
        "{%0,%1,%2,%3}, {%4,%5,%6,%7}, {%8,%9}, {%0,%1,%2,%3};"
        : "+f"(c0), "+f"(c1), "+f"(c2), "+f"(c3)
        : "r"(a0), "r"(a1), "r"(a2), "r"(a3), "r"(b0), "r"(b1));
}

__device__ __forceinline__ void cp16(float* s, const float* g) {
    unsigned sa = (unsigned)__cvta_generic_to_shared(s);
    asm volatile("cp.async.cg.shared.global [%0], [%1], 16;" :: "r"(sa), "l"(g));
}
__device__ __forceinline__ void cp_commit() {
    asm volatile("cp.async.commit_group;");
}

// ================= 3xTF32 tensor-core GEMM, cp.async double-buffered ============
// BM=128, BN=128, BK=32, 256 threads = 8 warps (2 M x 4 N), warp tile 64x32.
#define APAD 36
#define BPAD 136
#define ASZ (128 * APAD)
#define BSZ (32 * BPAD)
#define TG_SMEM ((2 * ASZ + 2 * BSZ) * 4)   // 71680 bytes

// EPI 0: plain store (bias/act/res), A rows identity.
// EPI 1: gelu -> C[off+m] store; A rows GATHERED via atok[off+m].
// EPI 2: atomic scatter to C[tok] with bias+gate; A rows LOCAL (bounded by cnt).
// EPI 3: plain atomicAdd (split-K accumulate), no bias/res; A rows identity.
template <int ACT, int EPI>
__device__ __forceinline__ void tgemm_body(
    const float* __restrict__ A, const float* __restrict__ B,
    const float* __restrict__ bias, const float* __restrict__ res,
    float* __restrict__ C, int M, int N, int K, int Kstride,
    int row0, int col0,
    const int* __restrict__ atok, const float* __restrict__ aw,
    int cnt, int off) {

    extern __shared__ float dsm[];
    float* As = dsm;                 // [2][ASZ]
    float* Bs = dsm + 2 * ASZ;       // [2][BSZ]

    int tid = threadIdx.x;
    int warp = tid >> 5, lane = tid & 31;
    int wm = warp >> 2, wn = warp & 3;
    int g = lane >> 2, t = lane & 3;

    int arow = tid >> 1, acb = (tid & 1) * 16;
    int brow = tid >> 3, bcb = (tid & 7) * 16;

    int asrc;
    if (EPI == 1) {
        int m = row0 + arow;
        asrc = (m < cnt) ? atok[off + m] : 0;
    } else if (EPI == 2) {
        int m = row0 + arow;
        asrc = (m < cnt) ? m : 0;
    } else {
        asrc = row0 + arow;
    }

    const float* Asrc = A + (size_t)asrc * Kstride + acb;
    const float* Bsrc = B + (size_t)brow * N + col0 + bcb;

    float c[4][4][4];
#pragma unroll
    for (int i = 0; i < 4; i++)
#pragma unroll
        for (int j = 0; j < 4; j++) { c[i][j][0] = c[i][j][1] = c[i][j][2] = c[i][j][3] = 0.f; }

    int NS = K / 32;
    {
        float* da = As + arow * APAD + acb;
        float* db = Bs + brow * BPAD + bcb;
#pragma unroll
        for (int i = 0; i < 4; i++) cp16(da + i * 4, Asrc + i * 4);
#pragma unroll
        for (int i = 0; i < 4; i++) cp16(db + i * 4, Bsrc + i * 4);
        cp_commit();
    }

    for (int s = 0; s < NS; s++) {
        if (s + 1 < NS) {
            int buf = (s + 1) & 1;
            int k0 = (s + 1) * 32;
            float* da = As + buf * ASZ + arow * APAD + acb;
            float* db = Bs + buf * BSZ + brow * BPAD + bcb;
#pragma unroll
            for (int i = 0; i < 4; i++) cp16(da + i * 4, Asrc + k0 + i * 4);
#pragma unroll
            for (int i = 0; i < 4; i++) cp16(db + i * 4, Bsrc + (size_t)k0 * N + i * 4);
            cp_commit();
            asm volatile("cp.async.wait_group 1;");
        } else {
            asm volatile("cp.async.wait_group 0;");
        }
        __syncthreads();

        const float* Ab = As + (s & 1) * ASZ;
        const float* Bb = Bs + (s & 1) * BSZ;
#pragma unroll
        for (int kk = 0; kk < 4; kk++) {
            int kb = kk * 8;
            unsigned ah[4][4], al[4][4], bh[4][2], bl[4][2];
#pragma unroll
            for (int mt = 0; mt < 4; mt++) {
                int mb = wm * 64 + mt * 16;
                int i0 = (mb + g) * APAD + kb + t;
                int i1 = (mb + g + 8) * APAD + kb + t;
                tf32_split(Ab[i0],     ah[mt][0], al[mt][0]);
                tf32_split(Ab[i1],     ah[mt][1], al[mt][1]);
                tf32_split(Ab[i0 + 4], ah[mt][2], al[mt][2]);
                tf32_split(Ab[i1 + 4], ah[mt][3], al[mt][3]);
            }
#pragma unroll
            for (int nt = 0; nt < 4; nt++) {
                int nb = wn * 32 + nt * 8;
                tf32_split(Bb[(kb + t) * BPAD + nb + g],     bh[nt][0], bl[nt][0]);
                tf32_split(Bb[(kb + t + 4) * BPAD + nb + g], bh[nt][1], bl[nt][1]);
            }
#pragma unroll
            for (int mt = 0; mt < 4; mt++)
#pragma unroll
                for (int nt = 0; nt < 4; nt++) {
                    mma_tf32(c[mt][nt][0], c[mt][nt][1], c[mt][nt][2], c[mt][nt][3],
                             al[mt][0], al[mt][1], al[mt][2], al[mt][3],
                             bh[nt][0], bh[nt][1]);
                    mma_tf32(c[mt][nt][0], c[mt][nt][1], c[mt][nt][2], c[mt][nt][3],
                             ah[mt][0], ah[mt][1], ah[mt][2], ah[mt][3],
                             bl[nt][0], bl[nt][1]);
                    mma_tf32(c[mt][nt][0], c[mt][nt][1], c[mt][nt][2], c[mt][nt][3],
                             ah[mt][0], ah[mt][1], ah[mt][2], ah[mt][3],
                             bh[nt][0], bh[nt][1]);
                }
        }
        __syncthreads();
    }

#pragma unroll
    for (int mt = 0; mt < 4; mt++) {
        int mb = row0 + wm * 64 + mt * 16;
#pragma unroll
        for (int nt = 0; nt < 4; nt++) {
            int nb = col0 + wn * 32 + nt * 8 + 2 * t;
#pragma unroll
            for (int half = 0; half < 2; half++) {
                int r = mb + g + half * 8;
                float v0 = c[mt][nt][half * 2 + 0];
                float v1 = c[mt][nt][half * 2 + 1];
                if (EPI == 0) {
                    if (bias) { v0 += bias[nb]; v1 += bias[nb + 1]; }
                    if (ACT == 1) { v0 = gelu_tanh(v0); v1 = gelu_tanh(v1); }
                    if (res) {
                        v0 += res[(size_t)r * N + nb];
                        v1 += res[(size_t)r * N + nb + 1];
                    }
                    C[(size_t)r * N + nb] = v0;
                    C[(size_t)r * N + nb + 1] = v1;
                } else if (EPI == 1) {
                    if (r < cnt) {
                        C[(size_t)(off + r) * N + nb] = gelu_tanh(v0 + bias[nb]);
                        C[(size_t)(off + r) * N + nb + 1] = gelu_tanh(v1 + bias[nb + 1]);
                    }
                } else if (EPI == 2) {
                    if (r < cnt) {
                        int tok = atok[off + r];
                        float wgt = aw[off + r];
                        atomicAdd(&C[(size_t)tok * N + nb], (v0 + bias[nb]) * wgt);
                        atomicAdd(&C[(size_t)tok * N + nb + 1], (v1 + bias[nb + 1]) * wgt);
                    }
                } else {
                    atomicAdd(&C[(size_t)r * N + nb], v0);
                    atomicAdd(&C[(size_t)r * N + nb + 1], v1);
                }
            }
        }
    }
}

template <int ACT>
__global__ __launch_bounds__(256) void tgemm(const float* __restrict__ A,
                                             const float* __restrict__ B,
                                             const float* __restrict__ bias,
                                             const float* __restrict__ res,
                                             float* __restrict__ C,
                                             int M, int N, int K) {
    tgemm_body<ACT, 0>(A, B, bias, res, C, M, N, K, K,
                       blockIdx.y * 128, blockIdx.x * 128, nullptr, nullptr, 0, 0);
}

__global__ __launch_bounds__(256) void qkv_tgemm(const float* __restrict__ A,
                                                 const float* __restrict__ wq,
                                                 const float* __restrict__ wk,
                                                 const float* __restrict__ wv,
                                                 const float* __restrict__ bq,
                                                 const float* __restrict__ bk,
                                                 const float* __restrict__ bv) {
    int z = blockIdx.z;
    const float* W = (z == 0) ? wq : (z == 1) ? wk : wv;
    const float* bias = (z == 0) ? bq : (z == 1) ? bk : bv;
    float* C = (z == 0) ? g_q : (z == 1) ? g_k : g_v;
    tgemm_body<0, 0>(A, W, bias, nullptr, C, TOK, EMB, EMB, EMB,
                     blockIdx.y * 128, blockIdx.x * 128, nullptr, nullptr, 0, 0);
}

__global__ __launch_bounds__(256) void routed_tgemm1(const float* __restrict__ W1all,
                                                     const float* __restrict__ b1all) {
    int e = blockIdx.z;
    int cnt = g_cnt[e];
    int m0 = blockIdx.y * 128;
    if (m0 >= cnt) return;
    tgemm_body<0, 1>(g_h2, W1all + (size_t)e * EMB * EHID, b1all + (size_t)e * EHID,
                     nullptr, g_H, TOK, EHID, EMB, EMB,
                     m0, blockIdx.x * 128, g_atok, nullptr, cnt, g_off[e]);
}

__global__ __launch_bounds__(256) void routed_tgemm2(const float* __restrict__ W2all,
                                                     const float* __restrict__ b2all,
                                                     float* __restrict__ out) {
    int e = blockIdx.z;
    int cnt = g_cnt[e];
    int m0 = blockIdx.y * 128;
    if (m0 >= cnt) return;
    int off = g_off[e];
    tgemm_body<0, 2>(g_H + (size_t)off * EHID, W2all + (size_t)e * EHID * EMB,
                     b2all + (size_t)e * EMB, nullptr, out, TOK, EMB, EHID, EHID,
                     m0, blockIdx.x * 128, g_atok, g_aw, cnt, off);
}

// shared-expert GEMM2 split-K
#define KSPLIT 4
#define KCH (SHID / KSPLIT)
__global__ __launch_bounds__(256) void shared2_splitk(const float* __restrict__ hs,
                                                      const float* __restrict__ w2,
                                                      float* __restrict__ out) {
    int kc = blockIdx.z;
    tgemm_body<0, 3>(hs + (size_t)kc * KCH, w2 + (size_t)kc * KCH * EMB,
                     nullptr, nullptr, out, TOK, EMB, KCH, SHID,
                     blockIdx.y * 128, blockIdx.x * 128, nullptr, nullptr, 0, 0);
}

// init out = x1 + se_b2
__global__ __launch_bounds__(256) void init_out_kernel(const float* __restrict__ x1,
                                                       const float* __restrict__ b2,
                                                       float* __restrict__ out) {
    int i = blockIdx.x * 256 + threadIdx.x;   // float4 index
    float4 v = reinterpret_cast<const float4*>(x1)[i];
    int col = (i * 4) & (EMB - 1);
    float4 b = *reinterpret_cast<const float4*>(b2 + col);
    v.x += b.x; v.y += b.y; v.z += b.z; v.w += b.w;
    reinterpret_cast<float4*>(out)[i] = v;
}

// ---------------- LayerNorm ----------------
__global__ __launch_bounds__(128) void ln_kernel(const float* __restrict__ X,
                                                 const float* __restrict__ g,
                                                 const float* __restrict__ b,
                                                 float* __restrict__ Y) {
    int t = blockIdx.x;
    int tid = threadIdx.x;
    const float4 v = *reinterpret_cast<const float4*>(X + (size_t)t * EMB + tid * 4);
    float s  = v.x + v.y + v.z + v.w;
    float sq = v.x * v.x + v.y * v.y + v.z * v.z + v.w * v.w;
    for (int o = 16; o > 0; o >>= 1) {
        s  += __shfl_xor_sync(0xffffffff, s, o);
        sq += __shfl_xor_sync(0xffffffff, sq, o);
    }
    __shared__ float ssum[4], ssq[4], stats[2];
    int w = tid >> 5;
    if ((tid & 31) == 0) { ssum[w] = s; ssq[w] = sq; }
    __syncthreads();
    if (tid == 0) {
        float S = ssum[0] + ssum[1] + ssum[2] + ssum[3];
        float Q = ssq[0] + ssq[1] + ssq[2] + ssq[3];
        float mu = S * (1.0f / EMB);
        float var = Q * (1.0f / EMB) - mu * mu;
        stats[0] = mu;
        stats[1] = rsqrtf(var + 1e-5f);
    }
    __syncthreads();
    float mu = stats[0], rs = stats[1];
    int cc = tid * 4;
    float4 gg = *reinterpret_cast<const float4*>(g + cc);
    float4 bb = *reinterpret_cast<const float4*>(b + cc);
    float4 o;
    o.x = (v.x - mu) * rs * gg.x + bb.x;
    o.y = (v.y - mu) * rs * gg.y + bb.y;
    o.z = (v.z - mu) * rs * gg.z + bb.z;
    o.w = (v.w - mu) * rs * gg.w + bb.w;
    *reinterpret_cast<float4*>(Y + (size_t)t * EMB + cc) = o;
}

// ---------------- fp32 SGEMM (router only, small N) ----------------
template <int ACT>
__global__ __launch_bounds__(256) void sgemm(const float* __restrict__ A,
                                             const float* __restrict__ B,
                                             const float* __restrict__ bias,
                                             const float* __restrict__ res,
                                             float* __restrict__ C,
                                             int M, int N, int K) {
    __shared__ float As[8][128];
    __shared__ float Bs[8][128];
    int tid = threadIdx.x;
    int row0 = blockIdx.y * 128, col0 = blockIdx.x * 128;
    int aRow = tid >> 1, aCol = (tid & 1) * 4;
    int bRow = tid >> 5, bCol = (tid & 31) * 4;
    int tr = (tid >> 4) * 8, tc = (tid & 15) * 8;

    float acc[8][8];
#pragma unroll
    for (int i = 0; i < 8; i++)
#pragma unroll
        for (int j = 0; j < 8; j++) acc[i][j] = 0.f;

    const float* Ap = A + (size_t)(row0 + aRow) * K + aCol;
    for (int k0 = 0; k0 < K; k0 += 8) {
        float4 av = *reinterpret_cast<const float4*>(Ap + k0);
        As[aCol + 0][aRow] = av.x;
        As[aCol + 1][aRow] = av.y;
        As[aCol + 2][aRow] = av.z;
        As[aCol + 3][aRow] = av.w;
        int gc = col0 + bCol;
        const float* Bp = B + (size_t)(k0 + bRow) * N + gc;
        float4 bv;
        if (gc + 3 < N) {
            bv = *reinterpret_cast<const float4*>(Bp);
        } else {
            bv.x = (gc + 0 < N) ? Bp[0] : 0.f;
            bv.y = (gc + 1 < N) ? Bp[1] : 0.f;
            bv.z = (gc + 2 < N) ? Bp[2] : 0.f;
            bv.w = (gc + 3 < N) ? Bp[3] : 0.f;
        }
        Bs[bRow][bCol + 0] = bv.x;
        Bs[bRow][bCol + 1] = bv.y;
        Bs[bRow][bCol + 2] = bv.z;
        Bs[bRow][bCol + 3] = bv.w;
        __syncthreads();
#pragma unroll
        for (int k = 0; k < 8; k++) {
            float4 ra0 = *reinterpret_cast<const float4*>(&As[k][tr]);
            float4 ra1 = *reinterpret_cast<const float4*>(&As[k][tr + 4]);
            float4 rb0 = *reinterpret_cast<const float4*>(&Bs[k][tc]);
            float4 rb1 = *reinterpret_cast<const float4*>(&Bs[k][tc + 4]);
            float ra[8] = {ra0.x, ra0.y, ra0.z, ra0.w, ra1.x, ra1.y, ra1.z, ra1.w};
            float rb[8] = {rb0.x, rb0.y, rb0.z, rb0.w, rb1.x, rb1.y, rb1.z, rb1.w};
#pragma unroll
            for (int i = 0; i < 8; i++)
#pragma unroll
                for (int j = 0; j < 8; j++) acc[i][j] += ra[i] * rb[j];
        }
        __syncthreads();
    }
#pragma unroll
    for (int i = 0; i < 8; i++) {
        int gr = row0 + tr + i;
#pragma unroll
        for (int j = 0; j < 8; j++) {
            int gc = col0 + tc + j;
            if (gc < N) {
                float v = acc[i][j];
                if (bias) v += bias[gc];
                if (ACT == 1) v = gelu_tanh(v);
                if (res) v += res[(size_t)gr * N + gc];
                C[(size_t)gr * N + gc] = v;
            }
        }
    }
}

// ---------------- flash attention v4: float4 P, Ps aliases Kt, 2 blocks/SM ----
// 256 thr, 4x4/thread. smem: Qt, Kt(=Ps), Vs, each 64x68 = 52.2 KB total.
// PV inner loop: 8 LDS.128 per 64 FMA (P loads broadcast in 16-lane groups).
#define ATP 68
#define AT_SMEM (3 * 64 * ATP * 4)   // 52224 bytes

__global__ __launch_bounds__(256) void attn_kernel() {
    const float* __restrict__ Q = g_q;
    const float* __restrict__ K = g_k;
    const float* __restrict__ V = g_v;
    float* __restrict__ O = g_attn;

    extern __shared__ float dsm[];
    float* Qt = dsm;                 // [d][qrow]
    float* Kt = Qt + 64 * ATP;       // [d][krow]; reused as Ps [qrow][krow]
    float* Vs = Kt + 64 * ATP;       // [krow][d]
    float* Ps = Kt;                  // alias (Kt fully consumed before P write)
    __shared__ float rowm[64], rowl[64];

    int bh = blockIdx.x;
    int qt = blockIdx.y;
    int b = bh >> 3, h = bh & 7;
    const size_t base = (size_t)b * SEQ * EMB + h * HD;
    int tid = threadIdx.x;
    int ti = (tid >> 4) * 4;         // q-row group of 4
    int tj = (tid & 15) * 4;         // k-col / d-col group of 4
    bool glead = ((tid & 15) == 0);

    for (int idx = tid; idx < 64 * 16; idx += 256) {
        int r = idx >> 4, c4 = (idx & 15) * 4;
        float4 qv = *reinterpret_cast<const float4*>(Q + base + (size_t)(qt * 64 + r) * EMB + c4);
        Qt[(c4 + 0) * ATP + r] = qv.x;
        Qt[(c4 + 1) * ATP + r] = qv.y;
        Qt[(c4 + 2) * ATP + r] = qv.z;
        Qt[(c4 + 3) * ATP + r] = qv.w;
    }
    if (tid < 64) { rowm[tid] = -1e30f; rowl[tid] = 0.f; }

    float o[4][4];
#pragma unroll
    for (int i = 0; i < 4; i++)
#pragma unroll
        for (int j = 0; j < 4; j++) o[i][j] = 0.f;
    __syncthreads();

    for (int kt = 0; kt < SEQ / 64; kt++) {
        for (int idx = tid; idx < 64 * 16; idx += 256) {
            int r = idx >> 4, c4 = (idx & 15) * 4;
            float4 kv = *reinterpret_cast<const float4*>(K + base + (size_t)(kt * 64 + r) * EMB + c4);
            Kt[(c4 + 0) * ATP + r] = kv.x;
            Kt[(c4 + 1) * ATP + r] = kv.y;
            Kt[(c4 + 2) * ATP + r] = kv.z;
            Kt[(c4 + 3) * ATP + r] = kv.w;
            float4 vv = *reinterpret_cast<const float4*>(V + base + (size_t)(kt * 64 + r) * EMB + c4);
            *reinterpret_cast<float4*>(&Vs[r * ATP + c4]) = vv;
        }
        __syncthreads();

        // S = Q @ K^T in registers
        float s[4][4];
#pragma unroll
        for (int i = 0; i < 4; i++)
#pragma unroll
            for (int j = 0; j < 4; j++) s[i][j] = 0.f;
        for (int d = 0; d < 64; d++) {
            float4 qa = *reinterpret_cast<const float4*>(&Qt[d * ATP + ti]);
            float4 kb = *reinterpret_cast<const float4*>(&Kt[d * ATP + tj]);
            float a[4] = {qa.x, qa.y, qa.z, qa.w};
            float bb[4] = {kb.x, kb.y, kb.z, kb.w};
#pragma unroll
            for (int i = 0; i < 4; i++)
#pragma unroll
                for (int j = 0; j < 4; j++) s[i][j] += a[i] * bb[j];
        }
        __syncthreads();   // all Kt reads done -> safe to overwrite with P

        // register softmax per row (16-lane groups), P stored float4 row-major
        float fi[4];
#pragma unroll
        for (int i = 0; i < 4; i++) {
            int r = ti + i;
            float mloc = fmaxf(fmaxf(s[i][0], s[i][1]), fmaxf(s[i][2], s[i][3])) * 0.125f;
#pragma unroll
            for (int off = 8; off > 0; off >>= 1)
                mloc = fmaxf(mloc, __shfl_xor_sync(0xffffffff, mloc, off));
            float mo = rowm[r];
            float mx = fmaxf(mloc, mo);
            float4 p;
            p.x = __expf(s[i][0] * 0.125f - mx);
            p.y = __expf(s[i][1] * 0.125f - mx);
            p.z = __expf(s[i][2] * 0.125f - mx);
            p.w = __expf(s[i][3] * 0.125f - mx);
            float sm = p.x + p.y + p.z + p.w;
#pragma unroll
            for (int off = 8; off > 0; off >>= 1)
                sm += __shfl_xor_sync(0xffffffff, sm, off);
            *reinterpret_cast<float4*>(&Ps[r * ATP + tj]) = p;
            float f = __expf(mo - mx);
            fi[i] = f;
            if (glead) {
                rowl[r] = rowl[r] * f + sm;
                rowm[r] = mx;
            }
        }
        __syncthreads();

        // O rescale + O += P @ V (4 k-steps per float4 P load)
#pragma unroll
        for (int i = 0; i < 4; i++)
#pragma unroll
            for (int j = 0; j < 4; j++) o[i][j] *= fi[i];
        for (int t4 = 0; t4 < 64; t4 += 4) {
            float4 p4[4];
#pragma unroll
            for (int i = 0; i < 4; i++)
                p4[i] = *reinterpret_cast<const float4*>(&Ps[(ti + i) * ATP + t4]);
#pragma unroll
            for (int j4 = 0; j4 < 4; j4++) {
                float4 vb = *reinterpret_cast<const float4*>(&Vs[(t4 + j4) * ATP + tj]);
                float pj[4] = {j4 == 0 ? p4[0].x : j4 == 1 ? p4[0].y : j4 == 2 ? p4[0].z : p4[0].w,
                               j4 == 0 ? p4[1].x : j4 == 1 ? p4[1].y : j4 == 2 ? p4[1].z : p4[1].w,
                               j4 == 0 ? p4[2].x : j4 == 1 ? p4[2].y : j4 == 2 ? p4[2].z : p4[2].w,
                               j4 == 0 ? p4[3].x : j4 == 1 ? p4[3].y : j4 == 2 ? p4[3].z : p4[3].w};
#pragma unroll
                for (int i = 0; i < 4; i++) {
                    o[i][0] += pj[i] * vb.x;
                    o[i][1] += pj[i] * vb.y;
                    o[i][2] += pj[i] * vb.z;
                    o[i][3] += pj[i] * vb.w;
                }
            }
        }
        __syncthreads();   // P reads done before next tile overwrites Kt/Ps
    }
#pragma unroll
    for (int i = 0; i < 4; i++) {
        float inv = 1.0f / rowl[ti + i];
#pragma unroll
        for (int j = 0; j < 4; j++)
            O[base + (size_t)(qt * 64 + ti + i) * EMB + tj + j] = o[i][j] * inv;
    }
}

// ---------------- router: softmax + top-4 + stats ----------------
__global__ __launch_bounds__(128) void router_topk_kernel() {
    const float* __restrict__ logits = g_logits;
    __shared__ float s_imp[NEXP];
    __shared__ int s_cnt[NEXP];
    int tid = threadIdx.x;
    if (tid < NEXP) { s_imp[tid] = 0.f; s_cnt[tid] = 0; }
    __syncthreads();
    int t = blockIdx.x * 128 + tid;
    float p[NEXP];
    float mx = -1e30f;
#pragma unroll
    for (int e = 0; e < NEXP; e++) {
        p[e] = logits[(size_t)t * NEXP + e];
        mx = fmaxf(mx, p[e]);
    }
    float sum = 0.f;
#pragma unroll
    for (int e = 0; e < NEXP; e++) { p[e] = __expf(p[e] - mx); sum += p[e]; }
    float inv = 1.f / sum;
#pragma unroll
    for (int e = 0; e < NEXP; e++) {
        p[e] *= inv;
        atomicAdd(&s_imp[e], p[e]);
    }
    int idx[TOPK];
    float w[TOPK];
    float tot = 0.f;
#pragma unroll
    for (int k = 0; k < TOPK; k++) {
        float best = -1.f;
        int bi = 0;
#pragma unroll
        for (int e = 0; e < NEXP; e++)
            if (p[e] > best) { best = p[e]; bi = e; }
        idx[k] = bi;
        w[k] = best;
        tot += best;
        p[bi] = -1.f;
        atomicAdd(&s_cnt[bi], 1);
    }
    float it = 1.f / tot;
#pragma unroll
    for (int k = 0; k < TOPK; k++) {
        g_topi[t * TOPK + k] = idx[k];
        g_topw[t * TOPK + k] = w[k] * it;
    }
    __syncthreads();
    if (tid < NEXP) {
        atomicAdd(&g_imp[tid], s_imp[tid]);
        atomicAdd(&g_cnt[tid], s_cnt[tid]);
    }
}

// ---------------- prefix scan + aux loss ----------------
__global__ void scan_aux_kernel(float* __restrict__ out, int out_size) {
    if (threadIdx.x == 0) {
        int acc = 0;
        float aux = 0.f;
        for (int e = 0; e < NEXP; e++) {
            g_off[e] = acc;
            acc += g_cnt[e];
            aux += g_imp[e] * (float)g_cnt[e];
        }
        aux *= (float)NEXP / ((float)TOK * (float)TOK);
        if (out_size > TOK * EMB) out[TOK * EMB] = aux;
    }
}

// ---------------- fill per-expert assignment lists ----------------
__global__ __launch_bounds__(128) void fill_assign_kernel() {
    int t = blockIdx.x * 128 + threadIdx.x;
#pragma unroll
    for (int k = 0; k < TOPK; k++) {
        int e = g_topi[t * TOPK + k];
        int pos = atomicAdd(&g_cur[e], 1);
        int gidx = g_off[e] + pos;
        g_atok[gidx] = t;
        g_aw[gidx] = g_topw[t * TOPK + k];
    }
}

__global__ void zero_small_kernel() {
    int i = threadIdx.x;
    if (i < NEXP) { g_imp[i] = 0.f; g_cnt[i] = 0; g_cur[i] = 0; }
}

// ---------------- launch ----------------
extern "C" void kernel_launch(void* const* d_in, const int* in_sizes, int n_in,
                              void* d_out, int out_size) {
    const float* x        = (const float*)d_in[0];
    const float* ln1_g    = (const float*)d_in[1];
    const float* ln1_b    = (const float*)d_in[2];
    const float* wq       = (const float*)d_in[3];
    const float* bq       = (const float*)d_in[4];
    const float* wk       = (const float*)d_in[5];
    const float* bk       = (const float*)d_in[6];
    const float* wv       = (const float*)d_in[7];
    const float* bv       = (const float*)d_in[8];
    const float* wo       = (const float*)d_in[9];
    const float* bo       = (const float*)d_in[10];
    const float* ln2_g    = (const float*)d_in[11];
    const float* ln2_b    = (const float*)d_in[12];
    const float* router_a = (const float*)d_in[13];
    const float* router_b = (const float*)d_in[14];
    const float* re_w1    = (const float*)d_in[15];
    const float* re_b1    = (const float*)d_in[16];
    const float* re_w2    = (const float*)d_in[17];
    const float* re_b2    = (const float*)d_in[18];
    const float* se_w1    = (const float*)d_in[19];
    const float* se_b1    = (const float*)d_in[20];
    const float* se_w2    = (const float*)d_in[21];
    const float* se_b2    = (const float*)d_in[22];
    float* out = (float*)d_out;

    float *p_h1, *p_attn, *p_x1, *p_h2, *p_rlat, *p_logits, *p_hs;
    cudaGetSymbolAddress((void**)&p_h1, g_h1);
    cudaGetSymbolAddress((void**)&p_attn, g_attn);
    cudaGetSymbolAddress((void**)&p_x1, g_x1);
    cudaGetSymbolAddress((void**)&p_h2, g_h2);
    cudaGetSymbolAddress((void**)&p_rlat, g_rlat);
    cudaGetSymbolAddress((void**)&p_logits, g_logits);
    cudaGetSymbolAddress((void**)&p_hs, g_hs);

    cudaFuncSetAttribute(tgemm<0>, cudaFuncAttributeMaxDynamicSharedMemorySize, TG_SMEM);
    cudaFuncSetAttribute(tgemm<1>, cudaFuncAttributeMaxDynamicSharedMemorySize, TG_SMEM);
    cudaFuncSetAttribute(qkv_tgemm, cudaFuncAttributeMaxDynamicSharedMemorySize, TG_SMEM);
    cudaFuncSetAttribute(routed_tgemm1, cudaFuncAttributeMaxDynamicSharedMemorySize, TG_SMEM);
    cudaFuncSetAttribute(routed_tgemm2, cudaFuncAttributeMaxDynamicSharedMemorySize, TG_SMEM);
    cudaFuncSetAttribute(shared2_splitk, cudaFuncAttributeMaxDynamicSharedMemorySize, TG_SMEM);
    cudaFuncSetAttribute(attn_kernel, cudaFuncAttributeMaxDynamicSharedMemorySize, AT_SMEM);

    zero_small_kernel<<<1, 32>>>();
    ln_kernel<<<TOK, 128>>>(x, ln1_g, ln1_b, p_h1);

    qkv_tgemm<<<dim3(4, 32, 3), 256, TG_SMEM>>>(p_h1, wq, wk, wv, bq, bk, bv);

    attn_kernel<<<dim3(32, 16), 256, AT_SMEM>>>();

    dim3 g512(4, 32);
    tgemm<0><<<g512, 256, TG_SMEM>>>(p_attn, wo, bo, x, p_x1, TOK, EMB, EMB);
    ln_kernel<<<TOK, 128>>>(p_x1, ln2_g, ln2_b, p_h2);

    sgemm<0><<<dim3(1, 32), 256>>>(p_h2, router_a, nullptr, nullptr, p_rlat, TOK, RRANK, EMB);
    sgemm<0><<<dim3(1, 32), 256>>>(p_rlat, router_b, nullptr, nullptr, p_logits, TOK, NEXP, RRANK);
    router_topk_kernel<<<TOK / 128, 128>>>();
    scan_aux_kernel<<<1, 32>>>(out, out_size);
    fill_assign_kernel<<<TOK / 128, 128>>>();

    routed_tgemm1<<<dim3(4, 32, 32), 256, TG_SMEM>>>(re_w1, re_b1);

    tgemm<1><<<dim3(32, 32), 256, TG_SMEM>>>(p_h2, se_w1, se_b1, nullptr, p_hs, TOK, SHID, EMB);

    init_out_kernel<<<(TOK * EMB / 4) / 256, 256>>>(p_x1, se_b2, out);
    shared2_splitk<<<dim3(4, 32, KSPLIT), 256, TG_SMEM>>>(p_hs, se_w2, out);
    routed_tgemm2<<<dim3(4, 32, 32), 256, TG_SMEM>>>(re_w2, re_b2, out);
}

// round 12
// speedup vs baseline: 1.2069x; 1.0933x over previous
#include <cuda_runtime.h>
#include <math.h>

// ---------------- problem constants ----------------
#define TOK   4096          // B*S = 4*1024
#define SEQ   1024
#define BATCH 4
#define EMB   512
#define NH    8
#define HD    64
#define NEXP  32
#define TOPK  4
#define RRANK 64
#define SHID  4096
#define EHID  512

// ---------------- device scratch (static, allocation-free) ----------------
__device__ float g_h1[TOK * EMB];
__device__ float g_q[TOK * EMB];
__device__ float g_k[TOK * EMB];
__device__ float g_v[TOK * EMB];
__device__ float g_attn[TOK * EMB];
__device__ float g_x1[TOK * EMB];
__device__ float g_h2[TOK * EMB];
__device__ float g_rlat[TOK * RRANK];
__device__ float g_logits[TOK * NEXP];
__device__ int   g_topi[TOK * TOPK];
__device__ float g_topw[TOK * TOPK];
__device__ float g_imp[NEXP];
__device__ int   g_cnt[NEXP];
__device__ int   g_off[NEXP];
__device__ int   g_cur[NEXP];
__device__ int   g_atok[TOK * TOPK];
__device__ float g_aw[TOK * TOPK];
__device__ float g_H[TOK * TOPK * EHID];   // routed hidden
__device__ float g_hs[TOK * SHID];         // shared-expert hidden

// ---------------- helpers ----------------
__device__ __forceinline__ float gelu_tanh(float x) {
    float x3 = x * x * x;
    return 0.5f * x * (1.0f + tanhf(0.7978845608028654f * (x + 0.044715f * x3)));
}

__device__ __forceinline__ unsigned f2tf32(float f) {
    unsigned r;
    asm("cvt.rna.tf32.f32 %0, %1;" : "=r"(r) : "f"(f));
    return r;
}

__device__ __forceinline__ void tf32_split(float f, unsigned& hi, unsigned& lo) {
    hi = f2tf32(f);
    lo = f2tf32(f - __uint_as_float(hi));
}

__device__ __forceinline__ void mma_tf32(float& c0, float& c1, float& c2, float& c3,
                                         unsigned a0, unsigned a1, unsigned a2, unsigned a3,
                                         unsigned b0, unsigned b1) {
    asm volatile(
        "mma.sync.aligned.m16n8k8.row.col.f32.tf32.tf32.f32 "
        "{%0,%1,%2,%3}, {%4,%5,%6,%7}, {%8,%9}, {%0,%1,%2,%3};"
        : "+f"(c0), "+f"(c1), "+f"(c2), "+f"(c3)
        : "r"(a0), "r"(a1), "r"(a2), "r"(a3), "r"(b0), "r"(b1));
}

__device__ __forceinline__ void cp16(float* s, const float* g) {
    unsigned sa = (unsigned)__cvta_generic_to_shared(s);
    asm volatile("cp.async.cg.shared.global [%0], [%1], 16;" :: "r"(sa), "l"(g));
}
__device__ __forceinline__ void cp_commit() {
    asm volatile("cp.async.commit_group;");
}

// ================= 3xTF32 tensor-core GEMM, cp.async double-buffered ============
// BM=128, BN=128, BK=32, 256 threads = 8 warps (2 M x 4 N), warp tile 64x32.
#define APAD 36
#define BPAD 136
#define ASZ (128 * APAD)
#define BSZ (32 * BPAD)
#define TG_SMEM ((2 * ASZ + 2 * BSZ) * 4)   // 71680 bytes

// EPI 0: plain store (bias/act/res), A rows identity.
// EPI 1: gelu -> C[off+m] store; A rows GATHERED via atok[off+m].
// EPI 2: atomic scatter to C[tok] with bias+gate; A rows LOCAL (bounded by cnt).
// EPI 3: plain atomicAdd (split-K accumulate), no bias/res; A rows identity.
template <int ACT, int EPI>
__device__ __forceinline__ void tgemm_body(
    const float* __restrict__ A, const float* __restrict__ B,
    const float* __restrict__ bias, const float* __restrict__ res,
    float* __restrict__ C, int M, int N, int K, int Kstride,
    int row0, int col0,
    const int* __restrict__ atok, const float* __restrict__ aw,
    int cnt, int off) {

    extern __shared__ float dsm[];
    float* As = dsm;                 // [2][ASZ]
    float* Bs = dsm + 2 * ASZ;       // [2][BSZ]

    int tid = threadIdx.x;
    int warp = tid >> 5, lane = tid & 31;
    int wm = warp >> 2, wn = warp & 3;
    int g = lane >> 2, t = lane & 3;

    int arow = tid >> 1, acb = (tid & 1) * 16;
    int brow = tid >> 3, bcb = (tid & 7) * 16;

    int asrc;
    if (EPI == 1) {
        int m = row0 + arow;
        asrc = (m < cnt) ? atok[off + m] : 0;
    } else if (EPI == 2) {
        int m = row0 + arow;
        asrc = (m < cnt) ? m : 0;
    } else {
        asrc = row0 + arow;
    }

    const float* Asrc = A + (size_t)asrc * Kstride + acb;
    const float* Bsrc = B + (size_t)brow * N + col0 + bcb;

    float c[4][4][4];
#pragma unroll
    for (int i = 0; i < 4; i++)
#pragma unroll
        for (int j = 0; j < 4; j++) { c[i][j][0] = c[i][j][1] = c[i][j][2] = c[i][j][3] = 0.f; }

    int NS = K / 32;
    {
        float* da = As + arow * APAD + acb;
        float* db = Bs + brow * BPAD + bcb;
#pragma unroll
        for (int i = 0; i < 4; i++) cp16(da + i * 4, Asrc + i * 4);
#pragma unroll
        for (int i = 0; i < 4; i++) cp16(db + i * 4, Bsrc + i * 4);
        cp_commit();
    }

    for (int s = 0; s < NS; s++) {
        if (s + 1 < NS) {
            int buf = (s + 1) & 1;
            int k0 = (s + 1) * 32;
            float* da = As + buf * ASZ + arow * APAD + acb;
            float* db = Bs + buf * BSZ + brow * BPAD + bcb;
#pragma unroll
            for (int i = 0; i < 4; i++) cp16(da + i * 4, Asrc + k0 + i * 4);
#pragma unroll
            for (int i = 0; i < 4; i++) cp16(db + i * 4, Bsrc + (size_t)k0 * N + i * 4);
            cp_commit();
            asm volatile("cp.async.wait_group 1;");
        } else {
            asm volatile("cp.async.wait_group 0;");
        }
        __syncthreads();

        const float* Ab = As + (s & 1) * ASZ;
        const float* Bb = Bs + (s & 1) * BSZ;
#pragma unroll
        for (int kk = 0; kk < 4; kk++) {
            int kb = kk * 8;
            unsigned ah[4][4], al[4][4], bh[4][2], bl[4][2];
#pragma unroll
            for (int mt = 0; mt < 4; mt++) {
                int mb = wm * 64 + mt * 16;
                int i0 = (mb + g) * APAD + kb + t;
                int i1 = (mb + g + 8) * APAD + kb + t;
                tf32_split(Ab[i0],     ah[mt][0], al[mt][0]);
                tf32_split(Ab[i1],     ah[mt][1], al[mt][1]);
                tf32_split(Ab[i0 + 4], ah[mt][2], al[mt][2]);
                tf32_split(Ab[i1 + 4], ah[mt][3], al[mt][3]);
            }
#pragma unroll
            for (int nt = 0; nt < 4; nt++) {
                int nb = wn * 32 + nt * 8;
                tf32_split(Bb[(kb + t) * BPAD + nb + g],     bh[nt][0], bl[nt][0]);
                tf32_split(Bb[(kb + t + 4) * BPAD + nb + g], bh[nt][1], bl[nt][1]);
            }
#pragma unroll
            for (int mt = 0; mt < 4; mt++)
#pragma unroll
                for (int nt = 0; nt < 4; nt++) {
                    mma_tf32(c[mt][nt][0], c[mt][nt][1], c[mt][nt][2], c[mt][nt][3],
                             al[mt][0], al[mt][1], al[mt][2], al[mt][3],
                             bh[nt][0], bh[nt][1]);
                    mma_tf32(c[mt][nt][0], c[mt][nt][1], c[mt][nt][2], c[mt][nt][3],
                             ah[mt][0], ah[mt][1], ah[mt][2], ah[mt][3],
                             bl[nt][0], bl[nt][1]);
                    mma_tf32(c[mt][nt][0], c[mt][nt][1], c[mt][nt][2], c[mt][nt][3],
                             ah[mt][0], ah[mt][1], ah[mt][2], ah[mt][3],
                             bh[nt][0], bh[nt][1]);
                }
        }
        __syncthreads();
    }

#pragma unroll
    for (int mt = 0; mt < 4; mt++) {
        int mb = row0 + wm * 64 + mt * 16;
#pragma unroll
        for (int nt = 0; nt < 4; nt++) {
            int nb = col0 + wn * 32 + nt * 8 + 2 * t;
#pragma unroll
            for (int half = 0; half < 2; half++) {
                int r = mb + g + half * 8;
                float v0 = c[mt][nt][half * 2 + 0];
                float v1 = c[mt][nt][half * 2 + 1];
                if (EPI == 0) {
                    if (bias) { v0 += bias[nb]; v1 += bias[nb + 1]; }
                    if (ACT == 1) { v0 = gelu_tanh(v0); v1 = gelu_tanh(v1); }
                    if (res) {
                        v0 += res[(size_t)r * N + nb];
                        v1 += res[(size_t)r * N + nb + 1];
                    }
                    C[(size_t)r * N + nb] = v0;
                    C[(size_t)r * N + nb + 1] = v1;
                } else if (EPI == 1) {
                    if (r < cnt) {
                        C[(size_t)(off + r) * N + nb] = gelu_tanh(v0 + bias[nb]);
                        C[(size_t)(off + r) * N + nb + 1] = gelu_tanh(v1 + bias[nb + 1]);
                    }
                } else if (EPI == 2) {
                    if (r < cnt) {
                        int tok = atok[off + r];
                        float wgt = aw[off + r];
                        atomicAdd(&C[(size_t)tok * N + nb], (v0 + bias[nb]) * wgt);
                        atomicAdd(&C[(size_t)tok * N + nb + 1], (v1 + bias[nb + 1]) * wgt);
                    }
                } else {
                    atomicAdd(&C[(size_t)r * N + nb], v0);
                    atomicAdd(&C[(size_t)r * N + nb + 1], v1);
                }
            }
        }
    }
}

template <int ACT>
__global__ __launch_bounds__(256, 2) void tgemm(const float* __restrict__ A,
                                                const float* __restrict__ B,
                                                const float* __restrict__ bias,
                                                const float* __restrict__ res,
                                                float* __restrict__ C,
                                                int M, int N, int K) {
    tgemm_body<ACT, 0>(A, B, bias, res, C, M, N, K, K,
                       blockIdx.y * 128, blockIdx.x * 128, nullptr, nullptr, 0, 0);
}

__global__ __launch_bounds__(256, 2) void qkv_tgemm(const float* __restrict__ A,
                                                    const float* __restrict__ wq,
                                                    const float* __restrict__ wk,
                                                    const float* __restrict__ wv,
                                                    const float* __restrict__ bq,
                                                    const float* __restrict__ bk,
                                                    const float* __restrict__ bv) {
    int z = blockIdx.z;
    const float* W = (z == 0) ? wq : (z == 1) ? wk : wv;
    const float* bias = (z == 0) ? bq : (z == 1) ? bk : bv;
    float* C = (z == 0) ? g_q : (z == 1) ? g_k : g_v;
    tgemm_body<0, 0>(A, W, bias, nullptr, C, TOK, EMB, EMB, EMB,
                     blockIdx.y * 128, blockIdx.x * 128, nullptr, nullptr, 0, 0);
}

__global__ __launch_bounds__(256, 2) void routed_tgemm1(const float* __restrict__ W1all,
                                                        const float* __restrict__ b1all) {
    int e = blockIdx.z;
    int cnt = g_cnt[e];
    int m0 = blockIdx.y * 128;
    if (m0 >= cnt) return;
    tgemm_body<0, 1>(g_h2, W1all + (size_t)e * EMB * EHID, b1all + (size_t)e * EHID,
                     nullptr, g_H, TOK, EHID, EMB, EMB,
                     m0, blockIdx.x * 128, g_atok, nullptr, cnt, g_off[e]);
}

__global__ __launch_bounds__(256, 2) void routed_tgemm2(const float* __restrict__ W2all,
                                                        const float* __restrict__ b2all,
                                                        float* __restrict__ out) {
    int e = blockIdx.z;
    int cnt = g_cnt[e];
    int m0 = blockIdx.y * 128;
    if (m0 >= cnt) return;
    int off = g_off[e];
    tgemm_body<0, 2>(g_H + (size_t)off * EHID, W2all + (size_t)e * EHID * EMB,
                     b2all + (size_t)e * EMB, nullptr, out, TOK, EMB, EHID, EHID,
                     m0, blockIdx.x * 128, g_atok, g_aw, cnt, off);
}

// shared-expert GEMM2 split-K
#define KSPLIT 4
#define KCH (SHID / KSPLIT)
__global__ __launch_bounds__(256, 2) void shared2_splitk(const float* __restrict__ hs,
                                                         const float* __restrict__ w2,
                                                         float* __restrict__ out) {
    int kc = blockIdx.z;
    tgemm_body<0, 3>(hs + (size_t)kc * KCH, w2 + (size_t)kc * KCH * EMB,
                     nullptr, nullptr, out, TOK, EMB, KCH, SHID,
                     blockIdx.y * 128, blockIdx.x * 128, nullptr, nullptr, 0, 0);
}

// init out = x1 + se_b2
__global__ __launch_bounds__(256) void init_out_kernel(const float* __restrict__ x1,
                                                       const float* __restrict__ b2,
                                                       float* __restrict__ out) {
    int i = blockIdx.x * 256 + threadIdx.x;   // float4 index
    float4 v = reinterpret_cast<const float4*>(x1)[i];
    int col = (i * 4) & (EMB - 1);
    float4 b = *reinterpret_cast<const float4*>(b2 + col);
    v.x += b.x; v.y += b.y; v.z += b.z; v.w += b.w;
    reinterpret_cast<float4*>(out)[i] = v;
}

// ---------------- LayerNorm ----------------
__global__ __launch_bounds__(128) void ln_kernel(const float* __restrict__ X,
                                                 const float* __restrict__ g,
                                                 const float* __restrict__ b,
                                                 float* __restrict__ Y) {
    int t = blockIdx.x;
    int tid = threadIdx.x;
    const float4 v = *reinterpret_cast<const float4*>(X + (size_t)t * EMB + tid * 4);
    float s  = v.x + v.y + v.z + v.w;
    float sq = v.x * v.x + v.y * v.y + v.z * v.z + v.w * v.w;
    for (int o = 16; o > 0; o >>= 1) {
        s  += __shfl_xor_sync(0xffffffff, s, o);
        sq += __shfl_xor_sync(0xffffffff, sq, o);
    }
    __shared__ float ssum[4], ssq[4], stats[2];
    int w = tid >> 5;
    if ((tid & 31) == 0) { ssum[w] = s; ssq[w] = sq; }
    __syncthreads();
    if (tid == 0) {
        float S = ssum[0] + ssum[1] + ssum[2] + ssum[3];
        float Q = ssq[0] + ssq[1] + ssq[2] + ssq[3];
        float mu = S * (1.0f / EMB);
        float var = Q * (1.0f / EMB) - mu * mu;
        stats[0] = mu;
        stats[1] = rsqrtf(var + 1e-5f);
    }
    __syncthreads();
    float mu = stats[0], rs = stats[1];
    int cc = tid * 4;
    float4 gg = *reinterpret_cast<const float4*>(g + cc);
    float4 bb = *reinterpret_cast<const float4*>(b + cc);
    float4 o;
    o.x = (v.x - mu) * rs * gg.x + bb.x;
    o.y = (v.y - mu) * rs * gg.y + bb.y;
    o.z = (v.z - mu) * rs * gg.z + bb.z;
    o.w = (v.w - mu) * rs * gg.w + bb.w;
    *reinterpret_cast<float4*>(Y + (size_t)t * EMB + cc) = o;
}

// ---------------- fp32 SGEMM (router only, small N) ----------------
template <int ACT>
__global__ __launch_bounds__(256) void sgemm(const float* __restrict__ A,
                                             const float* __restrict__ B,
                                             const float* __restrict__ bias,
                                             const float* __restrict__ res,
                                             float* __restrict__ C,
                                             int M, int N, int K) {
    __shared__ float As[8][128];
    __shared__ float Bs[8][128];
    int tid = threadIdx.x;
    int row0 = blockIdx.y * 128, col0 = blockIdx.x * 128;
    int aRow = tid >> 1, aCol = (tid & 1) * 4;
    int bRow = tid >> 5, bCol = (tid & 31) * 4;
    int tr = (tid >> 4) * 8, tc = (tid & 15) * 8;

    float acc[8][8];
#pragma unroll
    for (int i = 0; i < 8; i++)
#pragma unroll
        for (int j = 0; j < 8; j++) acc[i][j] = 0.f;

    const float* Ap = A + (size_t)(row0 + aRow) * K + aCol;
    for (int k0 = 0; k0 < K; k0 += 8) {
        float4 av = *reinterpret_cast<const float4*>(Ap + k0);
        As[aCol + 0][aRow] = av.x;
        As[aCol + 1][aRow] = av.y;
        As[aCol + 2][aRow] = av.z;
        As[aCol + 3][aRow] = av.w;
        int gc = col0 + bCol;
        const float* Bp = B + (size_t)(k0 + bRow) * N + gc;
        float4 bv;
        if (gc + 3 < N) {
            bv = *reinterpret_cast<const float4*>(Bp);
        } else {
            bv.x = (gc + 0 < N) ? Bp[0] : 0.f;
            bv.y = (gc + 1 < N) ? Bp[1] : 0.f;
            bv.z = (gc + 2 < N) ? Bp[2] : 0.f;
            bv.w = (gc + 3 < N) ? Bp[3] : 0.f;
        }
        Bs[bRow][bCol + 0] = bv.x;
        Bs[bRow][bCol + 1] = bv.y;
        Bs[bRow][bCol + 2] = bv.z;
        Bs[bRow][bCol + 3] = bv.w;
        __syncthreads();
#pragma unroll
        for (int k = 0; k < 8; k++) {
            float4 ra0 = *reinterpret_cast<const float4*>(&As[k][tr]);
            float4 ra1 = *reinterpret_cast<const float4*>(&As[k][tr + 4]);
            float4 rb0 = *reinterpret_cast<const float4*>(&Bs[k][tc]);
            float4 rb1 = *reinterpret_cast<const float4*>(&Bs[k][tc + 4]);
            float ra[8] = {ra0.x, ra0.y, ra0.z, ra0.w, ra1.x, ra1.y, ra1.z, ra1.w};
            float rb[8] = {rb0.x, rb0.y, rb0.z, rb0.w, rb1.x, rb1.y, rb1.z, rb1.w};
#pragma unroll
            for (int i = 0; i < 8; i++)
#pragma unroll
                for (int j = 0; j < 8; j++) acc[i][j] += ra[i] * rb[j];
        }
        __syncthreads();
    }
#pragma unroll
    for (int i = 0; i < 8; i++) {
        int gr = row0 + tr + i;
#pragma unroll
        for (int j = 0; j < 8; j++) {
            int gc = col0 + tc + j;
            if (gc < N) {
                float v = acc[i][j];
                if (bias) v += bias[gc];
                if (ACT == 1) v = gelu_tanh(v);
                if (res) v += res[(size_t)gr * N + gc];
                C[(size_t)gr * N + gc] = v;
            }
        }
    }
}

// ---------------- flash attention v5: 128-q tile, 8x4/thread, 1.5 B/FMA ----------
// 256 thr; q-tile 128, k-tile 64. Qt [d][128] pitch 132; Kt [d][64] pitch 68
// (aliased by Ps [128 q][64 k] pitch 68 after QK); Vs [64 k][d] pitch 68.
// smem 86 KB -> 2 blocks/SM; grid 32x8 = 256 blocks = one wave.
#define QTP 132
#define ATP 68
#define QT_FLOATS (64 * QTP)           // 8448
#define PS_FLOATS (128 * ATP)          // 8704
#define VS_FLOATS (64 * ATP)           // 4352
#define AT_SMEM ((QT_FLOATS + PS_FLOATS + VS_FLOATS) * 4)   // 86016

__global__ __launch_bounds__(256, 2) void attn_kernel() {
    const float* __restrict__ Q = g_q;
    const float* __restrict__ K = g_k;
    const float* __restrict__ V = g_v;
    float* __restrict__ O = g_attn;

    extern __shared__ float dsm[];
    float* Qt = dsm;                       // [d][qrow] pitch QTP
    float* Kt = dsm + QT_FLOATS;           // [d][krow] pitch ATP (first half of Ps)
    float* Ps = Kt;                        // [qrow][krow] pitch ATP (aliases Kt+pad)
    float* Vs = dsm + QT_FLOATS + PS_FLOATS;  // [krow][d] pitch ATP

    __shared__ float rowm[128], rowl[128];

    int bh = blockIdx.x;
    int qt = blockIdx.y;                   // 0..7 (128-row q tiles)
    int b = bh >> 3, h = bh & 7;
    const size_t base = (size_t)b * SEQ * EMB + h * HD;
    int tid = threadIdx.x;
    int ti = (tid >> 4) * 8;               // q-row group of 8
    int tj = (tid & 15) * 4;               // k-col / d-col group of 4
    bool glead = ((tid & 15) == 0);

    // load Q tile (128 rows) transposed
    for (int idx = tid; idx < 128 * 16; idx += 256) {
        int r = idx >> 4, c4 = (idx & 15) * 4;
        float4 qv = *reinterpret_cast<const float4*>(Q + base + (size_t)(qt * 128 + r) * EMB + c4);
        Qt[(c4 + 0) * QTP + r] = qv.x;
        Qt[(c4 + 1) * QTP + r] = qv.y;
        Qt[(c4 + 2) * QTP + r] = qv.z;
        Qt[(c4 + 3) * QTP + r] = qv.w;
    }
    if (tid < 128) { rowm[tid] = -1e30f; rowl[tid] = 0.f; }

    float o[8][4];
#pragma unroll
    for (int i = 0; i < 8; i++)
#pragma unroll
        for (int j = 0; j < 4; j++) o[i][j] = 0.f;
    __syncthreads();

    for (int kt = 0; kt < SEQ / 64; kt++) {
        // load K transposed + V row-major (64 rows)
        for (int idx = tid; idx < 64 * 16; idx += 256) {
            int r = idx >> 4, c4 = (idx & 15) * 4;
            float4 kv = *reinterpret_cast<const float4*>(K + base + (size_t)(kt * 64 + r) * EMB + c4);
            Kt[(c4 + 0) * ATP + r] = kv.x;
            Kt[(c4 + 1) * ATP + r] = kv.y;
            Kt[(c4 + 2) * ATP + r] = kv.z;
            Kt[(c4 + 3) * ATP + r] = kv.w;
            float4 vv = *reinterpret_cast<const float4*>(V + base + (size_t)(kt * 64 + r) * EMB + c4);
            *reinterpret_cast<float4*>(&Vs[r * ATP + c4]) = vv;
        }
        __syncthreads();

        // S = Q @ K^T in registers: 8 q x 4 k per thread
        float s[8][4];
#pragma unroll
        for (int i = 0; i < 8; i++)
#pragma unroll
            for (int j = 0; j < 4; j++) s[i][j] = 0.f;
        for (int d = 0; d < 64; d++) {
            float4 qa0 = *reinterpret_cast<const float4*>(&Qt[d * QTP + ti]);
            float4 qa1 = *reinterpret_cast<const float4*>(&Qt[d * QTP + ti + 4]);
            float4 kb = *reinterpret_cast<const float4*>(&Kt[d * ATP + tj]);
            float a[8] = {qa0.x, qa0.y, qa0.z, qa0.w, qa1.x, qa1.y, qa1.z, qa1.w};
            float bb[4] = {kb.x, kb.y, kb.z, kb.w};
#pragma unroll
            for (int i = 0; i < 8; i++)
#pragma unroll
                for (int j = 0; j < 4; j++) s[i][j] += a[i] * bb[j];
        }
        __syncthreads();   // Kt reads done -> safe to overwrite with P

        // register softmax per row (16-lane groups), P stored float4 row-major
        float fi[8];
#pragma unroll
        for (int i = 0; i < 8; i++) {
            int r = ti + i;
            float mloc = fmaxf(fmaxf(s[i][0], s[i][1]), fmaxf(s[i][2], s[i][3])) * 0.125f;
#pragma unroll
            for (int off = 8; off > 0; off >>= 1)
                mloc = fmaxf(mloc, __shfl_xor_sync(0xffffffff, mloc, off));
            float mo = rowm[r];
            float mx = fmaxf(mloc, mo);
            float4 p;
            p.x = __expf(s[i][0] * 0.125f - mx);
            p.y = __expf(s[i][1] * 0.125f - mx);
            p.z = __expf(s[i][2] * 0.125f - mx);
            p.w = __expf(s[i][3] * 0.125f - mx);
            float sm = p.x + p.y + p.z + p.w;
#pragma unroll
            for (int off = 8; off > 0; off >>= 1)
                sm += __shfl_xor_sync(0xffffffff, sm, off);
            *reinterpret_cast<float4*>(&Ps[r * ATP + tj]) = p;
            float f = __expf(mo - mx);
            fi[i] = f;
            if (glead) {
                rowl[r] = rowl[r] * f + sm;
                rowm[r] = mx;
            }
        }
        __syncthreads();

        // O rescale + O += P @ V
#pragma unroll
        for (int i = 0; i < 8; i++)
#pragma unroll
            for (int j = 0; j < 4; j++) o[i][j] *= fi[i];
        for (int t4 = 0; t4 < 64; t4 += 4) {
            float4 p4[8];
#pragma unroll
            for (int i = 0; i < 8; i++)
                p4[i] = *reinterpret_cast<const float4*>(&Ps[(ti + i) * ATP + t4]);
#pragma unroll
            for (int j4 = 0; j4 < 4; j4++) {
                float4 vb = *reinterpret_cast<const float4*>(&Vs[(t4 + j4) * ATP + tj]);
#pragma unroll
                for (int i = 0; i < 8; i++) {
                    float pj = j4 == 0 ? p4[i].x : j4 == 1 ? p4[i].y : j4 == 2 ? p4[i].z : p4[i].w;
                    o[i][0] += pj * vb.x;
                    o[i][1] += pj * vb.y;
                    o[i][2] += pj * vb.z;
                    o[i][3] += pj * vb.w;
                }
            }
        }
        __syncthreads();   // P reads done before next tile overwrites Kt/Ps
    }
#pragma unroll
    for (int i = 0; i < 8; i++) {
        float inv = 1.0f / rowl[ti + i];
#pragma unroll
        for (int j = 0; j < 4; j++)
            O[base + (size_t)(qt * 128 + ti + i) * EMB + tj + j] = o[i][j] * inv;
    }
}

// ---------------- router: softmax + top-4 + stats ----------------
__global__ __launch_bounds__(128) void router_topk_kernel() {
    const float* __restrict__ logits = g_logits;
    __shared__ float s_imp[NEXP];
    __shared__ int s_cnt[NEXP];
    int tid = threadIdx.x;
    if (tid < NEXP) { s_imp[tid] = 0.f; s_cnt[tid] = 0; }
    __syncthreads();
    int t = blockIdx.x * 128 + tid;
    float p[NEXP];
    float mx = -1e30f;
#pragma unroll
    for (int e = 0; e < NEXP; e++) {
        p[e] = logits[(size_t)t * NEXP + e];
        mx = fmaxf(mx, p[e]);
    }
    float sum = 0.f;
#pragma unroll
    for (int e = 0; e < NEXP; e++) { p[e] = __expf(p[e] - mx); sum += p[e]; }
    float inv = 1.f / sum;
#pragma unroll
    for (int e = 0; e < NEXP; e++) {
        p[e] *= inv;
        atomicAdd(&s_imp[e], p[e]);
    }
    int idx[TOPK];
    float w[TOPK];
    float tot = 0.f;
#pragma unroll
    for (int k = 0; k < TOPK; k++) {
        float best = -1.f;
        int bi = 0;
#pragma unroll
        for (int e = 0; e < NEXP; e++)
            if (p[e] > best) { best = p[e]; bi = e; }
        idx[k] = bi;
        w[k] = best;
        tot += best;
        p[bi] = -1.f;
        atomicAdd(&s_cnt[bi], 1);
    }
    float it = 1.f / tot;
#pragma unroll
    for (int k = 0; k < TOPK; k++) {
        g_topi[t * TOPK + k] = idx[k];
        g_topw[t * TOPK + k] = w[k] * it;
    }
    __syncthreads();
    if (tid < NEXP) {
        atomicAdd(&g_imp[tid], s_imp[tid]);
        atomicAdd(&g_cnt[tid], s_cnt[tid]);
    }
}

// ---------------- prefix scan + aux loss ----------------
__global__ void scan_aux_kernel(float* __restrict__ out, int out_size) {
    if (threadIdx.x == 0) {
        int acc = 0;
        float aux = 0.f;
        for (int e = 0; e < NEXP; e++) {
            g_off[e] = acc;
            acc += g_cnt[e];
            aux += g_imp[e] * (float)g_cnt[e];
        }
        aux *= (float)NEXP / ((float)TOK * (float)TOK);
        if (out_size > TOK * EMB) out[TOK * EMB] = aux;
    }
}

// ---------------- fill per-expert assignment lists ----------------
__global__ __launch_bounds__(128) void fill_assign_kernel() {
    int t = blockIdx.x * 128 + threadIdx.x;
#pragma unroll
    for (int k = 0; k < TOPK; k++) {
        int e = g_topi[t * TOPK + k];
        int pos = atomicAdd(&g_cur[e], 1);
        int gidx = g_off[e] + pos;
        g_atok[gidx] = t;
        g_aw[gidx] = g_topw[t * TOPK + k];
    }
}

__global__ void zero_small_kernel() {
    int i = threadIdx.x;
    if (i < NEXP) { g_imp[i] = 0.f; g_cnt[i] = 0; g_cur[i] = 0; }
}

// ---------------- launch ----------------
extern "C" void kernel_launch(void* const* d_in, const int* in_sizes, int n_in,
                              void* d_out, int out_size) {
    const float* x        = (const float*)d_in[0];
    const float* ln1_g    = (const float*)d_in[1];
    const float* ln1_b    = (const float*)d_in[2];
    const float* wq       = (const float*)d_in[3];
    const float* bq       = (const float*)d_in[4];
    const float* wk       = (const float*)d_in[5];
    const float* bk       = (const float*)d_in[6];
    const float* wv       = (const float*)d_in[7];
    const float* bv       = (const float*)d_in[8];
    const float* wo       = (const float*)d_in[9];
    const float* bo       = (const float*)d_in[10];
    const float* ln2_g    = (const float*)d_in[11];
    const float* ln2_b    = (const float*)d_in[12];
    const float* router_a = (const float*)d_in[13];
    const float* router_b = (const float*)d_in[14];
    const float* re_w1    = (const float*)d_in[15];
    const float* re_b1    = (const float*)d_in[16];
    const float* re_w2    = (const float*)d_in[17];
    const float* re_b2    = (const float*)d_in[18];
    const float* se_w1    = (const float*)d_in[19];
    const float* se_b1    = (const float*)d_in[20];
    const float* se_w2    = (const float*)d_in[21];
    const float* se_b2    = (const float*)d_in[22];
    float* out = (float*)d_out;

    float *p_h1, *p_attn, *p_x1, *p_h2, *p_rlat, *p_logits, *p_hs;
    cudaGetSymbolAddress((void**)&p_h1, g_h1);
    cudaGetSymbolAddress((void**)&p_attn, g_attn);
    cudaGetSymbolAddress((void**)&p_x1, g_x1);
    cudaGetSymbolAddress((void**)&p_h2, g_h2);
    cudaGetSymbolAddress((void**)&p_rlat, g_rlat);
    cudaGetSymbolAddress((void**)&p_logits, g_logits);
    cudaGetSymbolAddress((void**)&p_hs, g_hs);

    cudaFuncSetAttribute(tgemm<0>, cudaFuncAttributeMaxDynamicSharedMemorySize, TG_SMEM);
    cudaFuncSetAttribute(tgemm<1>, cudaFuncAttributeMaxDynamicSharedMemorySize, TG_SMEM);
    cudaFuncSetAttribute(qkv_tgemm, cudaFuncAttributeMaxDynamicSharedMemorySize, TG_SMEM);
    cudaFuncSetAttribute(routed_tgemm1, cudaFuncAttributeMaxDynamicSharedMemorySize, TG_SMEM);
    cudaFuncSetAttribute(routed_tgemm2, cudaFuncAttributeMaxDynamicSharedMemorySize, TG_SMEM);
    cudaFuncSetAttribute(shared2_splitk, cudaFuncAttributeMaxDynamicSharedMemorySize, TG_SMEM);
    cudaFuncSetAttribute(attn_kernel, cudaFuncAttributeMaxDynamicSharedMemorySize, AT_SMEM);

    zero_small_kernel<<<1, 32>>>();
    ln_kernel<<<TOK, 128>>>(x, ln1_g, ln1_b, p_h1);

    qkv_tgemm<<<dim3(4, 32, 3), 256, TG_SMEM>>>(p_h1, wq, wk, wv, bq, bk, bv);

    attn_kernel<<<dim3(32, 8), 256, AT_SMEM>>>();

    dim3 g512(4, 32);
    tgemm<0><<<g512, 256, TG_SMEM>>>(p_attn, wo, bo, x, p_x1, TOK, EMB, EMB);
    ln_kernel<<<TOK, 128>>>(p_x1, ln2_g, ln2_b, p_h2);

    sgemm<0><<<dim3(1, 32), 256>>>(p_h2, router_a, nullptr, nullptr, p_rlat, TOK, RRANK, EMB);
    sgemm<0><<<dim3(1, 32), 256>>>(p_rlat, router_b, nullptr, nullptr, p_logits, TOK, NEXP, RRANK);
    router_topk_kernel<<<TOK / 128, 128>>>();
    scan_aux_kernel<<<1, 32>>>(out, out_size);
    fill_assign_kernel<<<TOK / 128, 128>>>();

    routed_tgemm1<<<dim3(4, 32, 32), 256, TG_SMEM>>>(re_w1, re_b1);

    tgemm<1><<<dim3(32, 32), 256, TG_SMEM>>>(p_h2, se_w1, se_b1, nullptr, p_hs, TOK, SHID, EMB);

    init_out_kernel<<<(TOK * EMB / 4) / 256, 256>>>(p_x1, se_b2, out);
    shared2_splitk<<<dim3(4, 32, KSPLIT), 256, TG_SMEM>>>(p_hs, se_w2, out);
    routed_tgemm2<<<dim3(4, 32, 32), 256, TG_SMEM>>>(re_w2, re_b2, out);
}

// round 13
// speedup vs baseline: 1.2503x; 1.0359x over previous
#include <cuda_runtime.h>
#include <math.h>

// ---------------- problem constants ----------------
#define TOK   4096          // B*S = 4*1024
#define SEQ   1024
#define BATCH 4
#define EMB   512
#define NH    8
#define HD    64
#define NEXP  32
#define TOPK  4
#define RRANK 64
#define SHID  4096
#define EHID  512

// ---------------- device scratch (static, allocation-free) ----------------
__device__ float g_h1[TOK * EMB];
__device__ float g_q[TOK * EMB];
__device__ float g_k[TOK * EMB];
__device__ float g_v[TOK * EMB];
__device__ float g_attn[TOK * EMB];
__device__ float g_x1[TOK * EMB];
__device__ float g_h2[TOK * EMB];
__device__ float g_rlat[TOK * RRANK];
__device__ float g_logits[TOK * NEXP];
__device__ int   g_topi[TOK * TOPK];
__device__ float g_topw[TOK * TOPK];
__device__ float g_imp[NEXP];
__device__ int   g_cnt[NEXP];
__device__ int   g_off[NEXP];
__device__ int   g_cur[NEXP];
__device__ int   g_atok[TOK * TOPK];
__device__ float g_aw[TOK * TOPK];
__device__ float g_H[TOK * TOPK * EHID];   // routed hidden
__device__ float g_hs[TOK * SHID];         // shared-expert hidden

// ---------------- helpers ----------------
__device__ __forceinline__ float gelu_tanh(float x) {
    float x3 = x * x * x;
    return 0.5f * x * (1.0f + tanhf(0.7978845608028654f * (x + 0.044715f * x3)));
}

__device__ __forceinline__ unsigned f2tf32(float f) {
    unsigned r;
    asm("cvt.rna.tf32.f32 %0, %1;" : "=r"(r) : "f"(f));
    return r;
}

// hi = rna-rounded tf32; lo = raw residual (tf32 HW reads only upper bits, so
// the un-rounded difference is a valid lo operand; saves one cvt per element).
__device__ __forceinline__ void tf32_split(float f, unsigned& hi, unsigned& lo) {
    hi = f2tf32(f);
    lo = __float_as_uint(f - __uint_as_float(hi));
}

__device__ __forceinline__ void mma_tf32(float& c0, float& c1, float& c2, float& c3,
                                         unsigned a0, unsigned a1, unsigned a2, unsigned a3,
                                         unsigned b0, unsigned b1) {
    asm volatile(
        "mma.sync.aligned.m16n8k8.row.col.f32.tf32.tf32.f32 "
        "{%0,%1,%2,%3}, {%4,%5,%6,%7}, {%8,%9}, {%0,%1,%2,%3};"
        : "+f"(c0), "+f"(c1), "+f"(c2), "+f"(c3)
        : "r"(a0), "r"(a1), "r"(a2), "r"(a3), "r"(b0), "r"(b1));
}

__device__ __forceinline__ void cp16(float* s, const float* g) {
    unsigned sa = (unsigned)__cvta_generic_to_shared(s);
    asm volatile("cp.async.cg.shared.global [%0], [%1], 16;" :: "r"(sa), "l"(g));
}
__device__ __forceinline__ void cp_commit() {
    asm volatile("cp.async.commit_group;");
}

// ================= 3xTF32 tensor-core GEMM, cp.async double-buffered ============
// BM=128, BN=128, BK=32, 256 threads = 8 warps (2 M x 4 N), warp tile 64x32.
#define APAD 36
#define BPAD 136
#define ASZ (128 * APAD)
#define BSZ (32 * BPAD)
#define TG_SMEM ((2 * ASZ + 2 * BSZ) * 4)   // 71680 bytes

// EPI 0: plain store (bias/act/res), A rows identity.
// EPI 1: gelu -> C[off+m] store; A rows GATHERED via atok[off+m].
// EPI 2: atomic scatter to C[tok] with bias+gate; A rows LOCAL (bounded by cnt).
// EPI 3: plain atomicAdd (split-K accumulate), no bias/res; A rows identity.
template <int ACT, int EPI>
__device__ __forceinline__ void tgemm_body(
    const float* __restrict__ A, const float* __restrict__ B,
    const float* __restrict__ bias, const float* __restrict__ res,
    float* __restrict__ C, int M, int N, int K, int Kstride,
    int row0, int col0,
    const int* __restrict__ atok, const float* __restrict__ aw,
    int cnt, int off) {

    extern __shared__ float dsm[];
    float* As = dsm;                 // [2][ASZ]
    float* Bs = dsm + 2 * ASZ;       // [2][BSZ]

    int tid = threadIdx.x;
    int warp = tid >> 5, lane = tid & 31;
    int wm = warp >> 2, wn = warp & 3;
    int g = lane >> 2, t = lane & 3;

    int arow = tid >> 1, acb = (tid & 1) * 16;
    int brow = tid >> 3, bcb = (tid & 7) * 16;

    int asrc;
    if (EPI == 1) {
        int m = row0 + arow;
        asrc = (m < cnt) ? atok[off + m] : 0;
    } else if (EPI == 2) {
        int m = row0 + arow;
        asrc = (m < cnt) ? m : 0;
    } else {
        asrc = row0 + arow;
    }

    const float* Asrc = A + (size_t)asrc * Kstride + acb;
    const float* Bsrc = B + (size_t)brow * N + col0 + bcb;

    float c[4][4][4];
#pragma unroll
    for (int i = 0; i < 4; i++)
#pragma unroll
        for (int j = 0; j < 4; j++) { c[i][j][0] = c[i][j][1] = c[i][j][2] = c[i][j][3] = 0.f; }

    int NS = K / 32;
    {
        float* da = As + arow * APAD + acb;
        float* db = Bs + brow * BPAD + bcb;
#pragma unroll
        for (int i = 0; i < 4; i++) cp16(da + i * 4, Asrc + i * 4);
#pragma unroll
        for (int i = 0; i < 4; i++) cp16(db + i * 4, Bsrc + i * 4);
        cp_commit();
    }

    for (int s = 0; s < NS; s++) {
        if (s + 1 < NS) {
            int buf = (s + 1) & 1;
            int k0 = (s + 1) * 32;
            float* da = As + buf * ASZ + arow * APAD + acb;
            float* db = Bs + buf * BSZ + brow * BPAD + bcb;
#pragma unroll
            for (int i = 0; i < 4; i++) cp16(da + i * 4, Asrc + k0 + i * 4);
#pragma unroll
            for (int i = 0; i < 4; i++) cp16(db + i * 4, Bsrc + (size_t)k0 * N + i * 4);
            cp_commit();
            asm volatile("cp.async.wait_group 1;");
        } else {
            asm volatile("cp.async.wait_group 0;");
        }
        __syncthreads();

        const float* Ab = As + (s & 1) * ASZ;
        const float* Bb = Bs + (s & 1) * BSZ;
#pragma unroll
        for (int kk = 0; kk < 4; kk++) {
            int kb = kk * 8;
            unsigned ah[4][4], al[4][4], bh[4][2], bl[4][2];
#pragma unroll
            for (int mt = 0; mt < 4; mt++) {
                int mb = wm * 64 + mt * 16;
                int i0 = (mb + g) * APAD + kb + t;
                int i1 = (mb + g + 8) * APAD + kb + t;
                tf32_split(Ab[i0],     ah[mt][0], al[mt][0]);
                tf32_split(Ab[i1],     ah[mt][1], al[mt][1]);
                tf32_split(Ab[i0 + 4], ah[mt][2], al[mt][2]);
                tf32_split(Ab[i1 + 4], ah[mt][3], al[mt][3]);
            }
#pragma unroll
            for (int nt = 0; nt < 4; nt++) {
                int nb = wn * 32 + nt * 8;
                tf32_split(Bb[(kb + t) * BPAD + nb + g],     bh[nt][0], bl[nt][0]);
                tf32_split(Bb[(kb + t + 4) * BPAD + nb + g], bh[nt][1], bl[nt][1]);
            }
#pragma unroll
            for (int mt = 0; mt < 4; mt++)
#pragma unroll
                for (int nt = 0; nt < 4; nt++) {
                    mma_tf32(c[mt][nt][0], c[mt][nt][1], c[mt][nt][2], c[mt][nt][3],
                             al[mt][0], al[mt][1], al[mt][2], al[mt][3],
                             bh[nt][0], bh[nt][1]);
                    mma_tf32(c[mt][nt][0], c[mt][nt][1], c[mt][nt][2], c[mt][nt][3],
                             ah[mt][0], ah[mt][1], ah[mt][2], ah[mt][3],
                             bl[nt][0], bl[nt][1]);
                    mma_tf32(c[mt][nt][0], c[mt][nt][1], c[mt][nt][2], c[mt][nt][3],
                             ah[mt][0], ah[mt][1], ah[mt][2], ah[mt][3],
                             bh[nt][0], bh[nt][1]);
                }
        }
        __syncthreads();
    }

#pragma unroll
    for (int mt = 0; mt < 4; mt++) {
        int mb = row0 + wm * 64 + mt * 16;
#pragma unroll
        for (int nt = 0; nt < 4; nt++) {
            int nb = col0 + wn * 32 + nt * 8 + 2 * t;
#pragma unroll
            for (int half = 0; half < 2; half++) {
                int r = mb + g + half * 8;
                float v0 = c[mt][nt][half * 2 + 0];
                float v1 = c[mt][nt][half * 2 + 1];
                if (EPI == 0) {
                    if (bias) { v0 += bias[nb]; v1 += bias[nb + 1]; }
                    if (ACT == 1) { v0 = gelu_tanh(v0); v1 = gelu_tanh(v1); }
                    if (res) {
                        v0 += res[(size_t)r * N + nb];
                        v1 += res[(size_t)r * N + nb + 1];
                    }
                    C[(size_t)r * N + nb] = v0;
                    C[(size_t)r * N + nb + 1] = v1;
                } else if (EPI == 1) {
                    if (r < cnt) {
                        C[(size_t)(off + r) * N + nb] = gelu_tanh(v0 + bias[nb]);
                        C[(size_t)(off + r) * N + nb + 1] = gelu_tanh(v1 + bias[nb + 1]);
                    }
                } else if (EPI == 2) {
                    if (r < cnt) {
                        int tok = atok[off + r];
                        float wgt = aw[off + r];
                        atomicAdd(&C[(size_t)tok * N + nb], (v0 + bias[nb]) * wgt);
                        atomicAdd(&C[(size_t)tok * N + nb + 1], (v1 + bias[nb + 1]) * wgt);
                    }
                } else {
                    atomicAdd(&C[(size_t)r * N + nb], v0);
                    atomicAdd(&C[(size_t)r * N + nb + 1], v1);
                }
            }
        }
    }
}

template <int ACT>
__global__ __launch_bounds__(256, 2) void tgemm(const float* __restrict__ A,
                                                const float* __restrict__ B,
                                                const float* __restrict__ bias,
                                                const float* __restrict__ res,
                                                float* __restrict__ C,
                                                int M, int N, int K) {
    tgemm_body<ACT, 0>(A, B, bias, res, C, M, N, K, K,
                       blockIdx.y * 128, blockIdx.x * 128, nullptr, nullptr, 0, 0);
}

__global__ __launch_bounds__(256, 2) void qkv_tgemm(const float* __restrict__ A,
                                                    const float* __restrict__ wq,
                                                    const float* __restrict__ wk,
                                                    const float* __restrict__ wv,
                                                    const float* __restrict__ bq,
                                                    const float* __restrict__ bk,
                                                    const float* __restrict__ bv) {
    int z = blockIdx.z;
    const float* W = (z == 0) ? wq : (z == 1) ? wk : wv;
    const float* bias = (z == 0) ? bq : (z == 1) ? bk : bv;
    float* C = (z == 0) ? g_q : (z == 1) ? g_k : g_v;
    tgemm_body<0, 0>(A, W, bias, nullptr, C, TOK, EMB, EMB, EMB,
                     blockIdx.y * 128, blockIdx.x * 128, nullptr, nullptr, 0, 0);
}

__global__ __launch_bounds__(256, 2) void routed_tgemm1(const float* __restrict__ W1all,
                                                        const float* __restrict__ b1all) {
    int e = blockIdx.z;
    int cnt = g_cnt[e];
    int m0 = blockIdx.y * 128;
    if (m0 >= cnt) return;
    tgemm_body<0, 1>(g_h2, W1all + (size_t)e * EMB * EHID, b1all + (size_t)e * EHID,
                     nullptr, g_H, TOK, EHID, EMB, EMB,
                     m0, blockIdx.x * 128, g_atok, nullptr, cnt, g_off[e]);
}

__global__ __launch_bounds__(256, 2) void routed_tgemm2(const float* __restrict__ W2all,
                                                        const float* __restrict__ b2all,
                                                        float* __restrict__ out) {
    int e = blockIdx.z;
    int cnt = g_cnt[e];
    int m0 = blockIdx.y * 128;
    if (m0 >= cnt) return;
    int off = g_off[e];
    tgemm_body<0, 2>(g_H + (size_t)off * EHID, W2all + (size_t)e * EHID * EMB,
                     b2all + (size_t)e * EMB, nullptr, out, TOK, EMB, EHID, EHID,
                     m0, blockIdx.x * 128, g_atok, g_aw, cnt, off);
}

// shared-expert GEMM2 split-K
#define KSPLIT 4
#define KCH (SHID / KSPLIT)
__global__ __launch_bounds__(256, 2) void shared2_splitk(const float* __restrict__ hs,
                                                         const float* __restrict__ w2,
                                                         float* __restrict__ out) {
    int kc = blockIdx.z;
    tgemm_body<0, 3>(hs + (size_t)kc * KCH, w2 + (size_t)kc * KCH * EMB,
                     nullptr, nullptr, out, TOK, EMB, KCH, SHID,
                     blockIdx.y * 128, blockIdx.x * 128, nullptr, nullptr, 0, 0);
}

// O-projection split-K: x1 += attn[:, kc*256:...] @ wo[kc*256:...]
#define WOSPLIT 2
#define WOCH (EMB / WOSPLIT)
__global__ __launch_bounds__(256, 2) void wo_splitk(const float* __restrict__ attn,
                                                    const float* __restrict__ wo,
                                                    float* __restrict__ x1) {
    int kc = blockIdx.z;
    tgemm_body<0, 3>(attn + (size_t)kc * WOCH, wo + (size_t)kc * WOCH * EMB,
                     nullptr, nullptr, x1, TOK, EMB, WOCH, EMB,
                     blockIdx.y * 128, blockIdx.x * 128, nullptr, nullptr, 0, 0);
}

// init dst = src + bias (row-broadcast)
__global__ __launch_bounds__(256) void init_add_bias(const float* __restrict__ src,
                                                     const float* __restrict__ bias,
                                                     float* __restrict__ dst) {
    int i = blockIdx.x * 256 + threadIdx.x;   // float4 index
    float4 v = reinterpret_cast<const float4*>(src)[i];
    int col = (i * 4) & (EMB - 1);
    float4 b = *reinterpret_cast<const float4*>(bias + col);
    v.x += b.x; v.y += b.y; v.z += b.z; v.w += b.w;
    reinterpret_cast<float4*>(dst)[i] = v;
}

// ---------------- LayerNorm ----------------
__global__ __launch_bounds__(128) void ln_kernel(const float* __restrict__ X,
                                                 const float* __restrict__ g,
                                                 const float* __restrict__ b,
                                                 float* __restrict__ Y) {
    int t = blockIdx.x;
    int tid = threadIdx.x;
    const float4 v = *reinterpret_cast<const float4*>(X + (size_t)t * EMB + tid * 4);
    float s  = v.x + v.y + v.z + v.w;
    float sq = v.x * v.x + v.y * v.y + v.z * v.z + v.w * v.w;
    for (int o = 16; o > 0; o >>= 1) {
        s  += __shfl_xor_sync(0xffffffff, s, o);
        sq += __shfl_xor_sync(0xffffffff, sq, o);
    }
    __shared__ float ssum[4], ssq[4], stats[2];
    int w = tid >> 5;
    if ((tid & 31) == 0) { ssum[w] = s; ssq[w] = sq; }
    __syncthreads();
    if (tid == 0) {
        float S = ssum[0] + ssum[1] + ssum[2] + ssum[3];
        float Q = ssq[0] + ssq[1] + ssq[2] + ssq[3];
        float mu = S * (1.0f / EMB);
        float var = Q * (1.0f / EMB) - mu * mu;
        stats[0] = mu;
        stats[1] = rsqrtf(var + 1e-5f);
    }
    __syncthreads();
    float mu = stats[0], rs = stats[1];
    int cc = tid * 4;
    float4 gg = *reinterpret_cast<const float4*>(g + cc);
    float4 bb = *reinterpret_cast<const float4*>(b + cc);
    float4 o;
    o.x = (v.x - mu) * rs * gg.x + bb.x;
    o.y = (v.y - mu) * rs * gg.y + bb.y;
    o.z = (v.z - mu) * rs * gg.z + bb.z;
    o.w = (v.w - mu) * rs * gg.w + bb.w;
    *reinterpret_cast<float4*>(Y + (size_t)t * EMB + cc) = o;
}

// ---------------- fp32 SGEMM (router only, small N) ----------------
template <int ACT>
__global__ __launch_bounds__(256) void sgemm(const float* __restrict__ A,
                                             const float* __restrict__ B,
                                             const float* __restrict__ bias,
                                             const float* __restrict__ res,
                                             float* __restrict__ C,
                                             int M, int N, int K) {
    __shared__ float As[8][128];
    __shared__ float Bs[8][128];
    int tid = threadIdx.x;
    int row0 = blockIdx.y * 128, col0 = blockIdx.x * 128;
    int aRow = tid >> 1, aCol = (tid & 1) * 4;
    int bRow = tid >> 5, bCol = (tid & 31) * 4;
    int tr = (tid >> 4) * 8, tc = (tid & 15) * 8;

    float acc[8][8];
#pragma unroll
    for (int i = 0; i < 8; i++)
#pragma unroll
        for (int j = 0; j < 8; j++) acc[i][j] = 0.f;

    const float* Ap = A + (size_t)(row0 + aRow) * K + aCol;
    for (int k0 = 0; k0 < K; k0 += 8) {
        float4 av = *reinterpret_cast<const float4*>(Ap + k0);
        As[aCol + 0][aRow] = av.x;
        As[aCol + 1][aRow] = av.y;
        As[aCol + 2][aRow] = av.z;
        As[aCol + 3][aRow] = av.w;
        int gc = col0 + bCol;
        const float* Bp = B + (size_t)(k0 + bRow) * N + gc;
        float4 bv;
        if (gc + 3 < N) {
            bv = *reinterpret_cast<const float4*>(Bp);
        } else {
            bv.x = (gc + 0 < N) ? Bp[0] : 0.f;
            bv.y = (gc + 1 < N) ? Bp[1] : 0.f;
            bv.z = (gc + 2 < N) ? Bp[2] : 0.f;
            bv.w = (gc + 3 < N) ? Bp[3] : 0.f;
        }
        Bs[bRow][bCol + 0] = bv.x;
        Bs[bRow][bCol + 1] = bv.y;
        Bs[bRow][bCol + 2] = bv.z;
        Bs[bRow][bCol + 3] = bv.w;
        __syncthreads();
#pragma unroll
        for (int k = 0; k < 8; k++) {
            float4 ra0 = *reinterpret_cast<const float4*>(&As[k][tr]);
            float4 ra1 = *reinterpret_cast<const float4*>(&As[k][tr + 4]);
            float4 rb0 = *reinterpret_cast<const float4*>(&Bs[k][tc]);
            float4 rb1 = *reinterpret_cast<const float4*>(&Bs[k][tc + 4]);
            float ra[8] = {ra0.x, ra0.y, ra0.z, ra0.w, ra1.x, ra1.y, ra1.z, ra1.w};
            float rb[8] = {rb0.x, rb0.y, rb0.z, rb0.w, rb1.x, rb1.y, rb1.z, rb1.w};
#pragma unroll
            for (int i = 0; i < 8; i++)
#pragma unroll
                for (int j = 0; j < 8; j++) acc[i][j] += ra[i] * rb[j];
        }
        __syncthreads();
    }
#pragma unroll
    for (int i = 0; i < 8; i++) {
        int gr = row0 + tr + i;
#pragma unroll
        for (int j = 0; j < 8; j++) {
            int gc = col0 + tc + j;
            if (gc < N) {
                float v = acc[i][j];
                if (bias) v += bias[gc];
                if (ACT == 1) v = gelu_tanh(v);
                if (res) v += res[(size_t)gr * N + gc];
                C[(size_t)gr * N + gc] = v;
            }
        }
    }
}

// ---------------- flash attention v5: 128-q tile, 8x4/thread ----------
#define QTP 132
#define ATP 68
#define QT_FLOATS (64 * QTP)
#define PS_FLOATS (128 * ATP)
#define VS_FLOATS (64 * ATP)
#define AT_SMEM ((QT_FLOATS + PS_FLOATS + VS_FLOATS) * 4)   // 86016

__global__ __launch_bounds__(256, 2) void attn_kernel() {
    const float* __restrict__ Q = g_q;
    const float* __restrict__ K = g_k;
    const float* __restrict__ V = g_v;
    float* __restrict__ O = g_attn;

    extern __shared__ float dsm[];
    float* Qt = dsm;
    float* Kt = dsm + QT_FLOATS;
    float* Ps = Kt;
    float* Vs = dsm + QT_FLOATS + PS_FLOATS;

    __shared__ float rowm[128], rowl[128];

    int bh = blockIdx.x;
    int qt = blockIdx.y;
    int b = bh >> 3, h = bh & 7;
    const size_t base = (size_t)b * SEQ * EMB + h * HD;
    int tid = threadIdx.x;
    int ti = (tid >> 4) * 8;
    int tj = (tid & 15) * 4;
    bool glead = ((tid & 15) == 0);

    for (int idx = tid; idx < 128 * 16; idx += 256) {
        int r = idx >> 4, c4 = (idx & 15) * 4;
        float4 qv = *reinterpret_cast<const float4*>(Q + base + (size_t)(qt * 128 + r) * EMB + c4);
        Qt[(c4 + 0) * QTP + r] = qv.x;
        Qt[(c4 + 1) * QTP + r] = qv.y;
        Qt[(c4 + 2) * QTP + r] = qv.z;
        Qt[(c4 + 3) * QTP + r] = qv.w;
    }
    if (tid < 128) { rowm[tid] = -1e30f; rowl[tid] = 0.f; }

    float o[8][4];
#pragma unroll
    for (int i = 0; i < 8; i++)
#pragma unroll
        for (int j = 0; j < 4; j++) o[i][j] = 0.f;
    __syncthreads();

    for (int kt = 0; kt < SEQ / 64; kt++) {
        for (int idx = tid; idx < 64 * 16; idx += 256) {
            int r = idx >> 4, c4 = (idx & 15) * 4;
            float4 kv = *reinterpret_cast<const float4*>(K + base + (size_t)(kt * 64 + r) * EMB + c4);
            Kt[(c4 + 0) * ATP + r] = kv.x;
            Kt[(c4 + 1) * ATP + r] = kv.y;
            Kt[(c4 + 2) * ATP + r] = kv.z;
            Kt[(c4 + 3) * ATP + r] = kv.w;
            float4 vv = *reinterpret_cast<const float4*>(V + base + (size_t)(kt * 64 + r) * EMB + c4);
            *reinterpret_cast<float4*>(&Vs[r * ATP + c4]) = vv;
        }
        __syncthreads();

        float s[8][4];
#pragma unroll
        for (int i = 0; i < 8; i++)
#pragma unroll
            for (int j = 0; j < 4; j++) s[i][j] = 0.f;
        for (int d = 0; d < 64; d++) {
            float4 qa0 = *reinterpret_cast<const float4*>(&Qt[d * QTP + ti]);
            float4 qa1 = *reinterpret_cast<const float4*>(&Qt[d * QTP + ti + 4]);
            float4 kb = *reinterpret_cast<const float4*>(&Kt[d * ATP + tj]);
            float a[8] = {qa0.x, qa0.y, qa0.z, qa0.w, qa1.x, qa1.y, qa1.z, qa1.w};
            float bb[4] = {kb.x, kb.y, kb.z, kb.w};
#pragma unroll
            for (int i = 0; i < 8; i++)
#pragma unroll
                for (int j = 0; j < 4; j++) s[i][j] += a[i] * bb[j];
        }
        __syncthreads();

        float fi[8];
#pragma unroll
        for (int i = 0; i < 8; i++) {
            int r = ti + i;
            float mloc = fmaxf(fmaxf(s[i][0], s[i][1]), fmaxf(s[i][2], s[i][3])) * 0.125f;
#pragma unroll
            for (int off = 8; off > 0; off >>= 1)
                mloc = fmaxf(mloc, __shfl_xor_sync(0xffffffff, mloc, off));
            float mo = rowm[r];
            float mx = fmaxf(mloc, mo);
            float4 p;
            p.x = __expf(s[i][0] * 0.125f - mx);
            p.y = __expf(s[i][1] * 0.125f - mx);
            p.z = __expf(s[i][2] * 0.125f - mx);
            p.w = __expf(s[i][3] * 0.125f - mx);
            float sm = p.x + p.y + p.z + p.w;
#pragma unroll
            for (int off = 8; off > 0; off >>= 1)
                sm += __shfl_xor_sync(0xffffffff, sm, off);
            *reinterpret_cast<float4*>(&Ps[r * ATP + tj]) = p;
            float f = __expf(mo - mx);
            fi[i] = f;
            if (glead) {
                rowl[r] = rowl[r] * f + sm;
                rowm[r] = mx;
            }
        }
        __syncthreads();

#pragma unroll
        for (int i = 0; i < 8; i++)
#pragma unroll
            for (int j = 0; j < 4; j++) o[i][j] *= fi[i];
        for (int t4 = 0; t4 < 64; t4 += 4) {
            float4 p4[8];
#pragma unroll
            for (int i = 0; i < 8; i++)
                p4[i] = *reinterpret_cast<const float4*>(&Ps[(ti + i) * ATP + t4]);
#pragma unroll
            for (int j4 = 0; j4 < 4; j4++) {
                float4 vb = *reinterpret_cast<const float4*>(&Vs[(t4 + j4) * ATP + tj]);
#pragma unroll
                for (int i = 0; i < 8; i++) {
                    float pj = j4 == 0 ? p4[i].x : j4 == 1 ? p4[i].y : j4 == 2 ? p4[i].z : p4[i].w;
                    o[i][0] += pj * vb.x;
                    o[i][1] += pj * vb.y;
                    o[i][2] += pj * vb.z;
                    o[i][3] += pj * vb.w;
                }
            }
        }
        __syncthreads();
    }
#pragma unroll
    for (int i = 0; i < 8; i++) {
        float inv = 1.0f / rowl[ti + i];
#pragma unroll
        for (int j = 0; j < 4; j++)
            O[base + (size_t)(qt * 128 + ti + i) * EMB + tj + j] = o[i][j] * inv;
    }
}

// ---------------- router: softmax + top-4 + stats ----------------
__global__ __launch_bounds__(128) void router_topk_kernel() {
    const float* __restrict__ logits = g_logits;
    __shared__ float s_imp[NEXP];
    __shared__ int s_cnt[NEXP];
    int tid = threadIdx.x;
    if (tid < NEXP) { s_imp[tid] = 0.f; s_cnt[tid] = 0; }
    __syncthreads();
    int t = blockIdx.x * 128 + tid;
    float p[NEXP];
    float mx = -1e30f;
#pragma unroll
    for (int e = 0; e < NEXP; e++) {
        p[e] = logits[(size_t)t * NEXP + e];
        mx = fmaxf(mx, p[e]);
    }
    float sum = 0.f;
#pragma unroll
    for (int e = 0; e < NEXP; e++) { p[e] = __expf(p[e] - mx); sum += p[e]; }
    float inv = 1.f / sum;
#pragma unroll
    for (int e = 0; e < NEXP; e++) {
        p[e] *= inv;
        atomicAdd(&s_imp[e], p[e]);
    }
    int idx[TOPK];
    float w[TOPK];
    float tot = 0.f;
#pragma unroll
    for (int k = 0; k < TOPK; k++) {
        float best = -1.f;
        int bi = 0;
#pragma unroll
        for (int e = 0; e < NEXP; e++)
            if (p[e] > best) { best = p[e]; bi = e; }
        idx[k] = bi;
        w[k] = best;
        tot += best;
        p[bi] = -1.f;
        atomicAdd(&s_cnt[bi], 1);
    }
    float it = 1.f / tot;
#pragma unroll
    for (int k = 0; k < TOPK; k++) {
        g_topi[t * TOPK + k] = idx[k];
        g_topw[t * TOPK + k] = w[k] * it;
    }
    __syncthreads();
    if (tid < NEXP) {
        atomicAdd(&g_imp[tid], s_imp[tid]);
        atomicAdd(&g_cnt[tid], s_cnt[tid]);
    }
}

// ---------------- prefix scan + aux loss ----------------
__global__ void scan_aux_kernel(float* __restrict__ out, int out_size) {
    if (threadIdx.x == 0) {
        int acc = 0;
        float aux = 0.f;
        for (int e = 0; e < NEXP; e++) {
            g_off[e] = acc;
            acc += g_cnt[e];
            aux += g_imp[e] * (float)g_cnt[e];
        }
        aux *= (float)NEXP / ((float)TOK * (float)TOK);
        if (out_size > TOK * EMB) out[TOK * EMB] = aux;
    }
}

// ---------------- fill per-expert assignment lists ----------------
__global__ __launch_bounds__(128) void fill_assign_kernel() {
    int t = blockIdx.x * 128 + threadIdx.x;
#pragma unroll
    for (int k = 0; k < TOPK; k++) {
        int e = g_topi[t * TOPK + k];
        int pos = atomicAdd(&g_cur[e], 1);
        int gidx = g_off[e] + pos;
        g_atok[gidx] = t;
        g_aw[gidx] = g_topw[t * TOPK + k];
    }
}

__global__ void zero_small_kernel() {
    int i = threadIdx.x;
    if (i < NEXP) { g_imp[i] = 0.f; g_cnt[i] = 0; g_cur[i] = 0; }
}

// ---------------- launch ----------------
extern "C" void kernel_launch(void* const* d_in, const int* in_sizes, int n_in,
                              void* d_out, int out_size) {
    const float* x        = (const float*)d_in[0];
    const float* ln1_g    = (const float*)d_in[1];
    const float* ln1_b    = (const float*)d_in[2];
    const float* wq       = (const float*)d_in[3];
    const float* bq       = (const float*)d_in[4];
    const float* wk       = (const float*)d_in[5];
    const float* bk       = (const float*)d_in[6];
    const float* wv       = (const float*)d_in[7];
    const float* bv       = (const float*)d_in[8];
    const float* wo       = (const float*)d_in[9];
    const float* bo       = (const float*)d_in[10];
    const float* ln2_g    = (const float*)d_in[11];
    const float* ln2_b    = (const float*)d_in[12];
    const float* router_a = (const float*)d_in[13];
    const float* router_b = (const float*)d_in[14];
    const float* re_w1    = (const float*)d_in[15];
    const float* re_b1    = (const float*)d_in[16];
    const float* re_w2    = (const float*)d_in[17];
    const float* re_b2    = (const float*)d_in[18];
    const float* se_w1    = (const float*)d_in[19];
    const float* se_b1    = (const float*)d_in[20];
    const float* se_w2    = (const float*)d_in[21];
    const float* se_b2    = (const float*)d_in[22];
    float* out = (float*)d_out;

    float *p_h1, *p_attn, *p_x1, *p_h2, *p_rlat, *p_logits, *p_hs;
    cudaGetSymbolAddress((void**)&p_h1, g_h1);
    cudaGetSymbolAddress((void**)&p_attn, g_attn);
    cudaGetSymbolAddress((void**)&p_x1, g_x1);
    cudaGetSymbolAddress((void**)&p_h2, g_h2);
    cudaGetSymbolAddress((void**)&p_rlat, g_rlat);
    cudaGetSymbolAddress((void**)&p_logits, g_logits);
    cudaGetSymbolAddress((void**)&p_hs, g_hs);

    cudaFuncSetAttribute(tgemm<0>, cudaFuncAttributeMaxDynamicSharedMemorySize, TG_SMEM);
    cudaFuncSetAttribute(tgemm<1>, cudaFuncAttributeMaxDynamicSharedMemorySize, TG_SMEM);
    cudaFuncSetAttribute(qkv_tgemm, cudaFuncAttributeMaxDynamicSharedMemorySize, TG_SMEM);
    cudaFuncSetAttribute(routed_tgemm1, cudaFuncAttributeMaxDynamicSharedMemorySize, TG_SMEM);
    cudaFuncSetAttribute(routed_tgemm2, cudaFuncAttributeMaxDynamicSharedMemorySize, TG_SMEM);
    cudaFuncSetAttribute(shared2_splitk, cudaFuncAttributeMaxDynamicSharedMemorySize, TG_SMEM);
    cudaFuncSetAttribute(wo_splitk, cudaFuncAttributeMaxDynamicSharedMemorySize, TG_SMEM);
    cudaFuncSetAttribute(attn_kernel, cudaFuncAttributeMaxDynamicSharedMemorySize, AT_SMEM);

    zero_small_kernel<<<1, 32>>>();
    ln_kernel<<<TOK, 128>>>(x, ln1_g, ln1_b, p_h1);

    qkv_tgemm<<<dim3(4, 32, 3), 256, TG_SMEM>>>(p_h1, wq, wk, wv, bq, bk, bv);

    attn_kernel<<<dim3(32, 8), 256, AT_SMEM>>>();

    // x1 = x + bo, then split-K O-projection accumulates attn @ wo
    init_add_bias<<<(TOK * EMB / 4) / 256, 256>>>(x, bo, p_x1);
    wo_splitk<<<dim3(4, 32, WOSPLIT), 256, TG_SMEM>>>(p_attn, wo, p_x1);

    ln_kernel<<<TOK, 128>>>(p_x1, ln2_g, ln2_b, p_h2);

    sgemm<0><<<dim3(1, 32), 256>>>(p_h2, router_a, nullptr, nullptr, p_rlat, TOK, RRANK, EMB);
    sgemm<0><<<dim3(1, 32), 256>>>(p_rlat, router_b, nullptr, nullptr, p_logits, TOK, NEXP, RRANK);
    router_topk_kernel<<<TOK / 128, 128>>>();
    scan_aux_kernel<<<1, 32>>>(out, out_size);
    fill_assign_kernel<<<TOK / 128, 128>>>();

    routed_tgemm1<<<dim3(4, 32, 32), 256, TG_SMEM>>>(re_w1, re_b1);

    tgemm<1><<<dim3(32, 32), 256, TG_SMEM>>>(p_h2, se_w1, se_b1, nullptr, p_hs, TOK, SHID, EMB);

    init_add_bias<<<(TOK * EMB / 4) / 256, 256>>>(p_x1, se_b2, out);
    shared2_splitk<<<dim3(4, 32, KSPLIT), 256, TG_SMEM>>>(p_hs, se_w2, out);
    routed_tgemm2<<<dim3(4, 32, 32), 256, TG_SMEM>>>(re_w2, re_b2, out);
}

// round 14
// speedup vs baseline: 1.2648x; 1.0116x over previous
#include <cuda_runtime.h>
#include <math.h>

// ---------------- problem constants ----------------
#define TOK   4096          // B*S = 4*1024
#define SEQ   1024
#define BATCH 4
#define EMB   512
#define NH    8
#define HD    64
#define NEXP  32
#define TOPK  4
#define RRANK 64
#define SHID  4096
#define EHID  512

// ---------------- device scratch (static, allocation-free) ----------------
__device__ float g_h1[TOK * EMB];
__device__ float g_q[TOK * EMB];
__device__ float g_k[TOK * EMB];
__device__ float g_v[TOK * EMB];
__device__ float g_attn[TOK * EMB];
__device__ float g_x1[TOK * EMB];
__device__ float g_h2[TOK * EMB];
__device__ float g_rlat[TOK * RRANK];
__device__ float g_logits[TOK * NEXP];
__device__ int   g_topi[TOK * TOPK];
__device__ float g_topw[TOK * TOPK];
__device__ float g_imp[NEXP];
__device__ int   g_cnt[NEXP];
__device__ int   g_off[NEXP];
__device__ int   g_cur[NEXP];
__device__ int   g_atok[TOK * TOPK];
__device__ float g_aw[TOK * TOPK];
__device__ float g_H[TOK * TOPK * EHID];   // routed hidden
__device__ float g_hs[TOK * SHID];         // shared-expert hidden

// ---------------- helpers ----------------
__device__ __forceinline__ float gelu_tanh(float x) {
    float x3 = x * x * x;
    return 0.5f * x * (1.0f + tanhf(0.7978845608028654f * (x + 0.044715f * x3)));
}

__device__ __forceinline__ unsigned f2tf32(float f) {
    unsigned r;
    asm("cvt.rna.tf32.f32 %0, %1;" : "=r"(r) : "f"(f));
    return r;
}

// hi = rna-rounded tf32; lo = raw residual (tf32 HW reads only upper bits).
__device__ __forceinline__ void tf32_split(float f, unsigned& hi, unsigned& lo) {
    hi = f2tf32(f);
    lo = __float_as_uint(f - __uint_as_float(hi));
}

__device__ __forceinline__ void mma_tf32(float& c0, float& c1, float& c2, float& c3,
                                         unsigned a0, unsigned a1, unsigned a2, unsigned a3,
                                         unsigned b0, unsigned b1) {
    asm volatile(
        "mma.sync.aligned.m16n8k8.row.col.f32.tf32.tf32.f32 "
        "{%0,%1,%2,%3}, {%4,%5,%6,%7}, {%8,%9}, {%0,%1,%2,%3};"
        : "+f"(c0), "+f"(c1), "+f"(c2), "+f"(c3)
        : "r"(a0), "r"(a1), "r"(a2), "r"(a3), "r"(b0), "r"(b1));
}

__device__ __forceinline__ void cp16(float* s, const float* g) {
    unsigned sa = (unsigned)__cvta_generic_to_shared(s);
    asm volatile("cp.async.cg.shared.global [%0], [%1], 16;" :: "r"(sa), "l"(g));
}
__device__ __forceinline__ void cp_commit() {
    asm volatile("cp.async.commit_group;");
}

// ---------------- packed f32x2 helpers (sm_100a) ----------------
typedef unsigned long long u64t;
__device__ __forceinline__ u64t pk2(float lo, float hi) {
    u64t r;
    asm("mov.b64 %0, {%1, %2};" : "=l"(r) : "f"(lo), "f"(hi));
    return r;
}
__device__ __forceinline__ void upk2(u64t v, float& lo, float& hi) {
    asm("mov.b64 {%0, %1}, %2;" : "=f"(lo), "=f"(hi) : "l"(v));
}
__device__ __forceinline__ void fma2(u64t& acc, u64t a, u64t b) {
    asm("fma.rn.f32x2 %0, %1, %2, %0;" : "+l"(acc) : "l"(a), "l"(b));
}
__device__ __forceinline__ void mul2(u64t& acc, u64t f) {
    asm("mul.rn.f32x2 %0, %1, %2;" : "+l"(acc) : "l"(acc), "l"(f));
}

// ================= 3xTF32 tensor-core GEMM, cp.async double-buffered ============
#define APAD 36
#define BPAD 136
#define ASZ (128 * APAD)
#define BSZ (32 * BPAD)
#define TG_SMEM ((2 * ASZ + 2 * BSZ) * 4)   // 71680 bytes

// EPI 0: plain store; EPI 1: gelu scatter (A gathered); EPI 2: atomic token
// scatter (A local); EPI 3: plain atomicAdd (split-K).
template <int ACT, int EPI>
__device__ __forceinline__ void tgemm_body(
    const float* __restrict__ A, const float* __restrict__ B,
    const float* __restrict__ bias, const float* __restrict__ res,
    float* __restrict__ C, int M, int N, int K, int Kstride,
    int row0, int col0,
    const int* __restrict__ atok, const float* __restrict__ aw,
    int cnt, int off) {

    extern __shared__ float dsm[];
    float* As = dsm;
    float* Bs = dsm + 2 * ASZ;

    int tid = threadIdx.x;
    int warp = tid >> 5, lane = tid & 31;
    int wm = warp >> 2, wn = warp & 3;
    int g = lane >> 2, t = lane & 3;

    int arow = tid >> 1, acb = (tid & 1) * 16;
    int brow = tid >> 3, bcb = (tid & 7) * 16;

    int asrc;
    if (EPI == 1) {
        int m = row0 + arow;
        asrc = (m < cnt) ? atok[off + m] : 0;
    } else if (EPI == 2) {
        int m = row0 + arow;
        asrc = (m < cnt) ? m : 0;
    } else {
        asrc = row0 + arow;
    }

    const float* Asrc = A + (size_t)asrc * Kstride + acb;
    const float* Bsrc = B + (size_t)brow * N + col0 + bcb;

    float c[4][4][4];
#pragma unroll
    for (int i = 0; i < 4; i++)
#pragma unroll
        for (int j = 0; j < 4; j++) { c[i][j][0] = c[i][j][1] = c[i][j][2] = c[i][j][3] = 0.f; }

    int NS = K / 32;
    {
        float* da = As + arow * APAD + acb;
        float* db = Bs + brow * BPAD + bcb;
#pragma unroll
        for (int i = 0; i < 4; i++) cp16(da + i * 4, Asrc + i * 4);
#pragma unroll
        for (int i = 0; i < 4; i++) cp16(db + i * 4, Bsrc + i * 4);
        cp_commit();
    }

    for (int s = 0; s < NS; s++) {
        if (s + 1 < NS) {
            int buf = (s + 1) & 1;
            int k0 = (s + 1) * 32;
            float* da = As + buf * ASZ + arow * APAD + acb;
            float* db = Bs + buf * BSZ + brow * BPAD + bcb;
#pragma unroll
            for (int i = 0; i < 4; i++) cp16(da + i * 4, Asrc + k0 + i * 4);
#pragma unroll
            for (int i = 0; i < 4; i++) cp16(db + i * 4, Bsrc + (size_t)k0 * N + i * 4);
            cp_commit();
            asm volatile("cp.async.wait_group 1;");
        } else {
            asm volatile("cp.async.wait_group 0;");
        }
        __syncthreads();

        const float* Ab = As + (s & 1) * ASZ;
        const float* Bb = Bs + (s & 1) * BSZ;
#pragma unroll
        for (int kk = 0; kk < 4; kk++) {
            int kb = kk * 8;
            unsigned ah[4][4], al[4][4], bh[4][2], bl[4][2];
#pragma unroll
            for (int mt = 0; mt < 4; mt++) {
                int mb = wm * 64 + mt * 16;
                int i0 = (mb + g) * APAD + kb + t;
                int i1 = (mb + g + 8) * APAD + kb + t;
                tf32_split(Ab[i0],     ah[mt][0], al[mt][0]);
                tf32_split(Ab[i1],     ah[mt][1], al[mt][1]);
                tf32_split(Ab[i0 + 4], ah[mt][2], al[mt][2]);
                tf32_split(Ab[i1 + 4], ah[mt][3], al[mt][3]);
            }
#pragma unroll
            for (int nt = 0; nt < 4; nt++) {
                int nb = wn * 32 + nt * 8;
                tf32_split(Bb[(kb + t) * BPAD + nb + g],     bh[nt][0], bl[nt][0]);
                tf32_split(Bb[(kb + t + 4) * BPAD + nb + g], bh[nt][1], bl[nt][1]);
            }
#pragma unroll
            for (int mt = 0; mt < 4; mt++)
#pragma unroll
                for (int nt = 0; nt < 4; nt++) {
                    mma_tf32(c[mt][nt][0], c[mt][nt][1], c[mt][nt][2], c[mt][nt][3],
                             al[mt][0], al[mt][1], al[mt][2], al[mt][3],
                             bh[nt][0], bh[nt][1]);
                    mma_tf32(c[mt][nt][0], c[mt][nt][1], c[mt][nt][2], c[mt][nt][3],
                             ah[mt][0], ah[mt][1], ah[mt][2], ah[mt][3],
                             bl[nt][0], bl[nt][1]);
                    mma_tf32(c[mt][nt][0], c[mt][nt][1], c[mt][nt][2], c[mt][nt][3],
                             ah[mt][0], ah[mt][1], ah[mt][2], ah[mt][3],
                             bh[nt][0], bh[nt][1]);
                }
        }
        __syncthreads();
    }

#pragma unroll
    for (int mt = 0; mt < 4; mt++) {
        int mb = row0 + wm * 64 + mt * 16;
#pragma unroll
        for (int nt = 0; nt < 4; nt++) {
            int nb = col0 + wn * 32 + nt * 8 + 2 * t;
#pragma unroll
            for (int half = 0; half < 2; half++) {
                int r = mb + g + half * 8;
                float v0 = c[mt][nt][half * 2 + 0];
                float v1 = c[mt][nt][half * 2 + 1];
                if (EPI == 0) {
                    if (bias) { v0 += bias[nb]; v1 += bias[nb + 1]; }
                    if (ACT == 1) { v0 = gelu_tanh(v0); v1 = gelu_tanh(v1); }
                    if (res) {
                        v0 += res[(size_t)r * N + nb];
                        v1 += res[(size_t)r * N + nb + 1];
                    }
                    C[(size_t)r * N + nb] = v0;
                    C[(size_t)r * N + nb + 1] = v1;
                } else if (EPI == 1) {
                    if (r < cnt) {
                        C[(size_t)(off + r) * N + nb] = gelu_tanh(v0 + bias[nb]);
                        C[(size_t)(off + r) * N + nb + 1] = gelu_tanh(v1 + bias[nb + 1]);
                    }
                } else if (EPI == 2) {
                    if (r < cnt) {
                        int tok = atok[off + r];
                        float wgt = aw[off + r];
                        atomicAdd(&C[(size_t)tok * N + nb], (v0 + bias[nb]) * wgt);
                        atomicAdd(&C[(size_t)tok * N + nb + 1], (v1 + bias[nb + 1]) * wgt);
                    }
                } else {
                    atomicAdd(&C[(size_t)r * N + nb], v0);
                    atomicAdd(&C[(size_t)r * N + nb + 1], v1);
                }
            }
        }
    }
}

template <int ACT>
__global__ __launch_bounds__(256, 2) void tgemm(const float* __restrict__ A,
                                                const float* __restrict__ B,
                                                const float* __restrict__ bias,
                                                const float* __restrict__ res,
                                                float* __restrict__ C,
                                                int M, int N, int K) {
    tgemm_body<ACT, 0>(A, B, bias, res, C, M, N, K, K,
                       blockIdx.y * 128, blockIdx.x * 128, nullptr, nullptr, 0, 0);
}

__global__ __launch_bounds__(256, 2) void qkv_tgemm(const float* __restrict__ A,
                                                    const float* __restrict__ wq,
                                                    const float* __restrict__ wk,
                                                    const float* __restrict__ wv,
                                                    const float* __restrict__ bq,
                                                    const float* __restrict__ bk,
                                                    const float* __restrict__ bv) {
    int z = blockIdx.z;
    const float* W = (z == 0) ? wq : (z == 1) ? wk : wv;
    const float* bias = (z == 0) ? bq : (z == 1) ? bk : bv;
    float* C = (z == 0) ? g_q : (z == 1) ? g_k : g_v;
    tgemm_body<0, 0>(A, W, bias, nullptr, C, TOK, EMB, EMB, EMB,
                     blockIdx.y * 128, blockIdx.x * 128, nullptr, nullptr, 0, 0);
}

__global__ __launch_bounds__(256, 2) void routed_tgemm1(const float* __restrict__ W1all,
                                                        const float* __restrict__ b1all) {
    int e = blockIdx.z;
    int cnt = g_cnt[e];
    int m0 = blockIdx.y * 128;
    if (m0 >= cnt) return;
    tgemm_body<0, 1>(g_h2, W1all + (size_t)e * EMB * EHID, b1all + (size_t)e * EHID,
                     nullptr, g_H, TOK, EHID, EMB, EMB,
                     m0, blockIdx.x * 128, g_atok, nullptr, cnt, g_off[e]);
}

__global__ __launch_bounds__(256, 2) void routed_tgemm2(const float* __restrict__ W2all,
                                                        const float* __restrict__ b2all,
                                                        float* __restrict__ out) {
    int e = blockIdx.z;
    int cnt = g_cnt[e];
    int m0 = blockIdx.y * 128;
    if (m0 >= cnt) return;
    int off = g_off[e];
    tgemm_body<0, 2>(g_H + (size_t)off * EHID, W2all + (size_t)e * EHID * EMB,
                     b2all + (size_t)e * EMB, nullptr, out, TOK, EMB, EHID, EHID,
                     m0, blockIdx.x * 128, g_atok, g_aw, cnt, off);
}

#define KSPLIT 4
#define KCH (SHID / KSPLIT)
__global__ __launch_bounds__(256, 2) void shared2_splitk(const float* __restrict__ hs,
                                                         const float* __restrict__ w2,
                                                         float* __restrict__ out) {
    int kc = blockIdx.z;
    tgemm_body<0, 3>(hs + (size_t)kc * KCH, w2 + (size_t)kc * KCH * EMB,
                     nullptr, nullptr, out, TOK, EMB, KCH, SHID,
                     blockIdx.y * 128, blockIdx.x * 128, nullptr, nullptr, 0, 0);
}

#define WOSPLIT 2
#define WOCH (EMB / WOSPLIT)
__global__ __launch_bounds__(256, 2) void wo_splitk(const float* __restrict__ attn,
                                                    const float* __restrict__ wo,
                                                    float* __restrict__ x1) {
    int kc = blockIdx.z;
    tgemm_body<0, 3>(attn + (size_t)kc * WOCH, wo + (size_t)kc * WOCH * EMB,
                     nullptr, nullptr, x1, TOK, EMB, WOCH, EMB,
                     blockIdx.y * 128, blockIdx.x * 128, nullptr, nullptr, 0, 0);
}

__global__ __launch_bounds__(256) void init_add_bias(const float* __restrict__ src,
                                                     const float* __restrict__ bias,
                                                     float* __restrict__ dst) {
    int i = blockIdx.x * 256 + threadIdx.x;
    float4 v = reinterpret_cast<const float4*>(src)[i];
    int col = (i * 4) & (EMB - 1);
    float4 b = *reinterpret_cast<const float4*>(bias + col);
    v.x += b.x; v.y += b.y; v.z += b.z; v.w += b.w;
    reinterpret_cast<float4*>(dst)[i] = v;
}

// ---------------- LayerNorm ----------------
__global__ __launch_bounds__(128) void ln_kernel(const float* __restrict__ X,
                                                 const float* __restrict__ g,
                                                 const float* __restrict__ b,
                                                 float* __restrict__ Y) {
    int t = blockIdx.x;
    int tid = threadIdx.x;
    const float4 v = *reinterpret_cast<const float4*>(X + (size_t)t * EMB + tid * 4);
    float s  = v.x + v.y + v.z + v.w;
    float sq = v.x * v.x + v.y * v.y + v.z * v.z + v.w * v.w;
    for (int o = 16; o > 0; o >>= 1) {
        s  += __shfl_xor_sync(0xffffffff, s, o);
        sq += __shfl_xor_sync(0xffffffff, sq, o);
    }
    __shared__ float ssum[4], ssq[4], stats[2];
    int w = tid >> 5;
    if ((tid & 31) == 0) { ssum[w] = s; ssq[w] = sq; }
    __syncthreads();
    if (tid == 0) {
        float S = ssum[0] + ssum[1] + ssum[2] + ssum[3];
        float Q = ssq[0] + ssq[1] + ssq[2] + ssq[3];
        float mu = S * (1.0f / EMB);
        float var = Q * (1.0f / EMB) - mu * mu;
        stats[0] = mu;
        stats[1] = rsqrtf(var + 1e-5f);
    }
    __syncthreads();
    float mu = stats[0], rs = stats[1];
    int cc = tid * 4;
    float4 gg = *reinterpret_cast<const float4*>(g + cc);
    float4 bb = *reinterpret_cast<const float4*>(b + cc);
    float4 o;
    o.x = (v.x - mu) * rs * gg.x + bb.x;
    o.y = (v.y - mu) * rs * gg.y + bb.y;
    o.z = (v.z - mu) * rs * gg.z + bb.z;
    o.w = (v.w - mu) * rs * gg.w + bb.w;
    *reinterpret_cast<float4*>(Y + (size_t)t * EMB + cc) = o;
}

// ---------------- fp32 SGEMM (router only, small N) ----------------
template <int ACT>
__global__ __launch_bounds__(256) void sgemm(const float* __restrict__ A,
                                             const float* __restrict__ B,
                                             const float* __restrict__ bias,
                                             const float* __restrict__ res,
                                             float* __restrict__ C,
                                             int M, int N, int K) {
    __shared__ float As[8][128];
    __shared__ float Bs[8][128];
    int tid = threadIdx.x;
    int row0 = blockIdx.y * 128, col0 = blockIdx.x * 128;
    int aRow = tid >> 1, aCol = (tid & 1) * 4;
    int bRow = tid >> 5, bCol = (tid & 31) * 4;
    int tr = (tid >> 4) * 8, tc = (tid & 15) * 8;

    float acc[8][8];
#pragma unroll
    for (int i = 0; i < 8; i++)
#pragma unroll
        for (int j = 0; j < 8; j++) acc[i][j] = 0.f;

    const float* Ap = A + (size_t)(row0 + aRow) * K + aCol;
    for (int k0 = 0; k0 < K; k0 += 8) {
        float4 av = *reinterpret_cast<const float4*>(Ap + k0);
        As[aCol + 0][aRow] = av.x;
        As[aCol + 1][aRow] = av.y;
        As[aCol + 2][aRow] = av.z;
        As[aCol + 3][aRow] = av.w;
        int gc = col0 + bCol;
        const float* Bp = B + (size_t)(k0 + bRow) * N + gc;
        float4 bv;
        if (gc + 3 < N) {
            bv = *reinterpret_cast<const float4*>(Bp);
        } else {
            bv.x = (gc + 0 < N) ? Bp[0] : 0.f;
            bv.y = (gc + 1 < N) ? Bp[1] : 0.f;
            bv.z = (gc + 2 < N) ? Bp[2] : 0.f;
            bv.w = (gc + 3 < N) ? Bp[3] : 0.f;
        }
        Bs[bRow][bCol + 0] = bv.x;
        Bs[bRow][bCol + 1] = bv.y;
        Bs[bRow][bCol + 2] = bv.z;
        Bs[bRow][bCol + 3] = bv.w;
        __syncthreads();
#pragma unroll
        for (int k = 0; k < 8; k++) {
            float4 ra0 = *reinterpret_cast<const float4*>(&As[k][tr]);
            float4 ra1 = *reinterpret_cast<const float4*>(&As[k][tr + 4]);
            float4 rb0 = *reinterpret_cast<const float4*>(&Bs[k][tc]);
            float4 rb1 = *reinterpret_cast<const float4*>(&Bs[k][tc + 4]);
            float ra[8] = {ra0.x, ra0.y, ra0.z, ra0.w, ra1.x, ra1.y, ra1.z, ra1.w};
            float rb[8] = {rb0.x, rb0.y, rb0.z, rb0.w, rb1.x, rb1.y, rb1.z, rb1.w};
#pragma unroll
            for (int i = 0; i < 8; i++)
#pragma unroll
                for (int j = 0; j < 8; j++) acc[i][j] += ra[i] * rb[j];
        }
        __syncthreads();
    }
#pragma unroll
    for (int i = 0; i < 8; i++) {
        int gr = row0 + tr + i;
#pragma unroll
        for (int j = 0; j < 8; j++) {
            int gc = col0 + tc + j;
            if (gc < N) {
                float v = acc[i][j];
                if (bias) v += bias[gc];
                if (ACT == 1) v = gelu_tanh(v);
                if (res) v += res[(size_t)gr * N + gc];
                C[(size_t)gr * N + gc] = v;
            }
        }
    }
}

// ---------------- flash attention v6: packed f32x2 FMA ----------
#define QTP 132
#define ATP 68
#define QT_FLOATS (64 * QTP)
#define PS_FLOATS (128 * ATP)
#define VS_FLOATS (64 * ATP)
#define AT_SMEM ((QT_FLOATS + PS_FLOATS + VS_FLOATS) * 4)   // 86016

__global__ __launch_bounds__(256, 2) void attn_kernel() {
    const float* __restrict__ Q = g_q;
    const float* __restrict__ K = g_k;
    const float* __restrict__ V = g_v;
    float* __restrict__ O = g_attn;

    extern __shared__ float dsm[];
    float* Qt = dsm;
    float* Kt = dsm + QT_FLOATS;
    float* Ps = Kt;
    float* Vs = dsm + QT_FLOATS + PS_FLOATS;

    __shared__ float rowm[128], rowl[128];

    int bh = blockIdx.x;
    int qt = blockIdx.y;
    int b = bh >> 3, h = bh & 7;
    const size_t base = (size_t)b * SEQ * EMB + h * HD;
    int tid = threadIdx.x;
    int ti = (tid >> 4) * 8;
    int tj = (tid & 15) * 4;
    bool glead = ((tid & 15) == 0);

    for (int idx = tid; idx < 128 * 16; idx += 256) {
        int r = idx >> 4, c4 = (idx & 15) * 4;
        float4 qv = *reinterpret_cast<const float4*>(Q + base + (size_t)(qt * 128 + r) * EMB + c4);
        Qt[(c4 + 0) * QTP + r] = qv.x;
        Qt[(c4 + 1) * QTP + r] = qv.y;
        Qt[(c4 + 2) * QTP + r] = qv.z;
        Qt[(c4 + 3) * QTP + r] = qv.w;
    }
    if (tid < 128) { rowm[tid] = -1e30f; rowl[tid] = 0.f; }

    // packed O accumulators: o2[i][0]=(d0,d1), o2[i][1]=(d2,d3)
    u64t o2[8][2];
#pragma unroll
    for (int i = 0; i < 8; i++) { o2[i][0] = 0ull; o2[i][1] = 0ull; }
    __syncthreads();

    for (int kt = 0; kt < SEQ / 64; kt++) {
        for (int idx = tid; idx < 64 * 16; idx += 256) {
            int r = idx >> 4, c4 = (idx & 15) * 4;
            float4 kv = *reinterpret_cast<const float4*>(K + base + (size_t)(kt * 64 + r) * EMB + c4);
            Kt[(c4 + 0) * ATP + r] = kv.x;
            Kt[(c4 + 1) * ATP + r] = kv.y;
            Kt[(c4 + 2) * ATP + r] = kv.z;
            Kt[(c4 + 3) * ATP + r] = kv.w;
            float4 vv = *reinterpret_cast<const float4*>(V + base + (size_t)(kt * 64 + r) * EMB + c4);
            *reinterpret_cast<float4*>(&Vs[r * ATP + c4]) = vv;
        }
        __syncthreads();

        // S = Q @ K^T with packed FMA: s2[i][0]=(k0,k1), s2[i][1]=(k2,k3)
        u64t s2[8][2];
#pragma unroll
        for (int i = 0; i < 8; i++) { s2[i][0] = 0ull; s2[i][1] = 0ull; }
        for (int d = 0; d < 64; d++) {
            float4 qa0 = *reinterpret_cast<const float4*>(&Qt[d * QTP + ti]);
            float4 qa1 = *reinterpret_cast<const float4*>(&Qt[d * QTP + ti + 4]);
            float4 kb = *reinterpret_cast<const float4*>(&Kt[d * ATP + tj]);
            u64t kb01 = pk2(kb.x, kb.y);
            u64t kb23 = pk2(kb.z, kb.w);
            float a[8] = {qa0.x, qa0.y, qa0.z, qa0.w, qa1.x, qa1.y, qa1.z, qa1.w};
#pragma unroll
            for (int i = 0; i < 8; i++) {
                u64t aa = pk2(a[i], a[i]);
                fma2(s2[i][0], aa, kb01);
                fma2(s2[i][1], aa, kb23);
            }
        }
        __syncthreads();   // Kt reads done -> safe to overwrite with P

        // register softmax per row (16-lane groups)
        float fi[8];
#pragma unroll
        for (int i = 0; i < 8; i++) {
            int r = ti + i;
            float s0, s1, s2f, s3;
            upk2(s2[i][0], s0, s1);
            upk2(s2[i][1], s2f, s3);
            float mloc = fmaxf(fmaxf(s0, s1), fmaxf(s2f, s3)) * 0.125f;
#pragma unroll
            for (int off = 8; off > 0; off >>= 1)
                mloc = fmaxf(mloc, __shfl_xor_sync(0xffffffff, mloc, off));
            float mo = rowm[r];
            float mx = fmaxf(mloc, mo);
            float4 p;
            p.x = __expf(s0 * 0.125f - mx);
            p.y = __expf(s1 * 0.125f - mx);
            p.z = __expf(s2f * 0.125f - mx);
            p.w = __expf(s3 * 0.125f - mx);
            float sm = p.x + p.y + p.z + p.w;
#pragma unroll
            for (int off = 8; off > 0; off >>= 1)
                sm += __shfl_xor_sync(0xffffffff, sm, off);
            *reinterpret_cast<float4*>(&Ps[r * ATP + tj]) = p;
            float f = __expf(mo - mx);
            fi[i] = f;
            if (glead) {
                rowl[r] = rowl[r] * f + sm;
                rowm[r] = mx;
            }
        }
        __syncthreads();

        // O rescale + O += P @ V (packed)
#pragma unroll
        for (int i = 0; i < 8; i++) {
            u64t ff = pk2(fi[i], fi[i]);
            mul2(o2[i][0], ff);
            mul2(o2[i][1], ff);
        }
        for (int t4 = 0; t4 < 64; t4 += 4) {
            float4 p4[8];
#pragma unroll
            for (int i = 0; i < 8; i++)
                p4[i] = *reinterpret_cast<const float4*>(&Ps[(ti + i) * ATP + t4]);
#pragma unroll
            for (int j4 = 0; j4 < 4; j4++) {
                float4 vb = *reinterpret_cast<const float4*>(&Vs[(t4 + j4) * ATP + tj]);
                u64t vb01 = pk2(vb.x, vb.y);
                u64t vb23 = pk2(vb.z, vb.w);
#pragma unroll
                for (int i = 0; i < 8; i++) {
                    float pj = j4 == 0 ? p4[i].x : j4 == 1 ? p4[i].y : j4 == 2 ? p4[i].z : p4[i].w;
                    u64t pp = pk2(pj, pj);
                    fma2(o2[i][0], pp, vb01);
                    fma2(o2[i][1], pp, vb23);
                }
            }
        }
        __syncthreads();
    }
#pragma unroll
    for (int i = 0; i < 8; i++) {
        float inv = 1.0f / rowl[ti + i];
        float o0, o1, o2f, o3;
        upk2(o2[i][0], o0, o1);
        upk2(o2[i][1], o2f, o3);
        float* dst = O + base + (size_t)(qt * 128 + ti + i) * EMB + tj;
        dst[0] = o0 * inv;
        dst[1] = o1 * inv;
        dst[2] = o2f * inv;
        dst[3] = o3 * inv;
    }
}

// ---------------- router: softmax + top-4 + stats ----------------
__global__ __launch_bounds__(128) void router_topk_kernel() {
    const float* __restrict__ logits = g_logits;
    __shared__ float s_imp[NEXP];
    __shared__ int s_cnt[NEXP];
    int tid = threadIdx.x;
    if (tid < NEXP) { s_imp[tid] = 0.f; s_cnt[tid] = 0; }
    __syncthreads();
    int t = blockIdx.x * 128 + tid;
    float p[NEXP];
    float mx = -1e30f;
#pragma unroll
    for (int e = 0; e < NEXP; e++) {
        p[e] = logits[(size_t)t * NEXP + e];
        mx = fmaxf(mx, p[e]);
    }
    float sum = 0.f;
#pragma unroll
    for (int e = 0; e < NEXP; e++) { p[e] = __expf(p[e] - mx); sum += p[e]; }
    float inv = 1.f / sum;
#pragma unroll
    for (int e = 0; e < NEXP; e++) {
        p[e] *= inv;
        atomicAdd(&s_imp[e], p[e]);
    }
    int idx[TOPK];
    float w[TOPK];
    float tot = 0.f;
#pragma unroll
    for (int k = 0; k < TOPK; k++) {
        float best = -1.f;
        int bi = 0;
#pragma unroll
        for (int e = 0; e < NEXP; e++)
            if (p[e] > best) { best = p[e]; bi = e; }
        idx[k] = bi;
        w[k] = best;
        tot += best;
        p[bi] = -1.f;
        atomicAdd(&s_cnt[bi], 1);
    }
    float it = 1.f / tot;
#pragma unroll
    for (int k = 0; k < TOPK; k++) {
        g_topi[t * TOPK + k] = idx[k];
        g_topw[t * TOPK + k] = w[k] * it;
    }
    __syncthreads();
    if (tid < NEXP) {
        atomicAdd(&g_imp[tid], s_imp[tid]);
        atomicAdd(&g_cnt[tid], s_cnt[tid]);
    }
}

// ---------------- prefix scan + aux loss ----------------
__global__ void scan_aux_kernel(float* __restrict__ out, int out_size) {
    if (threadIdx.x == 0) {
        int acc = 0;
        float aux = 0.f;
        for (int e = 0; e < NEXP; e++) {
            g_off[e] = acc;
            acc += g_cnt[e];
            aux += g_imp[e] * (float)g_cnt[e];
        }
        aux *= (float)NEXP / ((float)TOK * (float)TOK);
        if (out_size > TOK * EMB) out[TOK * EMB] = aux;
    }
}

// ---------------- fill per-expert assignment lists ----------------
__global__ __launch_bounds__(128) void fill_assign_kernel() {
    int t = blockIdx.x * 128 + threadIdx.x;
#pragma unroll
    for (int k = 0; k < TOPK; k++) {
        int e = g_topi[t * TOPK + k];
        int pos = atomicAdd(&g_cur[e], 1);
        int gidx = g_off[e] + pos;
        g_atok[gidx] = t;
        g_aw[gidx] = g_topw[t * TOPK + k];
    }
}

__global__ void zero_small_kernel() {
    int i = threadIdx.x;
    if (i < NEXP) { g_imp[i] = 0.f; g_cnt[i] = 0; g_cur[i] = 0; }
}

// ---------------- launch ----------------
extern "C" void kernel_launch(void* const* d_in, const int* in_sizes, int n_in,
                              void* d_out, int out_size) {
    const float* x        = (const float*)d_in[0];
    const float* ln1_g    = (const float*)d_in[1];
    const float* ln1_b    = (const float*)d_in[2];
    const float* wq       = (const float*)d_in[3];
    const float* bq       = (const float*)d_in[4];
    const float* wk       = (const float*)d_in[5];
    const float* bk       = (const float*)d_in[6];
    const float* wv       = (const float*)d_in[7];
    const float* bv       = (const float*)d_in[8];
    const float* wo       = (const float*)d_in[9];
    const float* bo       = (const float*)d_in[10];
    const float* ln2_g    = (const float*)d_in[11];
    const float* ln2_b    = (const float*)d_in[12];
    const float* router_a = (const float*)d_in[13];
    const float* router_b = (const float*)d_in[14];
    const float* re_w1    = (const float*)d_in[15];
    const float* re_b1    = (const float*)d_in[16];
    const float* re_w2    = (const float*)d_in[17];
    const float* re_b2    = (const float*)d_in[18];
    const float* se_w1    = (const float*)d_in[19];
    const float* se_b1    = (const float*)d_in[20];
    const float* se_w2    = (const float*)d_in[21];
    const float* se_b2    = (const float*)d_in[22];
    float* out = (float*)d_out;

    float *p_h1, *p_attn, *p_x1, *p_h2, *p_rlat, *p_logits, *p_hs;
    cudaGetSymbolAddress((void**)&p_h1, g_h1);
    cudaGetSymbolAddress((void**)&p_attn, g_attn);
    cudaGetSymbolAddress((void**)&p_x1, g_x1);
    cudaGetSymbolAddress((void**)&p_h2, g_h2);
    cudaGetSymbolAddress((void**)&p_rlat, g_rlat);
    cudaGetSymbolAddress((void**)&p_logits, g_logits);
    cudaGetSymbolAddress((void**)&p_hs, g_hs);

    cudaFuncSetAttribute(tgemm<0>, cudaFuncAttributeMaxDynamicSharedMemorySize, TG_SMEM);
    cudaFuncSetAttribute(tgemm<1>, cudaFuncAttributeMaxDynamicSharedMemorySize, TG_SMEM);
    cudaFuncSetAttribute(qkv_tgemm, cudaFuncAttributeMaxDynamicSharedMemorySize, TG_SMEM);
    cudaFuncSetAttribute(routed_tgemm1, cudaFuncAttributeMaxDynamicSharedMemorySize, TG_SMEM);
    cudaFuncSetAttribute(routed_tgemm2, cudaFuncAttributeMaxDynamicSharedMemorySize, TG_SMEM);
    cudaFuncSetAttribute(shared2_splitk, cudaFuncAttributeMaxDynamicSharedMemorySize, TG_SMEM);
    cudaFuncSetAttribute(wo_splitk, cudaFuncAttributeMaxDynamicSharedMemorySize, TG_SMEM);
    cudaFuncSetAttribute(attn_kernel, cudaFuncAttributeMaxDynamicSharedMemorySize, AT_SMEM);

    zero_small_kernel<<<1, 32>>>();
    ln_kernel<<<TOK, 128>>>(x, ln1_g, ln1_b, p_h1);

    qkv_tgemm<<<dim3(4, 32, 3), 256, TG_SMEM>>>(p_h1, wq, wk, wv, bq, bk, bv);

    attn_kernel<<<dim3(32, 8), 256, AT_SMEM>>>();

    init_add_bias<<<(TOK * EMB / 4) / 256, 256>>>(x, bo, p_x1);
    wo_splitk<<<dim3(4, 32, WOSPLIT), 256, TG_SMEM>>>(p_attn, wo, p_x1);

    ln_kernel<<<TOK, 128>>>(p_x1, ln2_g, ln2_b, p_h2);

    sgemm<0><<<dim3(1, 32), 256>>>(p_h2, router_a, nullptr, nullptr, p_rlat, TOK, RRANK, EMB);
    sgemm<0><<<dim3(1, 32), 256>>>(p_rlat, router_b, nullptr, nullptr, p_logits, TOK, NEXP, RRANK);
    router_topk_kernel<<<TOK / 128, 128>>>();
    scan_aux_kernel<<<1, 32>>>(out, out_size);
    fill_assign_kernel<<<TOK / 128, 128>>>();

    routed_tgemm1<<<dim3(4, 32, 32), 256, TG_SMEM>>>(re_w1, re_b1);

    tgemm<1><<<dim3(32, 32), 256, TG_SMEM>>>(p_h2, se_w1, se_b1, nullptr, p_hs, TOK, SHID, EMB);

    init_add_bias<<<(TOK * EMB / 4) / 256, 256>>>(p_x1, se_b2, out);
    shared2_splitk<<<dim3(4, 32, KSPLIT), 256, TG_SMEM>>>(p_hs, se_w2, out);
    routed_tgemm2<<<dim3(4, 32, 32), 256, TG_SMEM>>>(re_w2, re_b2, out);
}

// round 15
// speedup vs baseline: 1.3137x; 1.0386x over previous
#include <cuda_runtime.h>
#include <math.h>

// ---------------- problem constants ----------------
#define TOK   4096          // B*S = 4*1024
#define SEQ   1024
#define BATCH 4
#define EMB   512
#define NH    8
#define HD    64
#define NEXP  32
#define TOPK  4
#define RRANK 64
#define SHID  4096
#define EHID  512

// ---------------- device scratch (static, allocation-free) ----------------
__device__ float g_h1[TOK * EMB];
__device__ float g_q[TOK * EMB];
__device__ float g_k[TOK * EMB];
__device__ float g_v[TOK * EMB];
__device__ float g_attn[TOK * EMB];
__device__ float g_x1[TOK * EMB];
__device__ float g_h2[TOK * EMB];
__device__ float g_rlat[TOK * RRANK];
__device__ float g_logits[TOK * NEXP];
__device__ int   g_topi[TOK * TOPK];
__device__ float g_topw[TOK * TOPK];
__device__ float g_imp[NEXP];
__device__ int   g_cnt[NEXP];
__device__ int   g_off[NEXP];
__device__ int   g_cur[NEXP];
__device__ int   g_atok[TOK * TOPK];
__device__ float g_aw[TOK * TOPK];
__device__ float g_H[TOK * TOPK * EHID];   // routed hidden
__device__ float g_hs[TOK * SHID];         // shared-expert hidden

// ---------------- helpers ----------------
__device__ __forceinline__ float gelu_tanh(float x) {
    float x3 = x * x * x;
    return 0.5f * x * (1.0f + tanhf(0.7978845608028654f * (x + 0.044715f * x3)));
}

__device__ __forceinline__ unsigned f2tf32(float f) {
    unsigned r;
    asm("cvt.rna.tf32.f32 %0, %1;" : "=r"(r) : "f"(f));
    return r;
}

// hi = rna-rounded tf32; lo = raw residual (tf32 HW reads only upper bits).
__device__ __forceinline__ void tf32_split(float f, unsigned& hi, unsigned& lo) {
    hi = f2tf32(f);
    lo = __float_as_uint(f - __uint_as_float(hi));
}

__device__ __forceinline__ void mma_tf32(float& c0, float& c1, float& c2, float& c3,
                                         unsigned a0, unsigned a1, unsigned a2, unsigned a3,
                                         unsigned b0, unsigned b1) {
    asm volatile(
        "mma.sync.aligned.m16n8k8.row.col.f32.tf32.tf32.f32 "
        "{%0,%1,%2,%3}, {%4,%5,%6,%7}, {%8,%9}, {%0,%1,%2,%3};"
        : "+f"(c0), "+f"(c1), "+f"(c2), "+f"(c3)
        : "r"(a0), "r"(a1), "r"(a2), "r"(a3), "r"(b0), "r"(b1));
}

__device__ __forceinline__ void cp16(float* s, const float* g) {
    unsigned sa = (unsigned)__cvta_generic_to_shared(s);
    asm volatile("cp.async.cg.shared.global [%0], [%1], 16;" :: "r"(sa), "l"(g));
}
__device__ __forceinline__ void cp_commit() {
    asm volatile("cp.async.commit_group;");
}

// ---------------- packed f32x2 helpers (sm_100a) ----------------
typedef unsigned long long u64t;
__device__ __forceinline__ u64t pk2(float lo, float hi) {
    u64t r;
    asm("mov.b64 %0, {%1, %2};" : "=l"(r) : "f"(lo), "f"(hi));
    return r;
}
__device__ __forceinline__ void upk2(u64t v, float& lo, float& hi) {
    asm("mov.b64 {%0, %1}, %2;" : "=f"(lo), "=f"(hi) : "l"(v));
}
__device__ __forceinline__ void fma2(u64t& acc, u64t a, u64t b) {
    asm("fma.rn.f32x2 %0, %1, %2, %0;" : "+l"(acc) : "l"(a), "l"(b));
}
__device__ __forceinline__ void mul2(u64t& acc, u64t f) {
    asm("mul.rn.f32x2 %0, %1, %2;" : "+l"(acc) : "l"(acc), "l"(f));
}

// ================= 3xTF32 tensor-core GEMM, cp.async double-buffered ============
#define APAD 36
#define BPAD 136
#define ASZ (128 * APAD)
#define BSZ (32 * BPAD)
#define TG_SMEM ((2 * ASZ + 2 * BSZ) * 4)   // 71680 bytes

// EPI 0: plain store; EPI 1: gelu scatter (A gathered); EPI 2: atomic token
// scatter (A local); EPI 3: plain atomicAdd (split-K).
template <int ACT, int EPI>
__device__ __forceinline__ void tgemm_body(
    const float* __restrict__ A, const float* __restrict__ B,
    const float* __restrict__ bias, const float* __restrict__ res,
    float* __restrict__ C, int M, int N, int K, int Kstride,
    int row0, int col0,
    const int* __restrict__ atok, const float* __restrict__ aw,
    int cnt, int off) {

    extern __shared__ float dsm[];
    float* As = dsm;
    float* Bs = dsm + 2 * ASZ;

    int tid = threadIdx.x;
    int warp = tid >> 5, lane = tid & 31;
    int wm = warp >> 2, wn = warp & 3;
    int g = lane >> 2, t = lane & 3;

    int arow = tid >> 1, acb = (tid & 1) * 16;
    int brow = tid >> 3, bcb = (tid & 7) * 16;

    int asrc;
    if (EPI == 1) {
        int m = row0 + arow;
        asrc = (m < cnt) ? atok[off + m] : 0;
    } else if (EPI == 2) {
        int m = row0 + arow;
        asrc = (m < cnt) ? m : 0;
    } else {
        asrc = row0 + arow;
    }

    const float* Asrc = A + (size_t)asrc * Kstride + acb;
    const float* Bsrc = B + (size_t)brow * N + col0 + bcb;

    float c[4][4][4];
#pragma unroll
    for (int i = 0; i < 4; i++)
#pragma unroll
        for (int j = 0; j < 4; j++) { c[i][j][0] = c[i][j][1] = c[i][j][2] = c[i][j][3] = 0.f; }

    int NS = K / 32;
    {
        float* da = As + arow * APAD + acb;
        float* db = Bs + brow * BPAD + bcb;
#pragma unroll
        for (int i = 0; i < 4; i++) cp16(da + i * 4, Asrc + i * 4);
#pragma unroll
        for (int i = 0; i < 4; i++) cp16(db + i * 4, Bsrc + i * 4);
        cp_commit();
    }

    for (int s = 0; s < NS; s++) {
        if (s + 1 < NS) {
            int buf = (s + 1) & 1;
            int k0 = (s + 1) * 32;
            float* da = As + buf * ASZ + arow * APAD + acb;
            float* db = Bs + buf * BSZ + brow * BPAD + bcb;
#pragma unroll
            for (int i = 0; i < 4; i++) cp16(da + i * 4, Asrc + k0 + i * 4);
#pragma unroll
            for (int i = 0; i < 4; i++) cp16(db + i * 4, Bsrc + (size_t)k0 * N + i * 4);
            cp_commit();
            asm volatile("cp.async.wait_group 1;");
        } else {
            asm volatile("cp.async.wait_group 0;");
        }
        __syncthreads();

        const float* Ab = As + (s & 1) * ASZ;
        const float* Bb = Bs + (s & 1) * BSZ;
#pragma unroll
        for (int kk = 0; kk < 4; kk++) {
            int kb = kk * 8;
            unsigned ah[4][4], al[4][4], bh[4][2], bl[4][2];
#pragma unroll
            for (int mt = 0; mt < 4; mt++) {
                int mb = wm * 64 + mt * 16;
                int i0 = (mb + g) * APAD + kb + t;
                int i1 = (mb + g + 8) * APAD + kb + t;
                tf32_split(Ab[i0],     ah[mt][0], al[mt][0]);
                tf32_split(Ab[i1],     ah[mt][1], al[mt][1]);
                tf32_split(Ab[i0 + 4], ah[mt][2], al[mt][2]);
                tf32_split(Ab[i1 + 4], ah[mt][3], al[mt][3]);
            }
#pragma unroll
            for (int nt = 0; nt < 4; nt++) {
                int nb = wn * 32 + nt * 8;
                tf32_split(Bb[(kb + t) * BPAD + nb + g],     bh[nt][0], bl[nt][0]);
                tf32_split(Bb[(kb + t + 4) * BPAD + nb + g], bh[nt][1], bl[nt][1]);
            }
#pragma unroll
            for (int mt = 0; mt < 4; mt++)
#pragma unroll
                for (int nt = 0; nt < 4; nt++) {
                    mma_tf32(c[mt][nt][0], c[mt][nt][1], c[mt][nt][2], c[mt][nt][3],
                             al[mt][0], al[mt][1], al[mt][2], al[mt][3],
                             bh[nt][0], bh[nt][1]);
                    mma_tf32(c[mt][nt][0], c[mt][nt][1], c[mt][nt][2], c[mt][nt][3],
                             ah[mt][0], ah[mt][1], ah[mt][2], ah[mt][3],
                             bl[nt][0], bl[nt][1]);
                    mma_tf32(c[mt][nt][0], c[mt][nt][1], c[mt][nt][2], c[mt][nt][3],
                             ah[mt][0], ah[mt][1], ah[mt][2], ah[mt][3],
                             bh[nt][0], bh[nt][1]);
                }
        }
        __syncthreads();
    }

#pragma unroll
    for (int mt = 0; mt < 4; mt++) {
        int mb = row0 + wm * 64 + mt * 16;
#pragma unroll
        for (int nt = 0; nt < 4; nt++) {
            int nb = col0 + wn * 32 + nt * 8 + 2 * t;
#pragma unroll
            for (int half = 0; half < 2; half++) {
                int r = mb + g + half * 8;
                float v0 = c[mt][nt][half * 2 + 0];
                float v1 = c[mt][nt][half * 2 + 1];
                if (EPI == 0) {
                    if (bias) { v0 += bias[nb]; v1 += bias[nb + 1]; }
                    if (ACT == 1) { v0 = gelu_tanh(v0); v1 = gelu_tanh(v1); }
                    if (res) {
                        v0 += res[(size_t)r * N + nb];
                        v1 += res[(size_t)r * N + nb + 1];
                    }
                    C[(size_t)r * N + nb] = v0;
                    C[(size_t)r * N + nb + 1] = v1;
                } else if (EPI == 1) {
                    if (r < cnt) {
                        C[(size_t)(off + r) * N + nb] = gelu_tanh(v0 + bias[nb]);
                        C[(size_t)(off + r) * N + nb + 1] = gelu_tanh(v1 + bias[nb + 1]);
                    }
                } else if (EPI == 2) {
                    if (r < cnt) {
                        int tok = atok[off + r];
                        float wgt = aw[off + r];
                        atomicAdd(&C[(size_t)tok * N + nb], (v0 + bias[nb]) * wgt);
                        atomicAdd(&C[(size_t)tok * N + nb + 1], (v1 + bias[nb + 1]) * wgt);
                    }
                } else {
                    atomicAdd(&C[(size_t)r * N + nb], v0);
                    atomicAdd(&C[(size_t)r * N + nb + 1], v1);
                }
            }
        }
    }
}

template <int ACT>
__global__ __launch_bounds__(256, 2) void tgemm(const float* __restrict__ A,
                                                const float* __restrict__ B,
                                                const float* __restrict__ bias,
                                                const float* __restrict__ res,
                                                float* __restrict__ C,
                                                int M, int N, int K) {
    tgemm_body<ACT, 0>(A, B, bias, res, C, M, N, K, K,
                       blockIdx.y * 128, blockIdx.x * 128, nullptr, nullptr, 0, 0);
}

__global__ __launch_bounds__(256, 2) void qkv_tgemm(const float* __restrict__ A,
                                                    const float* __restrict__ wq,
                                                    const float* __restrict__ wk,
                                                    const float* __restrict__ wv,
                                                    const float* __restrict__ bq,
                                                    const float* __restrict__ bk,
                                                    const float* __restrict__ bv) {
    int z = blockIdx.z;
    const float* W = (z == 0) ? wq : (z == 1) ? wk : wv;
    const float* bias = (z == 0) ? bq : (z == 1) ? bk : bv;
    float* C = (z == 0) ? g_q : (z == 1) ? g_k : g_v;
    tgemm_body<0, 0>(A, W, bias, nullptr, C, TOK, EMB, EMB, EMB,
                     blockIdx.y * 128, blockIdx.x * 128, nullptr, nullptr, 0, 0);
}

// ---- merged MoE up: shared1 (1024 blocks) + routed1 (32e x 4x x 32y) ----
#define UP_SHARED_BLOCKS 1024
__global__ __launch_bounds__(256, 2) void moe_up(const float* __restrict__ se_w1,
                                                 const float* __restrict__ se_b1,
                                                 const float* __restrict__ W1all,
                                                 const float* __restrict__ b1all) {
    int bid = blockIdx.x;
    if (bid < UP_SHARED_BLOCKS) {
        int xx = bid & 31, yy = bid >> 5;
        tgemm_body<1, 0>(g_h2, se_w1, se_b1, nullptr, g_hs, TOK, SHID, EMB, EMB,
                         yy * 128, xx * 128, nullptr, nullptr, 0, 0);
    } else {
        int r = bid - UP_SHARED_BLOCKS;       // 0..4095
        int e = r >> 7;                       // 32 experts
        int rem = r & 127;
        int xx = rem & 3, yy = rem >> 2;      // 4 x-tiles, 32 y-tiles
        int cnt = g_cnt[e];
        int m0 = yy * 128;
        if (m0 >= cnt) return;
        tgemm_body<0, 1>(g_h2, W1all + (size_t)e * EMB * EHID, b1all + (size_t)e * EHID,
                         nullptr, g_H, TOK, EHID, EMB, EMB,
                         m0, xx * 128, g_atok, nullptr, cnt, g_off[e]);
    }
}

// ---- merged MoE down: shared2 split-K (512 blocks) + routed2 (4096) ----
#define KSPLIT 4
#define KCH (SHID / KSPLIT)
#define DN_SHARED_BLOCKS 512
__global__ __launch_bounds__(256, 2) void moe_down(const float* __restrict__ se_w2,
                                                   const float* __restrict__ W2all,
                                                   const float* __restrict__ b2all,
                                                   float* __restrict__ out) {
    int bid = blockIdx.x;
    if (bid < DN_SHARED_BLOCKS) {
        int kc = bid >> 7;                    // 4 K chunks
        int rem = bid & 127;
        int xx = rem & 3, yy = rem >> 2;
        tgemm_body<0, 3>(g_hs + (size_t)kc * KCH, se_w2 + (size_t)kc * KCH * EMB,
                         nullptr, nullptr, out, TOK, EMB, KCH, SHID,
                         yy * 128, xx * 128, nullptr, nullptr, 0, 0);
    } else {
        int r = bid - DN_SHARED_BLOCKS;
        int e = r >> 7;
        int rem = r & 127;
        int xx = rem & 3, yy = rem >> 2;
        int cnt = g_cnt[e];
        int m0 = yy * 128;
        if (m0 >= cnt) return;
        int off = g_off[e];
        tgemm_body<0, 2>(g_H + (size_t)off * EHID, W2all + (size_t)e * EHID * EMB,
                         b2all + (size_t)e * EMB, nullptr, out, TOK, EMB, EHID, EHID,
                         m0, xx * 128, g_atok, g_aw, cnt, off);
    }
}

#define WOSPLIT 2
#define WOCH (EMB / WOSPLIT)
__global__ __launch_bounds__(256, 2) void wo_splitk(const float* __restrict__ attn,
                                                    const float* __restrict__ wo,
                                                    float* __restrict__ x1) {
    int kc = blockIdx.z;
    tgemm_body<0, 3>(attn + (size_t)kc * WOCH, wo + (size_t)kc * WOCH * EMB,
                     nullptr, nullptr, x1, TOK, EMB, WOCH, EMB,
                     blockIdx.y * 128, blockIdx.x * 128, nullptr, nullptr, 0, 0);
}

__global__ __launch_bounds__(256) void init_add_bias(const float* __restrict__ src,
                                                     const float* __restrict__ bias,
                                                     float* __restrict__ dst) {
    int i = blockIdx.x * 256 + threadIdx.x;
    float4 v = reinterpret_cast<const float4*>(src)[i];
    int col = (i * 4) & (EMB - 1);
    float4 b = *reinterpret_cast<const float4*>(bias + col);
    v.x += b.x; v.y += b.y; v.z += b.z; v.w += b.w;
    reinterpret_cast<float4*>(dst)[i] = v;
}

// ---------------- LayerNorm ----------------
__global__ __launch_bounds__(128) void ln_kernel(const float* __restrict__ X,
                                                 const float* __restrict__ g,
                                                 const float* __restrict__ b,
                                                 float* __restrict__ Y) {
    int t = blockIdx.x;
    int tid = threadIdx.x;
    const float4 v = *reinterpret_cast<const float4*>(X + (size_t)t * EMB + tid * 4);
    float s  = v.x + v.y + v.z + v.w;
    float sq = v.x * v.x + v.y * v.y + v.z * v.z + v.w * v.w;
    for (int o = 16; o > 0; o >>= 1) {
        s  += __shfl_xor_sync(0xffffffff, s, o);
        sq += __shfl_xor_sync(0xffffffff, sq, o);
    }
    __shared__ float ssum[4], ssq[4], stats[2];
    int w = tid >> 5;
    if ((tid & 31) == 0) { ssum[w] = s; ssq[w] = sq; }
    __syncthreads();
    if (tid == 0) {
        float S = ssum[0] + ssum[1] + ssum[2] + ssum[3];
        float Q = ssq[0] + ssq[1] + ssq[2] + ssq[3];
        float mu = S * (1.0f / EMB);
        float var = Q * (1.0f / EMB) - mu * mu;
        stats[0] = mu;
        stats[1] = rsqrtf(var + 1e-5f);
    }
    __syncthreads();
    float mu = stats[0], rs = stats[1];
    int cc = tid * 4;
    float4 gg = *reinterpret_cast<const float4*>(g + cc);
    float4 bb = *reinterpret_cast<const float4*>(b + cc);
    float4 o;
    o.x = (v.x - mu) * rs * gg.x + bb.x;
    o.y = (v.y - mu) * rs * gg.y + bb.y;
    o.z = (v.z - mu) * rs * gg.z + bb.z;
    o.w = (v.w - mu) * rs * gg.w + bb.w;
    *reinterpret_cast<float4*>(Y + (size_t)t * EMB + cc) = o;
}

// ---------------- fp32 SGEMM (router only, small N) ----------------
template <int ACT>
__global__ __launch_bounds__(256) void sgemm(const float* __restrict__ A,
                                             const float* __restrict__ B,
                                             const float* __restrict__ bias,
                                             const float* __restrict__ res,
                                             float* __restrict__ C,
                                             int M, int N, int K) {
    __shared__ float As[8][128];
    __shared__ float Bs[8][128];
    int tid = threadIdx.x;
    int row0 = blockIdx.y * 128, col0 = blockIdx.x * 128;
    int aRow = tid >> 1, aCol = (tid & 1) * 4;
    int bRow = tid >> 5, bCol = (tid & 31) * 4;
    int tr = (tid >> 4) * 8, tc = (tid & 15) * 8;

    float acc[8][8];
#pragma unroll
    for (int i = 0; i < 8; i++)
#pragma unroll
        for (int j = 0; j < 8; j++) acc[i][j] = 0.f;

    const float* Ap = A + (size_t)(row0 + aRow) * K + aCol;
    for (int k0 = 0; k0 < K; k0 += 8) {
        float4 av = *reinterpret_cast<const float4*>(Ap + k0);
        As[aCol + 0][aRow] = av.x;
        As[aCol + 1][aRow] = av.y;
        As[aCol + 2][aRow] = av.z;
        As[aCol + 3][aRow] = av.w;
        int gc = col0 + bCol;
        const float* Bp = B + (size_t)(k0 + bRow) * N + gc;
        float4 bv;
        if (gc + 3 < N) {
            bv = *reinterpret_cast<const float4*>(Bp);
        } else {
            bv.x = (gc + 0 < N) ? Bp[0] : 0.f;
            bv.y = (gc + 1 < N) ? Bp[1] : 0.f;
            bv.z = (gc + 2 < N) ? Bp[2] : 0.f;
            bv.w = (gc + 3 < N) ? Bp[3] : 0.f;
        }
        Bs[bRow][bCol + 0] = bv.x;
        Bs[bRow][bCol + 1] = bv.y;
        Bs[bRow][bCol + 2] = bv.z;
        Bs[bRow][bCol + 3] = bv.w;
        __syncthreads();
#pragma unroll
        for (int k = 0; k < 8; k++) {
            float4 ra0 = *reinterpret_cast<const float4*>(&As[k][tr]);
            float4 ra1 = *reinterpret_cast<const float4*>(&As[k][tr + 4]);
            float4 rb0 = *reinterpret_cast<const float4*>(&Bs[k][tc]);
            float4 rb1 = *reinterpret_cast<const float4*>(&Bs[k][tc + 4]);
            float ra[8] = {ra0.x, ra0.y, ra0.z, ra0.w, ra1.x, ra1.y, ra1.z, ra1.w};
            float rb[8] = {rb0.x, rb0.y, rb0.z, rb0.w, rb1.x, rb1.y, rb1.z, rb1.w};
#pragma unroll
            for (int i = 0; i < 8; i++)
#pragma unroll
                for (int j = 0; j < 8; j++) acc[i][j] += ra[i] * rb[j];
        }
        __syncthreads();
    }
#pragma unroll
    for (int i = 0; i < 8; i++) {
        int gr = row0 + tr + i;
#pragma unroll
        for (int j = 0; j < 8; j++) {
            int gc = col0 + tc + j;
            if (gc < N) {
                float v = acc[i][j];
                if (bias) v += bias[gc];
                if (ACT == 1) v = gelu_tanh(v);
                if (res) v += res[(size_t)gr * N + gc];
                C[(size_t)gr * N + gc] = v;
            }
        }
    }
}

// ---------------- flash attention v6: packed f32x2 FMA ----------
#define QTP 132
#define ATP 68
#define QT_FLOATS (64 * QTP)
#define PS_FLOATS (128 * ATP)
#define VS_FLOATS (64 * ATP)
#define AT_SMEM ((QT_FLOATS + PS_FLOATS + VS_FLOATS) * 4)   // 86016

__global__ __launch_bounds__(256, 2) void attn_kernel() {
    const float* __restrict__ Q = g_q;
    const float* __restrict__ K = g_k;
    const float* __restrict__ V = g_v;
    float* __restrict__ O = g_attn;

    extern __shared__ float dsm[];
    float* Qt = dsm;
    float* Kt = dsm + QT_FLOATS;
    float* Ps = Kt;
    float* Vs = dsm + QT_FLOATS + PS_FLOATS;

    __shared__ float rowm[128], rowl[128];

    int bh = blockIdx.x;
    int qt = blockIdx.y;
    int b = bh >> 3, h = bh & 7;
    const size_t base = (size_t)b * SEQ * EMB + h * HD;
    int tid = threadIdx.x;
    int ti = (tid >> 4) * 8;
    int tj = (tid & 15) * 4;
    bool glead = ((tid & 15) == 0);

    for (int idx = tid; idx < 128 * 16; idx += 256) {
        int r = idx >> 4, c4 = (idx & 15) * 4;
        float4 qv = *reinterpret_cast<const float4*>(Q + base + (size_t)(qt * 128 + r) * EMB + c4);
        Qt[(c4 + 0) * QTP + r] = qv.x;
        Qt[(c4 + 1) * QTP + r] = qv.y;
        Qt[(c4 + 2) * QTP + r] = qv.z;
        Qt[(c4 + 3) * QTP + r] = qv.w;
    }
    if (tid < 128) { rowm[tid] = -1e30f; rowl[tid] = 0.f; }

    u64t o2[8][2];
#pragma unroll
    for (int i = 0; i < 8; i++) { o2[i][0] = 0ull; o2[i][1] = 0ull; }
    __syncthreads();

    for (int kt = 0; kt < SEQ / 64; kt++) {
        for (int idx = tid; idx < 64 * 16; idx += 256) {
            int r = idx >> 4, c4 = (idx & 15) * 4;
            float4 kv = *reinterpret_cast<const float4*>(K + base + (size_t)(kt * 64 + r) * EMB + c4);
            Kt[(c4 + 0) * ATP + r] = kv.x;
            Kt[(c4 + 1) * ATP + r] = kv.y;
            Kt[(c4 + 2) * ATP + r] = kv.z;
            Kt[(c4 + 3) * ATP + r] = kv.w;
            float4 vv = *reinterpret_cast<const float4*>(V + base + (size_t)(kt * 64 + r) * EMB + c4);
            *reinterpret_cast<float4*>(&Vs[r * ATP + c4]) = vv;
        }
        __syncthreads();

        u64t s2[8][2];
#pragma unroll
        for (int i = 0; i < 8; i++) { s2[i][0] = 0ull; s2[i][1] = 0ull; }
#pragma unroll 2
        for (int d = 0; d < 64; d++) {
            float4 qa0 = *reinterpret_cast<const float4*>(&Qt[d * QTP + ti]);
            float4 qa1 = *reinterpret_cast<const float4*>(&Qt[d * QTP + ti + 4]);
            float4 kb = *reinterpret_cast<const float4*>(&Kt[d * ATP + tj]);
            u64t kb01 = pk2(kb.x, kb.y);
            u64t kb23 = pk2(kb.z, kb.w);
            float a[8] = {qa0.x, qa0.y, qa0.z, qa0.w, qa1.x, qa1.y, qa1.z, qa1.w};
#pragma unroll
            for (int i = 0; i < 8; i++) {
                u64t aa = pk2(a[i], a[i]);
                fma2(s2[i][0], aa, kb01);
                fma2(s2[i][1], aa, kb23);
            }
        }
        __syncthreads();

        float fi[8];
#pragma unroll
        for (int i = 0; i < 8; i++) {
            int r = ti + i;
            float s0, s1, s2f, s3;
            upk2(s2[i][0], s0, s1);
            upk2(s2[i][1], s2f, s3);
            float mloc = fmaxf(fmaxf(s0, s1), fmaxf(s2f, s3)) * 0.125f;
#pragma unroll
            for (int off = 8; off > 0; off >>= 1)
                mloc = fmaxf(mloc, __shfl_xor_sync(0xffffffff, mloc, off));
            float mo = rowm[r];
            float mx = fmaxf(mloc, mo);
            float4 p;
            p.x = __expf(s0 * 0.125f - mx);
            p.y = __expf(s1 * 0.125f - mx);
            p.z = __expf(s2f * 0.125f - mx);
            p.w = __expf(s3 * 0.125f - mx);
            float sm = p.x + p.y + p.z + p.w;
#pragma unroll
            for (int off = 8; off > 0; off >>= 1)
                sm += __shfl_xor_sync(0xffffffff, sm, off);
            *reinterpret_cast<float4*>(&Ps[r * ATP + tj]) = p;
            float f = __expf(mo - mx);
            fi[i] = f;
            if (glead) {
                rowl[r] = rowl[r] * f + sm;
                rowm[r] = mx;
            }
        }
        __syncthreads();

#pragma unroll
        for (int i = 0; i < 8; i++) {
            u64t ff = pk2(fi[i], fi[i]);
            mul2(o2[i][0], ff);
            mul2(o2[i][1], ff);
        }
        for (int t4 = 0; t4 < 64; t4 += 4) {
            float4 p4[8];
#pragma unroll
            for (int i = 0; i < 8; i++)
                p4[i] = *reinterpret_cast<const float4*>(&Ps[(ti + i) * ATP + t4]);
#pragma unroll
            for (int j4 = 0; j4 < 4; j4++) {
                float4 vb = *reinterpret_cast<const float4*>(&Vs[(t4 + j4) * ATP + tj]);
                u64t vb01 = pk2(vb.x, vb.y);
                u64t vb23 = pk2(vb.z, vb.w);
#pragma unroll
                for (int i = 0; i < 8; i++) {
                    float pj = j4 == 0 ? p4[i].x : j4 == 1 ? p4[i].y : j4 == 2 ? p4[i].z : p4[i].w;
                    u64t pp = pk2(pj, pj);
                    fma2(o2[i][0], pp, vb01);
                    fma2(o2[i][1], pp, vb23);
                }
            }
        }
        __syncthreads();
    }
#pragma unroll
    for (int i = 0; i < 8; i++) {
        float inv = 1.0f / rowl[ti + i];
        float o0, o1, o2f, o3;
        upk2(o2[i][0], o0, o1);
        upk2(o2[i][1], o2f, o3);
        float* dst = O + base + (size_t)(qt * 128 + ti + i) * EMB + tj;
        dst[0] = o0 * inv;
        dst[1] = o1 * inv;
        dst[2] = o2f * inv;
        dst[3] = o3 * inv;
    }
}

// ---------------- router: softmax + top-4 + stats ----------------
__global__ __launch_bounds__(128) void router_topk_kernel() {
    const float* __restrict__ logits = g_logits;
    __shared__ float s_imp[NEXP];
    __shared__ int s_cnt[NEXP];
    int tid = threadIdx.x;
    if (tid < NEXP) { s_imp[tid] = 0.f; s_cnt[tid] = 0; }
    __syncthreads();
    int t = blockIdx.x * 128 + tid;
    float p[NEXP];
    float mx = -1e30f;
#pragma unroll
    for (int e = 0; e < NEXP; e++) {
        p[e] = logits[(size_t)t * NEXP + e];
        mx = fmaxf(mx, p[e]);
    }
    float sum = 0.f;
#pragma unroll
    for (int e = 0; e < NEXP; e++) { p[e] = __expf(p[e] - mx); sum += p[e]; }
    float inv = 1.f / sum;
#pragma unroll
    for (int e = 0; e < NEXP; e++) {
        p[e] *= inv;
        atomicAdd(&s_imp[e], p[e]);
    }
    int idx[TOPK];
    float w[TOPK];
    float tot = 0.f;
#pragma unroll
    for (int k = 0; k < TOPK; k++) {
        float best = -1.f;
        int bi = 0;
#pragma unroll
        for (int e = 0; e < NEXP; e++)
            if (p[e] > best) { best = p[e]; bi = e; }
        idx[k] = bi;
        w[k] = best;
        tot += best;
        p[bi] = -1.f;
        atomicAdd(&s_cnt[bi], 1);
    }
    float it = 1.f / tot;
#pragma unroll
    for (int k = 0; k < TOPK; k++) {
        g_topi[t * TOPK + k] = idx[k];
        g_topw[t * TOPK + k] = w[k] * it;
    }
    __syncthreads();
    if (tid < NEXP) {
        atomicAdd(&g_imp[tid], s_imp[tid]);
        atomicAdd(&g_cnt[tid], s_cnt[tid]);
    }
}

// ---------------- prefix scan + aux loss ----------------
__global__ void scan_aux_kernel(float* __restrict__ out, int out_size) {
    if (threadIdx.x == 0) {
        int acc = 0;
        float aux = 0.f;
        for (int e = 0; e < NEXP; e++) {
            g_off[e] = acc;
            acc += g_cnt[e];
            aux += g_imp[e] * (float)g_cnt[e];
        }
        aux *= (float)NEXP / ((float)TOK * (float)TOK);
        if (out_size > TOK * EMB) out[TOK * EMB] = aux;
    }
}

// ---------------- fill per-expert assignment lists ----------------
__global__ __launch_bounds__(128) void fill_assign_kernel() {
    int t = blockIdx.x * 128 + threadIdx.x;
#pragma unroll
    for (int k = 0; k < TOPK; k++) {
        int e = g_topi[t * TOPK + k];
        int pos = atomicAdd(&g_cur[e], 1);
        int gidx = g_off[e] + pos;
        g_atok[gidx] = t;
        g_aw[gidx] = g_topw[t * TOPK + k];
    }
}

__global__ void zero_small_kernel() {
    int i = threadIdx.x;
    if (i < NEXP) { g_imp[i] = 0.f; g_cnt[i] = 0; g_cur[i] = 0; }
}

// ---------------- launch ----------------
extern "C" void kernel_launch(void* const* d_in, const int* in_sizes, int n_in,
                              void* d_out, int out_size) {
    const float* x        = (const float*)d_in[0];
    const float* ln1_g    = (const float*)d_in[1];
    const float* ln1_b    = (const float*)d_in[2];
    const float* wq       = (const float*)d_in[3];
    const float* bq       = (const float*)d_in[4];
    const float* wk       = (const float*)d_in[5];
    const float* bk       = (const float*)d_in[6];
    const float* wv       = (const float*)d_in[7];
    const float* bv       = (const float*)d_in[8];
    const float* wo       = (const float*)d_in[9];
    const float* bo       = (const float*)d_in[10];
    const float* ln2_g    = (const float*)d_in[11];
    const float* ln2_b    = (const float*)d_in[12];
    const float* router_a = (const float*)d_in[13];
    const float* router_b = (const float*)d_in[14];
    const float* re_w1    = (const float*)d_in[15];
    const float* re_b1    = (const float*)d_in[16];
    const float* re_w2    = (const float*)d_in[17];
    const float* re_b2    = (const float*)d_in[18];
    const float* se_w1    = (const float*)d_in[19];
    const float* se_b1    = (const float*)d_in[20];
    const float* se_w2    = (const float*)d_in[21];
    const float* se_b2    = (const float*)d_in[22];
    float* out = (float*)d_out;

    float *p_h1, *p_attn, *p_x1, *p_h2, *p_rlat, *p_logits;
    cudaGetSymbolAddress((void**)&p_h1, g_h1);
    cudaGetSymbolAddress((void**)&p_attn, g_attn);
    cudaGetSymbolAddress((void**)&p_x1, g_x1);
    cudaGetSymbolAddress((void**)&p_h2, g_h2);
    cudaGetSymbolAddress((void**)&p_rlat, g_rlat);
    cudaGetSymbolAddress((void**)&p_logits, g_logits);

    cudaFuncSetAttribute(qkv_tgemm, cudaFuncAttributeMaxDynamicSharedMemorySize, TG_SMEM);
    cudaFuncSetAttribute(moe_up, cudaFuncAttributeMaxDynamicSharedMemorySize, TG_SMEM);
    cudaFuncSetAttribute(moe_down, cudaFuncAttributeMaxDynamicSharedMemorySize, TG_SMEM);
    cudaFuncSetAttribute(wo_splitk, cudaFuncAttributeMaxDynamicSharedMemorySize, TG_SMEM);
    cudaFuncSetAttribute(attn_kernel, cudaFuncAttributeMaxDynamicSharedMemorySize, AT_SMEM);

    zero_small_kernel<<<1, 32>>>();
    ln_kernel<<<TOK, 128>>>(x, ln1_g, ln1_b, p_h1);

    qkv_tgemm<<<dim3(4, 32, 3), 256, TG_SMEM>>>(p_h1, wq, wk, wv, bq, bk, bv);

    attn_kernel<<<dim3(32, 8), 256, AT_SMEM>>>();

    init_add_bias<<<(TOK * EMB / 4) / 256, 256>>>(x, bo, p_x1);
    wo_splitk<<<dim3(4, 32, WOSPLIT), 256, TG_SMEM>>>(p_attn, wo, p_x1);

    ln_kernel<<<TOK, 128>>>(p_x1, ln2_g, ln2_b, p_h2);

    sgemm<0><<<dim3(1, 32), 256>>>(p_h2, router_a, nullptr, nullptr, p_rlat, TOK, RRANK, EMB);
    sgemm<0><<<dim3(1, 32), 256>>>(p_rlat, router_b, nullptr, nullptr, p_logits, TOK, NEXP, RRANK);
    router_topk_kernel<<<TOK / 128, 128>>>();
    scan_aux_kernel<<<1, 32>>>(out, out_size);
    fill_assign_kernel<<<TOK / 128, 128>>>();

    // merged MoE up: shared expert GEMM1 + routed GEMM1 in one grid
    moe_up<<<UP_SHARED_BLOCKS + NEXP * 128, 256, TG_SMEM>>>(se_w1, se_b1, re_w1, re_b1);

    // out = x1 + se_b2, then merged down: shared2 split-K + routed2 (both atomic)
    init_add_bias<<<(TOK * EMB / 4) / 256, 256>>>(p_x1, se_b2, out);
    moe_down<<<DN_SHARED_BLOCKS + NEXP * 128, 256, TG_SMEM>>>(se_w2, re_w2, re_b2, out);
}

// round 16
// speedup vs baseline: 1.3643x; 1.0385x over previous
#include <cuda_runtime.h>
#include <math.h>

// ---------------- problem constants ----------------
#define TOK   4096          // B*S = 4*1024
#define SEQ   1024
#define BATCH 4
#define EMB   512
#define NH    8
#define HD    64
#define NEXP  32
#define TOPK  4
#define RRANK 64
#define SHID  4096
#define EHID  512

// ---------------- device scratch (static, allocation-free) ----------------
__device__ float g_h1[TOK * EMB];
__device__ float g_q[TOK * EMB];
__device__ float g_k[TOK * EMB];
__device__ float g_v[TOK * EMB];
__device__ float g_attn[TOK * EMB];
__device__ float g_x1[TOK * EMB];
__device__ float g_h2[TOK * EMB];
__device__ int   g_topi[TOK * TOPK];
__device__ float g_topw[TOK * TOPK];
__device__ float g_imp[NEXP];
__device__ int   g_cnt[NEXP];
__device__ int   g_off[NEXP];
__device__ int   g_cur[NEXP];
__device__ int   g_atok[TOK * TOPK];
__device__ float g_aw[TOK * TOPK];
__device__ float g_H[TOK * TOPK * EHID];   // routed hidden
__device__ float g_hs[TOK * SHID];         // shared-expert hidden

// ---------------- helpers ----------------
__device__ __forceinline__ float gelu_tanh(float x) {
    float x3 = x * x * x;
    return 0.5f * x * (1.0f + tanhf(0.7978845608028654f * (x + 0.044715f * x3)));
}

__device__ __forceinline__ unsigned f2tf32(float f) {
    unsigned r;
    asm("cvt.rna.tf32.f32 %0, %1;" : "=r"(r) : "f"(f));
    return r;
}

// hi = rna-rounded tf32; lo = raw residual (tf32 HW reads only upper bits).
__device__ __forceinline__ void tf32_split(float f, unsigned& hi, unsigned& lo) {
    hi = f2tf32(f);
    lo = __float_as_uint(f - __uint_as_float(hi));
}

__device__ __forceinline__ void mma_tf32(float& c0, float& c1, float& c2, float& c3,
                                         unsigned a0, unsigned a1, unsigned a2, unsigned a3,
                                         unsigned b0, unsigned b1) {
    asm volatile(
        "mma.sync.aligned.m16n8k8.row.col.f32.tf32.tf32.f32 "
        "{%0,%1,%2,%3}, {%4,%5,%6,%7}, {%8,%9}, {%0,%1,%2,%3};"
        : "+f"(c0), "+f"(c1), "+f"(c2), "+f"(c3)
        : "r"(a0), "r"(a1), "r"(a2), "r"(a3), "r"(b0), "r"(b1));
}

__device__ __forceinline__ void cp16(float* s, const float* g) {
    unsigned sa = (unsigned)__cvta_generic_to_shared(s);
    asm volatile("cp.async.cg.shared.global [%0], [%1], 16;" :: "r"(sa), "l"(g));
}
__device__ __forceinline__ void cp_commit() {
    asm volatile("cp.async.commit_group;");
}

// ---------------- packed f32x2 helpers (sm_100a) ----------------
typedef unsigned long long u64t;
__device__ __forceinline__ u64t pk2(float lo, float hi) {
    u64t r;
    asm("mov.b64 %0, {%1, %2};" : "=l"(r) : "f"(lo), "f"(hi));
    return r;
}
__device__ __forceinline__ void upk2(u64t v, float& lo, float& hi) {
    asm("mov.b64 {%0, %1}, %2;" : "=f"(lo), "=f"(hi) : "l"(v));
}
__device__ __forceinline__ void fma2(u64t& acc, u64t a, u64t b) {
    asm("fma.rn.f32x2 %0, %1, %2, %0;" : "+l"(acc) : "l"(a), "l"(b));
}
__device__ __forceinline__ void mul2(u64t& acc, u64t f) {
    asm("mul.rn.f32x2 %0, %1, %2;" : "+l"(acc) : "l"(acc), "l"(f));
}

// ================= 3xTF32 tensor-core GEMM, cp.async double-buffered ============
#define APAD 36
#define BPAD 136
#define ASZ (128 * APAD)
#define BSZ (32 * BPAD)
#define TG_SMEM ((2 * ASZ + 2 * BSZ) * 4)   // 71680 bytes

// EPI 0: plain store; EPI 1: gelu scatter (A gathered); EPI 2: atomic token
// scatter (A local); EPI 3: plain atomicAdd (split-K).
template <int ACT, int EPI>
__device__ __forceinline__ void tgemm_body(
    const float* __restrict__ A, const float* __restrict__ B,
    const float* __restrict__ bias, const float* __restrict__ res,
    float* __restrict__ C, int M, int N, int K, int Kstride,
    int row0, int col0,
    const int* __restrict__ atok, const float* __restrict__ aw,
    int cnt, int off) {

    extern __shared__ float dsm[];
    float* As = dsm;
    float* Bs = dsm + 2 * ASZ;

    int tid = threadIdx.x;
    int warp = tid >> 5, lane = tid & 31;
    int wm = warp >> 2, wn = warp & 3;
    int g = lane >> 2, t = lane & 3;

    int arow = tid >> 1, acb = (tid & 1) * 16;
    int brow = tid >> 3, bcb = (tid & 7) * 16;

    int asrc;
    if (EPI == 1) {
        int m = row0 + arow;
        asrc = (m < cnt) ? atok[off + m] : 0;
    } else if (EPI == 2) {
        int m = row0 + arow;
        asrc = (m < cnt) ? m : 0;
    } else {
        asrc = row0 + arow;
    }

    const float* Asrc = A + (size_t)asrc * Kstride + acb;
    const float* Bsrc = B + (size_t)brow * N + col0 + bcb;

    float c[4][4][4];
#pragma unroll
    for (int i = 0; i < 4; i++)
#pragma unroll
        for (int j = 0; j < 4; j++) { c[i][j][0] = c[i][j][1] = c[i][j][2] = c[i][j][3] = 0.f; }

    int NS = K / 32;
    {
        float* da = As + arow * APAD + acb;
        float* db = Bs + brow * BPAD + bcb;
#pragma unroll
        for (int i = 0; i < 4; i++) cp16(da + i * 4, Asrc + i * 4);
#pragma unroll
        for (int i = 0; i < 4; i++) cp16(db + i * 4, Bsrc + i * 4);
        cp_commit();
    }

    for (int s = 0; s < NS; s++) {
        if (s + 1 < NS) {
            int buf = (s + 1) & 1;
            int k0 = (s + 1) * 32;
            float* da = As + buf * ASZ + arow * APAD + acb;
            float* db = Bs + buf * BSZ + brow * BPAD + bcb;
#pragma unroll
            for (int i = 0; i < 4; i++) cp16(da + i * 4, Asrc + k0 + i * 4);
#pragma unroll
            for (int i = 0; i < 4; i++) cp16(db + i * 4, Bsrc + (size_t)k0 * N + i * 4);
            cp_commit();
            asm volatile("cp.async.wait_group 1;");
        } else {
            asm volatile("cp.async.wait_group 0;");
        }
        __syncthreads();

        const float* Ab = As + (s & 1) * ASZ;
        const float* Bb = Bs + (s & 1) * BSZ;
#pragma unroll
        for (int kk = 0; kk < 4; kk++) {
            int kb = kk * 8;
            unsigned ah[4][4], al[4][4], bh[4][2], bl[4][2];
#pragma unroll
            for (int mt = 0; mt < 4; mt++) {
                int mb = wm * 64 + mt * 16;
                int i0 = (mb + g) * APAD + kb + t;
                int i1 = (mb + g + 8) * APAD + kb + t;
                tf32_split(Ab[i0],     ah[mt][0], al[mt][0]);
                tf32_split(Ab[i1],     ah[mt][1], al[mt][1]);
                tf32_split(Ab[i0 + 4], ah[mt][2], al[mt][2]);
                tf32_split(Ab[i1 + 4], ah[mt][3], al[mt][3]);
            }
#pragma unroll
            for (int nt = 0; nt < 4; nt++) {
                int nb = wn * 32 + nt * 8;
                tf32_split(Bb[(kb + t) * BPAD + nb + g],     bh[nt][0], bl[nt][0]);
                tf32_split(Bb[(kb + t + 4) * BPAD + nb + g], bh[nt][1], bl[nt][1]);
            }
#pragma unroll
            for (int mt = 0; mt < 4; mt++)
#pragma unroll
                for (int nt = 0; nt < 4; nt++) {
                    mma_tf32(c[mt][nt][0], c[mt][nt][1], c[mt][nt][2], c[mt][nt][3],
                             al[mt][0], al[mt][1], al[mt][2], al[mt][3],
                             bh[nt][0], bh[nt][1]);
                    mma_tf32(c[mt][nt][0], c[mt][nt][1], c[mt][nt][2], c[mt][nt][3],
                             ah[mt][0], ah[mt][1], ah[mt][2], ah[mt][3],
                             bl[nt][0], bl[nt][1]);
                    mma_tf32(c[mt][nt][0], c[mt][nt][1], c[mt][nt][2], c[mt][nt][3],
                             ah[mt][0], ah[mt][1], ah[mt][2], ah[mt][3],
                             bh[nt][0], bh[nt][1]);
                }
        }
        __syncthreads();
    }

#pragma unroll
    for (int mt = 0; mt < 4; mt++) {
        int mb = row0 + wm * 64 + mt * 16;
#pragma unroll
        for (int nt = 0; nt < 4; nt++) {
            int nb = col0 + wn * 32 + nt * 8 + 2 * t;
#pragma unroll
            for (int half = 0; half < 2; half++) {
                int r = mb + g + half * 8;
                float v0 = c[mt][nt][half * 2 + 0];
                float v1 = c[mt][nt][half * 2 + 1];
                if (EPI == 0) {
                    if (bias) { v0 += bias[nb]; v1 += bias[nb + 1]; }
                    if (ACT == 1) { v0 = gelu_tanh(v0); v1 = gelu_tanh(v1); }
                    if (res) {
                        v0 += res[(size_t)r * N + nb];
                        v1 += res[(size_t)r * N + nb + 1];
                    }
                    C[(size_t)r * N + nb] = v0;
                    C[(size_t)r * N + nb + 1] = v1;
                } else if (EPI == 1) {
                    if (r < cnt) {
                        C[(size_t)(off + r) * N + nb] = gelu_tanh(v0 + bias[nb]);
                        C[(size_t)(off + r) * N + nb + 1] = gelu_tanh(v1 + bias[nb + 1]);
                    }
                } else if (EPI == 2) {
                    if (r < cnt) {
                        int tok = atok[off + r];
                        float wgt = aw[off + r];
                        atomicAdd(&C[(size_t)tok * N + nb], (v0 + bias[nb]) * wgt);
                        atomicAdd(&C[(size_t)tok * N + nb + 1], (v1 + bias[nb + 1]) * wgt);
                    }
                } else {
                    atomicAdd(&C[(size_t)r * N + nb], v0);
                    atomicAdd(&C[(size_t)r * N + nb + 1], v1);
                }
            }
        }
    }
}

__global__ __launch_bounds__(256, 2) void qkv_tgemm(const float* __restrict__ A,
                                                    const float* __restrict__ wq,
                                                    const float* __restrict__ wk,
                                                    const float* __restrict__ wv,
                                                    const float* __restrict__ bq,
                                                    const float* __restrict__ bk,
                                                    const float* __restrict__ bv) {
    int z = blockIdx.z;
    const float* W = (z == 0) ? wq : (z == 1) ? wk : wv;
    const float* bias = (z == 0) ? bq : (z == 1) ? bk : bv;
    float* C = (z == 0) ? g_q : (z == 1) ? g_k : g_v;
    tgemm_body<0, 0>(A, W, bias, nullptr, C, TOK, EMB, EMB, EMB,
                     blockIdx.y * 128, blockIdx.x * 128, nullptr, nullptr, 0, 0);
}

// ---- merged MoE up: shared1 (1024 blocks) + routed1 (32e x 4x x 32y) ----
#define UP_SHARED_BLOCKS 1024
__global__ __launch_bounds__(256, 2) void moe_up(const float* __restrict__ se_w1,
                                                 const float* __restrict__ se_b1,
                                                 const float* __restrict__ W1all,
                                                 const float* __restrict__ b1all) {
    int bid = blockIdx.x;
    if (bid < UP_SHARED_BLOCKS) {
        int xx = bid & 31, yy = bid >> 5;
        tgemm_body<1, 0>(g_h2, se_w1, se_b1, nullptr, g_hs, TOK, SHID, EMB, EMB,
                         yy * 128, xx * 128, nullptr, nullptr, 0, 0);
    } else {
        int r = bid - UP_SHARED_BLOCKS;
        int e = r >> 7;
        int rem = r & 127;
        int xx = rem & 3, yy = rem >> 2;
        int cnt = g_cnt[e];
        int m0 = yy * 128;
        if (m0 >= cnt) return;
        tgemm_body<0, 1>(g_h2, W1all + (size_t)e * EMB * EHID, b1all + (size_t)e * EHID,
                         nullptr, g_H, TOK, EHID, EMB, EMB,
                         m0, xx * 128, g_atok, nullptr, cnt, g_off[e]);
    }
}

// ---- merged MoE down: shared2 split-K (512 blocks) + routed2 (4096) ----
#define KSPLIT 4
#define KCH (SHID / KSPLIT)
#define DN_SHARED_BLOCKS 512
__global__ __launch_bounds__(256, 2) void moe_down(const float* __restrict__ se_w2,
                                                   const float* __restrict__ W2all,
                                                   const float* __restrict__ b2all,
                                                   float* __restrict__ out) {
    int bid = blockIdx.x;
    if (bid < DN_SHARED_BLOCKS) {
        int kc = bid >> 7;
        int rem = bid & 127;
        int xx = rem & 3, yy = rem >> 2;
        tgemm_body<0, 3>(g_hs + (size_t)kc * KCH, se_w2 + (size_t)kc * KCH * EMB,
                         nullptr, nullptr, out, TOK, EMB, KCH, SHID,
                         yy * 128, xx * 128, nullptr, nullptr, 0, 0);
    } else {
        int r = bid - DN_SHARED_BLOCKS;
        int e = r >> 7;
        int rem = r & 127;
        int xx = rem & 3, yy = rem >> 2;
        int cnt = g_cnt[e];
        int m0 = yy * 128;
        if (m0 >= cnt) return;
        int off = g_off[e];
        tgemm_body<0, 2>(g_H + (size_t)off * EHID, W2all + (size_t)e * EHID * EMB,
                         b2all + (size_t)e * EMB, nullptr, out, TOK, EMB, EHID, EHID,
                         m0, xx * 128, g_atok, g_aw, cnt, off);
    }
}

#define WOSPLIT 2
#define WOCH (EMB / WOSPLIT)
__global__ __launch_bounds__(256, 2) void wo_splitk(const float* __restrict__ attn,
                                                    const float* __restrict__ wo,
                                                    float* __restrict__ x1) {
    int kc = blockIdx.z;
    tgemm_body<0, 3>(attn + (size_t)kc * WOCH, wo + (size_t)kc * WOCH * EMB,
                     nullptr, nullptr, x1, TOK, EMB, WOCH, EMB,
                     blockIdx.y * 128, blockIdx.x * 128, nullptr, nullptr, 0, 0);
}

__global__ __launch_bounds__(256) void init_add_bias(const float* __restrict__ src,
                                                     const float* __restrict__ bias,
                                                     float* __restrict__ dst) {
    int i = blockIdx.x * 256 + threadIdx.x;
    float4 v = reinterpret_cast<const float4*>(src)[i];
    int col = (i * 4) & (EMB - 1);
    float4 b = *reinterpret_cast<const float4*>(bias + col);
    v.x += b.x; v.y += b.y; v.z += b.z; v.w += b.w;
    reinterpret_cast<float4*>(dst)[i] = v;
}

// ---------------- LayerNorm ----------------
__global__ __launch_bounds__(128) void ln_kernel(const float* __restrict__ X,
                                                 const float* __restrict__ g,
                                                 const float* __restrict__ b,
                                                 float* __restrict__ Y) {
    int t = blockIdx.x;
    int tid = threadIdx.x;
    const float4 v = *reinterpret_cast<const float4*>(X + (size_t)t * EMB + tid * 4);
    float s  = v.x + v.y + v.z + v.w;
    float sq = v.x * v.x + v.y * v.y + v.z * v.z + v.w * v.w;
    for (int o = 16; o > 0; o >>= 1) {
        s  += __shfl_xor_sync(0xffffffff, s, o);
        sq += __shfl_xor_sync(0xffffffff, sq, o);
    }
    __shared__ float ssum[4], ssq[4], stats[2];
    int w = tid >> 5;
    if ((tid & 31) == 0) { ssum[w] = s; ssq[w] = sq; }
    __syncthreads();
    if (tid == 0) {
        float S = ssum[0] + ssum[1] + ssum[2] + ssum[3];
        float Q = ssq[0] + ssq[1] + ssq[2] + ssq[3];
        float mu = S * (1.0f / EMB);
        float var = Q * (1.0f / EMB) - mu * mu;
        stats[0] = mu;
        stats[1] = rsqrtf(var + 1e-5f);
    }
    __syncthreads();
    float mu = stats[0], rs = stats[1];
    int cc = tid * 4;
    float4 gg = *reinterpret_cast<const float4*>(g + cc);
    float4 bb = *reinterpret_cast<const float4*>(b + cc);
    float4 o;
    o.x = (v.x - mu) * rs * gg.x + bb.x;
    o.y = (v.y - mu) * rs * gg.y + bb.y;
    o.z = (v.z - mu) * rs * gg.z + bb.z;
    o.w = (v.w - mu) * rs * gg.w + bb.w;
    *reinterpret_cast<float4*>(Y + (size_t)t * EMB + cc) = o;
}

// ---------------- fused low-rank router: rlat + logits + softmax + top-4 ----------
// 32 blocks x 128 tokens. Phase 1: rlat[128x64] = h2 @ ra (K=512) via smem tiles.
// Phase 2: logits[128x32] = rlat @ rb (K=64). Phase 3: per-token softmax/top-4
// + importance/count stats. Dynamic smem layout (floats):
//   As 8x128=1024 | Bs 8x64=512 | rlat 128x64=8192 | B2 64x32=2048 | log 128x33=4224
#define RF_AS    0
#define RF_BS    (RF_AS + 1024)
#define RF_RLAT  (RF_BS + 512)
#define RF_B2    (RF_RLAT + 128 * 64)
#define RF_LOG   (RF_B2 + 64 * 32)
#define RF_SMEM  ((RF_LOG + 128 * 33) * 4)   // 63.5 KB

__global__ __launch_bounds__(256) void router_fused(const float* __restrict__ ra,
                                                    const float* __restrict__ rb) {
    extern __shared__ float sm[];
    float* As = sm + RF_AS;        // [8 k][128 row]
    float* Bs = sm + RF_BS;        // [8 k][64 col]
    float* rl = sm + RF_RLAT;      // [128 row][64]
    float* B2 = sm + RF_B2;        // [64 k][32 e]
    float* lg = sm + RF_LOG;       // [128 row][33]
    __shared__ float s_imp[NEXP];
    __shared__ int s_cnt[NEXP];

    int tid = threadIdx.x;
    int row0 = blockIdx.x * 128;
    if (tid < NEXP) { s_imp[tid] = 0.f; s_cnt[tid] = 0; }

    // B2 load (64x32 = 2048 floats, 8 per thread)
    for (int i = tid; i < 64 * 32; i += 256) B2[i] = rb[i];

    // phase 1: rlat = h2[row0..row0+128] @ ra  (BM=128, BN=64, BK=8)
    int aRow = tid >> 1, aCol = (tid & 1) * 4;        // A loads
    int bRow = tid >> 5, bCol = (tid & 31) * 2;       // B loads (float2)
    int tr = (tid >> 4) * 8, tc = (tid & 15) * 4;     // compute tile 8x4

    float acc[8][4];
#pragma unroll
    for (int i = 0; i < 8; i++)
#pragma unroll
        for (int j = 0; j < 4; j++) acc[i][j] = 0.f;

    const float* Ap = g_h2 + (size_t)(row0 + aRow) * EMB + aCol;
    for (int k0 = 0; k0 < EMB; k0 += 8) {
        float4 av = *reinterpret_cast<const float4*>(Ap + k0);
        As[(aCol + 0) * 128 + aRow] = av.x;
        As[(aCol + 1) * 128 + aRow] = av.y;
        As[(aCol + 2) * 128 + aRow] = av.z;
        As[(aCol + 3) * 128 + aRow] = av.w;
        float2 bv = *reinterpret_cast<const float2*>(ra + (size_t)(k0 + bRow) * RRANK + bCol);
        Bs[bRow * 64 + bCol] = bv.x;
        Bs[bRow * 64 + bCol + 1] = bv.y;
        __syncthreads();
#pragma unroll
        for (int k = 0; k < 8; k++) {
            float ra8[8], rb4[4];
#pragma unroll
            for (int i = 0; i < 8; i++) ra8[i] = As[k * 128 + tr + i];
#pragma unroll
            for (int j = 0; j < 4; j++) rb4[j] = Bs[k * 64 + tc + j];
#pragma unroll
            for (int i = 0; i < 8; i++)
#pragma unroll
                for (int j = 0; j < 4; j++) acc[i][j] += ra8[i] * rb4[j];
        }
        __syncthreads();
    }
#pragma unroll
    for (int i = 0; i < 8; i++)
#pragma unroll
        for (int j = 0; j < 4; j++) rl[(tr + i) * 64 + tc + j] = acc[i][j];
    __syncthreads();

    // phase 2: logits = rlat @ B2 (K=64); each thread: 1 row, 16 experts
    {
        int row = tid >> 1;
        int c0 = (tid & 1) * 16;
        float lacc[16];
#pragma unroll
        for (int c = 0; c < 16; c++) lacc[c] = 0.f;
        for (int k = 0; k < 64; k++) {
            float rv = rl[row * 64 + k];
#pragma unroll
            for (int c = 0; c < 16; c++) lacc[c] += rv * B2[k * 32 + c0 + c];
        }
#pragma unroll
        for (int c = 0; c < 16; c++) lg[row * 33 + c0 + c] = lacc[c];
    }
    __syncthreads();

    // phase 3: softmax + top-4 + stats (one thread per token, tid<128)
    if (tid < 128) {
        int t = row0 + tid;
        float p[NEXP];
        float mx = -1e30f;
#pragma unroll
        for (int e = 0; e < NEXP; e++) {
            p[e] = lg[tid * 33 + e];
            mx = fmaxf(mx, p[e]);
        }
        float sum = 0.f;
#pragma unroll
        for (int e = 0; e < NEXP; e++) { p[e] = __expf(p[e] - mx); sum += p[e]; }
        float inv = 1.f / sum;
#pragma unroll
        for (int e = 0; e < NEXP; e++) {
            p[e] *= inv;
            atomicAdd(&s_imp[e], p[e]);
        }
        int idx[TOPK];
        float w[TOPK];
        float tot = 0.f;
#pragma unroll
        for (int k = 0; k < TOPK; k++) {
            float best = -1.f;
            int bi = 0;
#pragma unroll
            for (int e = 0; e < NEXP; e++)
                if (p[e] > best) { best = p[e]; bi = e; }
            idx[k] = bi;
            w[k] = best;
            tot += best;
            p[bi] = -1.f;
            atomicAdd(&s_cnt[bi], 1);
        }
        float it = 1.f / tot;
#pragma unroll
        for (int k = 0; k < TOPK; k++) {
            g_topi[t * TOPK + k] = idx[k];
            g_topw[t * TOPK + k] = w[k] * it;
        }
    }
    __syncthreads();
    if (tid < NEXP) {
        atomicAdd(&g_imp[tid], s_imp[tid]);
        atomicAdd(&g_cnt[tid], s_cnt[tid]);
    }
}

// ---------------- flash attention v6: packed f32x2 FMA ----------
#define QTP 132
#define ATP 68
#define QT_FLOATS (64 * QTP)
#define PS_FLOATS (128 * ATP)
#define VS_FLOATS (64 * ATP)
#define AT_SMEM ((QT_FLOATS + PS_FLOATS + VS_FLOATS) * 4)   // 86016

__global__ __launch_bounds__(256, 2) void attn_kernel() {
    const float* __restrict__ Q = g_q;
    const float* __restrict__ K = g_k;
    const float* __restrict__ V = g_v;
    float* __restrict__ O = g_attn;

    extern __shared__ float dsm[];
    float* Qt = dsm;
    float* Kt = dsm + QT_FLOATS;
    float* Ps = Kt;
    float* Vs = dsm + QT_FLOATS + PS_FLOATS;

    __shared__ float rowm[128], rowl[128];

    int bh = blockIdx.x;
    int qt = blockIdx.y;
    int b = bh >> 3, h = bh & 7;
    const size_t base = (size_t)b * SEQ * EMB + h * HD;
    int tid = threadIdx.x;
    int ti = (tid >> 4) * 8;
    int tj = (tid & 15) * 4;
    bool glead = ((tid & 15) == 0);

    for (int idx = tid; idx < 128 * 16; idx += 256) {
        int r = idx >> 4, c4 = (idx & 15) * 4;
        float4 qv = *reinterpret_cast<const float4*>(Q + base + (size_t)(qt * 128 + r) * EMB + c4);
        Qt[(c4 + 0) * QTP + r] = qv.x;
        Qt[(c4 + 1) * QTP + r] = qv.y;
        Qt[(c4 + 2) * QTP + r] = qv.z;
        Qt[(c4 + 3) * QTP + r] = qv.w;
    }
    if (tid < 128) { rowm[tid] = -1e30f; rowl[tid] = 0.f; }

    u64t o2[8][2];
#pragma unroll
    for (int i = 0; i < 8; i++) { o2[i][0] = 0ull; o2[i][1] = 0ull; }
    __syncthreads();

    for (int kt = 0; kt < SEQ / 64; kt++) {
        for (int idx = tid; idx < 64 * 16; idx += 256) {
            int r = idx >> 4, c4 = (idx & 15) * 4;
            float4 kv = *reinterpret_cast<const float4*>(K + base + (size_t)(kt * 64 + r) * EMB + c4);
            Kt[(c4 + 0) * ATP + r] = kv.x;
            Kt[(c4 + 1) * ATP + r] = kv.y;
            Kt[(c4 + 2) * ATP + r] = kv.z;
            Kt[(c4 + 3) * ATP + r] = kv.w;
            float4 vv = *reinterpret_cast<const float4*>(V + base + (size_t)(kt * 64 + r) * EMB + c4);
            *reinterpret_cast<float4*>(&Vs[r * ATP + c4]) = vv;
        }
        __syncthreads();

        u64t s2[8][2];
#pragma unroll
        for (int i = 0; i < 8; i++) { s2[i][0] = 0ull; s2[i][1] = 0ull; }
        for (int d = 0; d < 64; d++) {
            float4 qa0 = *reinterpret_cast<const float4*>(&Qt[d * QTP + ti]);
            float4 qa1 = *reinterpret_cast<const float4*>(&Qt[d * QTP + ti + 4]);
            float4 kb = *reinterpret_cast<const float4*>(&Kt[d * ATP + tj]);
            u64t kb01 = pk2(kb.x, kb.y);
            u64t kb23 = pk2(kb.z, kb.w);
            float a[8] = {qa0.x, qa0.y, qa0.z, qa0.w, qa1.x, qa1.y, qa1.z, qa1.w};
#pragma unroll
            for (int i = 0; i < 8; i++) {
                u64t aa = pk2(a[i], a[i]);
                fma2(s2[i][0], aa, kb01);
                fma2(s2[i][1], aa, kb23);
            }
        }
        __syncthreads();

        float fi[8];
#pragma unroll
        for (int i = 0; i < 8; i++) {
            int r = ti + i;
            float s0, s1, s2f, s3;
            upk2(s2[i][0], s0, s1);
            upk2(s2[i][1], s2f, s3);
            float mloc = fmaxf(fmaxf(s0, s1), fmaxf(s2f, s3)) * 0.125f;
#pragma unroll
            for (int off = 8; off > 0; off >>= 1)
                mloc = fmaxf(mloc, __shfl_xor_sync(0xffffffff, mloc, off));
            float mo = rowm[r];
            float mx = fmaxf(mloc, mo);
            float4 p;
            p.x = __expf(s0 * 0.125f - mx);
            p.y = __expf(s1 * 0.125f - mx);
            p.z = __expf(s2f * 0.125f - mx);
            p.w = __expf(s3 * 0.125f - mx);
            float sm = p.x + p.y + p.z + p.w;
#pragma unroll
            for (int off = 8; off > 0; off >>= 1)
                sm += __shfl_xor_sync(0xffffffff, sm, off);
            *reinterpret_cast<float4*>(&Ps[r * ATP + tj]) = p;
            float f = __expf(mo - mx);
            fi[i] = f;
            if (glead) {
                rowl[r] = rowl[r] * f + sm;
                rowm[r] = mx;
            }
        }
        __syncthreads();

#pragma unroll
        for (int i = 0; i < 8; i++) {
            u64t ff = pk2(fi[i], fi[i]);
            mul2(o2[i][0], ff);
            mul2(o2[i][1], ff);
        }
        for (int t4 = 0; t4 < 64; t4 += 4) {
            float4 p4[8];
#pragma unroll
            for (int i = 0; i < 8; i++)
                p4[i] = *reinterpret_cast<const float4*>(&Ps[(ti + i) * ATP + t4]);
#pragma unroll
            for (int j4 = 0; j4 < 4; j4++) {
                float4 vb = *reinterpret_cast<const float4*>(&Vs[(t4 + j4) * ATP + tj]);
                u64t vb01 = pk2(vb.x, vb.y);
                u64t vb23 = pk2(vb.z, vb.w);
#pragma unroll
                for (int i = 0; i < 8; i++) {
                    float pj = j4 == 0 ? p4[i].x : j4 == 1 ? p4[i].y : j4 == 2 ? p4[i].z : p4[i].w;
                    u64t pp = pk2(pj, pj);
                    fma2(o2[i][0], pp, vb01);
                    fma2(o2[i][1], pp, vb23);
                }
            }
        }
        __syncthreads();
    }
#pragma unroll
    for (int i = 0; i < 8; i++) {
        float inv = 1.0f / rowl[ti + i];
        float o0, o1, o2f, o3;
        upk2(o2[i][0], o0, o1);
        upk2(o2[i][1], o2f, o3);
        float* dst = O + base + (size_t)(qt * 128 + ti + i) * EMB + tj;
        dst[0] = o0 * inv;
        dst[1] = o1 * inv;
        dst[2] = o2f * inv;
        dst[3] = o3 * inv;
    }
}

// ---------------- prefix scan + aux loss ----------------
__global__ void scan_aux_kernel(float* __restrict__ out, int out_size) {
    if (threadIdx.x == 0) {
        int acc = 0;
        float aux = 0.f;
        for (int e = 0; e < NEXP; e++) {
            g_off[e] = acc;
            acc += g_cnt[e];
            aux += g_imp[e] * (float)g_cnt[e];
        }
        aux *= (float)NEXP / ((float)TOK * (float)TOK);
        if (out_size > TOK * EMB) out[TOK * EMB] = aux;
    }
}

// ---------------- fill per-expert assignment lists ----------------
__global__ __launch_bounds__(128) void fill_assign_kernel() {
    int t = blockIdx.x * 128 + threadIdx.x;
#pragma unroll
    for (int k = 0; k < TOPK; k++) {
        int e = g_topi[t * TOPK + k];
        int pos = atomicAdd(&g_cur[e], 1);
        int gidx = g_off[e] + pos;
        g_atok[gidx] = t;
        g_aw[gidx] = g_topw[t * TOPK + k];
    }
}

__global__ void zero_small_kernel() {
    int i = threadIdx.x;
    if (i < NEXP) { g_imp[i] = 0.f; g_cnt[i] = 0; g_cur[i] = 0; }
}

// ---------------- launch ----------------
extern "C" void kernel_launch(void* const* d_in, const int* in_sizes, int n_in,
                              void* d_out, int out_size) {
    const float* x        = (const float*)d_in[0];
    const float* ln1_g    = (const float*)d_in[1];
    const float* ln1_b    = (const float*)d_in[2];
    const float* wq       = (const float*)d_in[3];
    const float* bq       = (const float*)d_in[4];
    const float* wk       = (const float*)d_in[5];
    const float* bk       = (const float*)d_in[6];
    const float* wv       = (const float*)d_in[7];
    const float* bv       = (const float*)d_in[8];
    const float* wo       = (const float*)d_in[9];
    const float* bo       = (const float*)d_in[10];
    const float* ln2_g    = (const float*)d_in[11];
    const float* ln2_b    = (const float*)d_in[12];
    const float* router_a = (const float*)d_in[13];
    const float* router_b = (const float*)d_in[14];
    const float* re_w1    = (const float*)d_in[15];
    const float* re_b1    = (const float*)d_in[16];
    const float* re_w2    = (const float*)d_in[17];
    const float* re_b2    = (const float*)d_in[18];
    const float* se_w1    = (const float*)d_in[19];
    const float* se_b1    = (const float*)d_in[20];
    const float* se_w2    = (const float*)d_in[21];
    const float* se_b2    = (const float*)d_in[22];
    float* out = (float*)d_out;

    float *p_h1, *p_attn, *p_x1, *p_h2;
    cudaGetSymbolAddress((void**)&p_h1, g_h1);
    cudaGetSymbolAddress((void**)&p_attn, g_attn);
    cudaGetSymbolAddress((void**)&p_x1, g_x1);
    cudaGetSymbolAddress((void**)&p_h2, g_h2);

    cudaFuncSetAttribute(qkv_tgemm, cudaFuncAttributeMaxDynamicSharedMemorySize, TG_SMEM);
    cudaFuncSetAttribute(moe_up, cudaFuncAttributeMaxDynamicSharedMemorySize, TG_SMEM);
    cudaFuncSetAttribute(moe_down, cudaFuncAttributeMaxDynamicSharedMemorySize, TG_SMEM);
    cudaFuncSetAttribute(wo_splitk, cudaFuncAttributeMaxDynamicSharedMemorySize, TG_SMEM);
    cudaFuncSetAttribute(attn_kernel, cudaFuncAttributeMaxDynamicSharedMemorySize, AT_SMEM);
    cudaFuncSetAttribute(router_fused, cudaFuncAttributeMaxDynamicSharedMemorySize, RF_SMEM);

    zero_small_kernel<<<1, 32>>>();
    ln_kernel<<<TOK, 128>>>(x, ln1_g, ln1_b, p_h1);

    qkv_tgemm<<<dim3(4, 32, 3), 256, TG_SMEM>>>(p_h1, wq, wk, wv, bq, bk, bv);

    attn_kernel<<<dim3(32, 8), 256, AT_SMEM>>>();

    init_add_bias<<<(TOK * EMB / 4) / 256, 256>>>(x, bo, p_x1);
    wo_splitk<<<dim3(4, 32, WOSPLIT), 256, TG_SMEM>>>(p_attn, wo, p_x1);

    ln_kernel<<<TOK, 128>>>(p_x1, ln2_g, ln2_b, p_h2);

    // fused router (rlat + logits + softmax + top-4 + stats)
    router_fused<<<TOK / 128, 256, RF_SMEM>>>(router_a, router_b);
    scan_aux_kernel<<<1, 32>>>(out, out_size);
    fill_assign_kernel<<<TOK / 128, 128>>>();

    // merged MoE up: shared expert GEMM1 + routed GEMM1 in one grid
    moe_up<<<UP_SHARED_BLOCKS + NEXP * 128, 256, TG_SMEM>>>(se_w1, se_b1, re_w1, re_b1);

    // out = x1 + se_b2, then merged down: shared2 split-K + routed2 (both atomic)
    init_add_bias<<<(TOK * EMB / 4) / 256, 256>>>(p_x1, se_b2, out);
    moe_down<<<DN_SHARED_BLOCKS + NEXP * 128, 256, TG_SMEM>>>(se_w2, re_w2, re_b2, out);
}